// round 2
// baseline (speedup 1.0000x reference)
#include <cuda_runtime.h>

// Problem constants (fixed shapes)
#define BB 4
#define NROWS 4096   // N (queries)
#define MROWS 4096   // M (keys)
#define CDIM 512
#define TOTQ (BB*NROWS)   // 16384

// ---------------------------------------------------------------------------
// Device scratch (static allocation is the sanctioned workaround)
// ---------------------------------------------------------------------------
__device__ __align__(16) float g_q[TOTQ * CDIM];            // 33.5 MB
__device__ __align__(16) float g_k[TOTQ * CDIM];            // 33.5 MB
__device__ __align__(16) float g_attn[67108864];            // 4*4096*4096 = 268 MB
__device__ __align__(16) float g_o1[TOTQ * CDIM];           // 33.5 MB
__device__ __align__(16) float g_o2[TOTQ * CDIM];           // 33.5 MB

// ---------------------------------------------------------------------------
// Tiled SGEMM: C[M,N] = scale * (A @ opB) (+ bias)
//   TRANS_B = true :  B is [N,K] row-major  (C = A @ B^T)
//   TRANS_B = false:  B is [K,N] row-major  (C = A @ B)
// Block tile 128x128, K-tile 16, 256 threads, 8x8 per-thread accumulators.
// All dims assumed multiples of the tile sizes (true for this problem).
// blockIdx.z batches via the given strides.
// ---------------------------------------------------------------------------
template<bool TRANS_B, bool HAS_BIAS>
__global__ void __launch_bounds__(256) gemm128(
    const float* __restrict__ A, const float* __restrict__ B,
    const float* __restrict__ bias, float* __restrict__ C,
    int Mdim, int Ndim, int Kdim, float scale,
    long long sA, long long sB, long long sC)
{
    A += (long long)blockIdx.z * sA;
    B += (long long)blockIdx.z * sB;
    C += (long long)blockIdx.z * sC;

    __shared__ float As[16][132];
    __shared__ float Bs[16][132];

    const int tid = threadIdx.x;
    const int tx = tid & 15;
    const int ty = tid >> 4;
    const int m0 = blockIdx.y * 128;
    const int n0 = blockIdx.x * 128;

    float acc[8][8];
#pragma unroll
    for (int i = 0; i < 8; i++)
#pragma unroll
        for (int j = 0; j < 8; j++) acc[i][j] = 0.f;

    // K-major tile loaders: each thread fetches 2 float4 (rows ar, ar+64; cols ac..ac+3)
    const int ar = tid >> 2;        // 0..63
    const int ac = (tid & 3) * 4;   // 0,4,8,12

    for (int k0 = 0; k0 < Kdim; k0 += 16) {
        // ---- load A tile (transpose into smem) ----
#pragma unroll
        for (int h = 0; h < 2; h++) {
            const int r = ar + h * 64;
            float4 av = *(const float4*)&A[(long long)(m0 + r) * Kdim + k0 + ac];
            As[ac + 0][r] = av.x; As[ac + 1][r] = av.y;
            As[ac + 2][r] = av.z; As[ac + 3][r] = av.w;
        }
        // ---- load B tile ----
        if (TRANS_B) {
#pragma unroll
            for (int h = 0; h < 2; h++) {
                const int r = ar + h * 64;
                float4 bv = *(const float4*)&B[(long long)(n0 + r) * Kdim + k0 + ac];
                Bs[ac + 0][r] = bv.x; Bs[ac + 1][r] = bv.y;
                Bs[ac + 2][r] = bv.z; Bs[ac + 3][r] = bv.w;
            }
        } else {
            const int kr = tid >> 5;          // 0..7
            const int c  = (tid & 31) * 4;    // 0..124
#pragma unroll
            for (int h = 0; h < 2; h++) {
                const int kk = kr + h * 8;
                float4 bv = *(const float4*)&B[(long long)(k0 + kk) * Ndim + n0 + c];
                *(float4*)&Bs[kk][c] = bv;
            }
        }
        __syncthreads();

#pragma unroll
        for (int kk = 0; kk < 16; kk++) {
            float a[8], b[8];
            *(float4*)&a[0] = *(const float4*)&As[kk][ty * 4];
            *(float4*)&a[4] = *(const float4*)&As[kk][64 + ty * 4];
            *(float4*)&b[0] = *(const float4*)&Bs[kk][tx * 4];
            *(float4*)&b[4] = *(const float4*)&Bs[kk][64 + tx * 4];
#pragma unroll
            for (int i = 0; i < 8; i++)
#pragma unroll
                for (int j = 0; j < 8; j++)
                    acc[i][j] += a[i] * b[j];
        }
        __syncthreads();
    }

    // ---- epilogue ----
#pragma unroll
    for (int i = 0; i < 8; i++) {
        const int row = m0 + ((i < 4) ? (ty * 4 + i) : (64 + ty * 4 + i - 4));
#pragma unroll
        for (int jh = 0; jh < 2; jh++) {
            const int col = n0 + jh * 64 + tx * 4;
            float4 o;
            o.x = acc[i][jh * 4 + 0] * scale;
            o.y = acc[i][jh * 4 + 1] * scale;
            o.z = acc[i][jh * 4 + 2] * scale;
            o.w = acc[i][jh * 4 + 3] * scale;
            if (HAS_BIAS) {
                o.x += bias[col + 0]; o.y += bias[col + 1];
                o.z += bias[col + 2]; o.w += bias[col + 3];
            }
            *(float4*)&C[(long long)row * Ndim + col] = o;
        }
    }
}

// ---------------------------------------------------------------------------
// Row softmax over 4096 elements + post-softmax key masking (mask after norm,
// matching the reference: denominator includes masked entries).
// One CTA (256 threads) per row, 16 elements per thread held in registers.
// ---------------------------------------------------------------------------
__global__ void __launch_bounds__(256) softmax_rows(
    float* __restrict__ attn, const int* __restrict__ mask)
{
    __shared__ float rmax[8];
    __shared__ float rsum[8];

    float* p = attn + (long long)blockIdx.x * MROWS;
    const int t = threadIdx.x;

    float4 v[4];
    float mx = -1e30f;
#pragma unroll
    for (int u = 0; u < 4; u++) {
        v[u] = ((const float4*)p)[u * 256 + t];
        mx = fmaxf(mx, fmaxf(fmaxf(v[u].x, v[u].y), fmaxf(v[u].z, v[u].w)));
    }
#pragma unroll
    for (int o = 16; o > 0; o >>= 1) mx = fmaxf(mx, __shfl_xor_sync(0xffffffffu, mx, o));
    if ((t & 31) == 0) rmax[t >> 5] = mx;
    __syncthreads();
    mx = fmaxf(fmaxf(fmaxf(rmax[0], rmax[1]), fmaxf(rmax[2], rmax[3])),
               fmaxf(fmaxf(rmax[4], rmax[5]), fmaxf(rmax[6], rmax[7])));

    float s = 0.f;
#pragma unroll
    for (int u = 0; u < 4; u++) {
        v[u].x = expf(v[u].x - mx);
        v[u].y = expf(v[u].y - mx);
        v[u].z = expf(v[u].z - mx);
        v[u].w = expf(v[u].w - mx);
        s += v[u].x + v[u].y + v[u].z + v[u].w;
    }
#pragma unroll
    for (int o = 16; o > 0; o >>= 1) s += __shfl_xor_sync(0xffffffffu, s, o);
    if ((t & 31) == 0) rsum[t >> 5] = s;
    __syncthreads();
    s = (rsum[0] + rsum[1]) + (rsum[2] + rsum[3]) + (rsum[4] + rsum[5]) + (rsum[6] + rsum[7]);
    const float inv = 1.0f / s;

#pragma unroll
    for (int u = 0; u < 4; u++) {
        const int i4 = u * 256 + t;
        const int4 mq = ((const int4*)mask)[i4];
        float4 o;
        o.x = v[u].x * inv * (mq.x != 0 ? 1.f : 0.f);
        o.y = v[u].y * inv * (mq.y != 0 ? 1.f : 0.f);
        o.z = v[u].z * inv * (mq.z != 0 ? 1.f : 0.f);
        o.w = v[u].w * inv * (mq.w != 0 ? 1.f : 0.f);
        ((float4*)p)[i4] = o;
    }
}

// ---------------------------------------------------------------------------
// Bug-faithful permute: out2[b, i, j] = out[b, (i%8)*512 + j, i/8].
// With i = 8a + r:  out2[b, 8a+r, j] = out[b, r*512 + j, a]
//  -> for each (b, r): transpose of a 512x512 block, dst row stride 4096.
// ---------------------------------------------------------------------------
__global__ void __launch_bounds__(256) permute_kernel(
    const float* __restrict__ out, float* __restrict__ out2)
{
    __shared__ float tile[32][33];
    const int br = blockIdx.z;
    const int b = br >> 3;
    const int r = br & 7;
    const float* src = out + (long long)b * NROWS * CDIM + (long long)r * 512 * CDIM;
    float* dst = out2 + (long long)b * NROWS * CDIM + r * CDIM;

    const int j0 = blockIdx.y * 32;
    const int a0 = blockIdx.x * 32;
    const int tx = threadIdx.x;   // 0..31
    const int ty = threadIdx.y;   // 0..7

#pragma unroll
    for (int h = 0; h < 32; h += 8)
        tile[ty + h][tx] = src[(long long)(j0 + ty + h) * 512 + a0 + tx];
    __syncthreads();
#pragma unroll
    for (int h = 0; h < 32; h += 8)
        dst[(long long)(a0 + ty + h) * 4096 + j0 + tx] = tile[tx][ty + h];
}

// ---------------------------------------------------------------------------
// Launch
// ---------------------------------------------------------------------------
extern "C" void kernel_launch(void* const* d_in, const int* in_sizes, int n_in,
                              void* d_out, int out_size)
{
    const float* x       = (const float*)d_in[0];
    const float* support = (const float*)d_in[1];
    const int*   mask    = (const int*)  d_in[2];
    const float* Wv      = (const float*)d_in[3];
    const float* Wp      = (const float*)d_in[4];
    const float* bp      = (const float*)d_in[5];
    float* out = (float*)d_out;

    float *q, *k, *attn, *o1, *o2;
    cudaGetSymbolAddress((void**)&q,    g_q);
    cudaGetSymbolAddress((void**)&k,    g_k);
    cudaGetSymbolAddress((void**)&attn, g_attn);
    cudaGetSymbolAddress((void**)&o1,   g_o1);
    cudaGetSymbolAddress((void**)&o2,   g_o2);

    const long long sQK = (long long)NROWS * CDIM;     // 4096*512
    const long long sAT = (long long)NROWS * MROWS;    // 4096*4096

    // q = x @ Wv^T ; k = support @ Wv^T    (batch folded into rows)
    gemm128<true, false><<<dim3(4, 128, 1), 256>>>(x,       Wv, nullptr, q, TOTQ, CDIM, CDIM, 1.0f, 0, 0, 0);
    gemm128<true, false><<<dim3(4, 128, 1), 256>>>(support, Wv, nullptr, k, TOTQ, CDIM, CDIM, 1.0f, 0, 0, 0);

    // logits = 0.125 * q @ k^T   (batched over z)
    gemm128<true, false><<<dim3(32, 32, BB), 256>>>(q, k, nullptr, attn,
                                                    NROWS, MROWS, CDIM, 0.125f, sQK, sQK, sAT);

    // softmax + post-softmax mask
    softmax_rows<<<TOTQ, 256>>>(attn, mask);

    // o1 = attn @ v   (v = k), batched
    gemm128<false, false><<<dim3(4, 32, BB), 256>>>(attn, k, nullptr, o1,
                                                    NROWS, CDIM, MROWS, 1.0f, sAT, sQK, sQK);

    // bug-faithful permute
    permute_kernel<<<dim3(16, 16, BB * 8), dim3(32, 8)>>>(o1, o2);

    // out = o2 @ Wp^T + bp
    gemm128<true, true><<<dim3(4, 128, 1), 256>>>(o2, Wp, bp, out, TOTQ, CDIM, CDIM, 1.0f, 0, 0, 0);
}

// round 4
// speedup vs baseline: 1.9612x; 1.9612x over previous
#include <cuda_runtime.h>
#include <cuda_bf16.h>

#define BB 4
#define NROWS 4096
#define MROWS 4096
#define CDIM 512
#define TOTQ (BB*NROWS)

// ---------------------------------------------------------------------------
// Device scratch
// ---------------------------------------------------------------------------
__device__ __align__(16) float g_attn[(size_t)BB * NROWS * MROWS];   // 268 MB
__device__ __align__(16) float g_o1[(size_t)TOTQ * CDIM];
__device__ __align__(16) __nv_bfloat16 g_xh[(size_t)TOTQ*CDIM], g_xl[(size_t)TOTQ*CDIM];
__device__ __align__(16) __nv_bfloat16 g_sh[(size_t)TOTQ*CDIM], g_sl[(size_t)TOTQ*CDIM];
__device__ __align__(16) __nv_bfloat16 g_wvh[CDIM*CDIM], g_wvl[CDIM*CDIM];
__device__ __align__(16) __nv_bfloat16 g_wph[CDIM*CDIM], g_wpl[CDIM*CDIM];
__device__ __align__(16) __nv_bfloat16 g_qh[(size_t)TOTQ*CDIM], g_ql[(size_t)TOTQ*CDIM];
__device__ __align__(16) __nv_bfloat16 g_kh[(size_t)TOTQ*CDIM], g_kl[(size_t)TOTQ*CDIM];
__device__ __align__(16) __nv_bfloat16 g_kth[(size_t)TOTQ*CDIM], g_ktl[(size_t)TOTQ*CDIM];
__device__ __align__(16) __nv_bfloat16 g_ah[(size_t)BB*NROWS*MROWS];  // 134 MB
__device__ __align__(16) __nv_bfloat16 g_al[(size_t)BB*NROWS*MROWS];  // 134 MB
__device__ __align__(16) __nv_bfloat16 g_o2h[(size_t)TOTQ*CDIM], g_o2l[(size_t)TOTQ*CDIM];

// ---------------------------------------------------------------------------
// helpers
// ---------------------------------------------------------------------------
static __device__ __forceinline__ unsigned smem_u32(const void* p) {
    unsigned a;
    asm("{ .reg .u64 t; cvta.to.shared.u64 t, %1; cvt.u32.u64 %0, t; }" : "=r"(a) : "l"(p));
    return a;
}
static __device__ __forceinline__ void cpa16(unsigned dst, const void* src) {
    asm volatile("cp.async.cg.shared.global [%0], [%1], 16;"
                 :: "r"(dst), "l"(__cvta_generic_to_global(src)) : "memory");
}
static __device__ __forceinline__ void ldm_x4(unsigned& r0, unsigned& r1,
                                              unsigned& r2, unsigned& r3, unsigned a) {
    asm volatile("ldmatrix.sync.aligned.m8n8.x4.shared.b16 {%0,%1,%2,%3}, [%4];"
                 : "=r"(r0), "=r"(r1), "=r"(r2), "=r"(r3) : "r"(a));
}
static __device__ __forceinline__ void mma16816(float* c, const unsigned* a,
                                                const unsigned* b) {
    asm volatile(
        "mma.sync.aligned.m16n8k16.row.col.f32.bf16.bf16.f32 "
        "{%0,%1,%2,%3}, {%4,%5,%6,%7}, {%8,%9}, {%0,%1,%2,%3};"
        : "+f"(c[0]), "+f"(c[1]), "+f"(c[2]), "+f"(c[3])
        : "r"(a[0]), "r"(a[1]), "r"(a[2]), "r"(a[3]), "r"(b[0]), "r"(b[1]));
}
static __device__ __forceinline__ unsigned bpack(float a, float b) {
    __nv_bfloat162 t = __floats2bfloat162_rn(a, b);
    return *reinterpret_cast<unsigned*>(&t);
}

// ---------------------------------------------------------------------------
// Split-bf16 HMMA GEMM. CTA tile 128x128, warp tile 64x32, K-slab 32,
// 3-stage cp.async pipeline. A is [M,K] row-major, B is [N,K] row-major
// (i.e. C = A @ B^T), both given as hi/lo bf16 pairs.
// MODE 0: Cf = scale*acc (batched)    MODE 1: Cf = acc + bias
// MODE 2: (Ch,Cl) = split(acc)
// ---------------------------------------------------------------------------
#define TK 32
#define ROWB 80                      // 32 bf16 = 64B data, padded to 80B
#define MAT_BYTES (128*ROWB)         // 10240
#define STG (4*MAT_BYTES)            // 40960 per stage
#define NSTAGE 3
#define SMEM_DYN (NSTAGE*STG)        // 122880

template<int MODE>
__global__ void __launch_bounds__(256, 1) hmma_gemm(
    const __nv_bfloat16* __restrict__ Ah, const __nv_bfloat16* __restrict__ Al,
    const __nv_bfloat16* __restrict__ Bh, const __nv_bfloat16* __restrict__ Bl,
    int ldA, int ldB, int ldC, int Kdim, float scale,
    long long sA, long long sB, long long sC,
    const float* __restrict__ bias, float* __restrict__ Cf,
    __nv_bfloat16* __restrict__ Ch, __nv_bfloat16* __restrict__ Cl)
{
    extern __shared__ char smem[];
    const unsigned sb = smem_u32(smem);
    const int tid = threadIdx.x;
    const int wid = tid >> 5;
    const int lane = tid & 31;
    const int m0 = blockIdx.y * 128;
    const int n0 = blockIdx.x * 128;
    const long long bz = blockIdx.z;
    Ah += bz * sA; Al += bz * sA;
    Bh += bz * sB; Bl += bz * sB;

    const int m_w = (wid >> 2) * 64;   // 0 or 64
    const int n_w = (wid & 3) * 32;    // 0..96

    float acc[4][4][4];
#pragma unroll
    for (int i = 0; i < 4; i++)
#pragma unroll
        for (int j = 0; j < 4; j++)
#pragma unroll
            for (int p = 0; p < 4; p++) acc[i][j][p] = 0.f;

    const int nslab = Kdim / TK;

    auto load_slab = [&](int stage, int k0) {
        const unsigned base = sb + stage * STG;
#pragma unroll
        for (int j = 0; j < 2; j++) {
            const int idx = tid + j * 256;       // 0..511
            const int row = idx >> 2;
            const int c = idx & 3;
            const unsigned doff = row * ROWB + c * 16;
            const long long ga = (long long)(m0 + row) * ldA + k0 + c * 8;
            const long long gb = (long long)(n0 + row) * ldB + k0 + c * 8;
            cpa16(base + doff,                 Ah + ga);
            cpa16(base + MAT_BYTES + doff,     Al + ga);
            cpa16(base + 2 * MAT_BYTES + doff, Bh + gb);
            cpa16(base + 3 * MAT_BYTES + doff, Bl + gb);
        }
        asm volatile("cp.async.commit_group;" ::: "memory");
    };

    // per-thread ldmatrix base offsets
    const unsigned aoff = (unsigned)(m_w + (lane & 15)) * ROWB + ((lane >> 4) * 8) * 2;
    const unsigned boff = (unsigned)(n_w + (lane & 7) + ((lane >> 4) << 3)) * ROWB
                        + ((lane & 8) ? 16 : 0);

    load_slab(0, 0);
    if (nslab > 1) load_slab(1, TK);
    if (nslab > 2) load_slab(2, 2 * TK);

    for (int s = 0; s < nslab; s++) {
        asm volatile("cp.async.wait_group 2;" ::: "memory");
        __syncthreads();
        const unsigned st = sb + (s % NSTAGE) * STG;
#pragma unroll
        for (int kk = 0; kk < 2; kk++) {
            unsigned ah[4][4], al[4][4], bh[4][2], bl[4][2];
#pragma unroll
            for (int mb = 0; mb < 4; mb++) {
                const unsigned a = st + aoff + mb * (16 * ROWB) + kk * 32;
                ldm_x4(ah[mb][0], ah[mb][1], ah[mb][2], ah[mb][3], a);
                ldm_x4(al[mb][0], al[mb][1], al[mb][2], al[mb][3], a + MAT_BYTES);
            }
#pragma unroll
            for (int nbp = 0; nbp < 2; nbp++) {
                const unsigned b = st + 2 * MAT_BYTES + boff + nbp * (16 * ROWB) + kk * 32;
                ldm_x4(bh[2*nbp][0], bh[2*nbp][1], bh[2*nbp+1][0], bh[2*nbp+1][1], b);
                ldm_x4(bl[2*nbp][0], bl[2*nbp][1], bl[2*nbp+1][0], bl[2*nbp+1][1],
                       b + MAT_BYTES);
            }
#pragma unroll
            for (int mb = 0; mb < 4; mb++)
#pragma unroll
                for (int nb = 0; nb < 4; nb++) {
                    mma16816(acc[mb][nb], ah[mb], bh[nb]);
                    mma16816(acc[mb][nb], ah[mb], bl[nb]);
                    mma16816(acc[mb][nb], al[mb], bh[nb]);
                }
        }
        __syncthreads();
        if (s + NSTAGE < nslab) load_slab((s + NSTAGE) % NSTAGE, (s + NSTAGE) * TK);
    }

    // ---- epilogue: direct register -> global stores ----
#pragma unroll
    for (int mb = 0; mb < 4; mb++)
#pragma unroll
        for (int p = 0; p < 2; p++) {
            const long long row = m0 + m_w + mb * 16 + (lane >> 2) + p * 8;
#pragma unroll
            for (int nb = 0; nb < 4; nb++) {
                const int col = n0 + n_w + nb * 8 + (lane & 3) * 2;
                float v0 = acc[mb][nb][2 * p];
                float v1 = acc[mb][nb][2 * p + 1];
                if (MODE == 0) {
                    float2 o = make_float2(v0 * scale, v1 * scale);
                    *(float2*)&Cf[bz * sC + row * ldC + col] = o;
                } else if (MODE == 1) {
                    float2 o = make_float2(v0 + bias[col], v1 + bias[col + 1]);
                    *(float2*)&Cf[row * ldC + col] = o;
                } else {
                    __nv_bfloat16 h0 = __float2bfloat16(v0);
                    __nv_bfloat16 h1 = __float2bfloat16(v1);
                    unsigned ph = bpack(__bfloat162float(h0), __bfloat162float(h1));
                    unsigned pl = bpack(v0 - __bfloat162float(h0),
                                        v1 - __bfloat162float(h1));
                    *(unsigned*)&Ch[row * (long long)ldC + col] = ph;
                    *(unsigned*)&Cl[row * (long long)ldC + col] = pl;
                }
            }
        }
}

// ---------------------------------------------------------------------------
// fp32 -> split bf16 (hi/lo)
// ---------------------------------------------------------------------------
__global__ void __launch_bounds__(256) split_f32(
    const float* __restrict__ src, __nv_bfloat16* __restrict__ h,
    __nv_bfloat16* __restrict__ l, int n4)
{
    int i = blockIdx.x * 256 + threadIdx.x;
    if (i >= n4) return;
    float4 v = ((const float4*)src)[i];
    __nv_bfloat16 h0 = __float2bfloat16(v.x), h1 = __float2bfloat16(v.y);
    __nv_bfloat16 h2 = __float2bfloat16(v.z), h3 = __float2bfloat16(v.w);
    uint2 ph, pl;
    ph.x = bpack(__bfloat162float(h0), __bfloat162float(h1));
    ph.y = bpack(__bfloat162float(h2), __bfloat162float(h3));
    pl.x = bpack(v.x - __bfloat162float(h0), v.y - __bfloat162float(h1));
    pl.y = bpack(v.z - __bfloat162float(h2), v.w - __bfloat162float(h3));
    ((uint2*)h)[i] = ph;
    ((uint2*)l)[i] = pl;
}

// ---------------------------------------------------------------------------
// kT: kth[b][d][m] = kh[b*4096+m][d]   (32x32 smem tile transpose, hi+lo)
// ---------------------------------------------------------------------------
__global__ void __launch_bounds__(256) transpose_split(
    const __nv_bfloat16* __restrict__ kh, const __nv_bfloat16* __restrict__ kl,
    __nv_bfloat16* __restrict__ kth, __nv_bfloat16* __restrict__ ktl)
{
    __shared__ __nv_bfloat16 th[32][33], tl[32][33];
    const int b = blockIdx.z;
    const int mm0 = blockIdx.x * 32;
    const int d0 = blockIdx.y * 32;
    const int tx = threadIdx.x, ty = threadIdx.y;
    const long long sbase = (long long)(b * 4096 + mm0) * CDIM + d0;
#pragma unroll
    for (int hh = 0; hh < 32; hh += 8) {
        th[ty + hh][tx] = kh[sbase + (long long)(ty + hh) * CDIM + tx];
        tl[ty + hh][tx] = kl[sbase + (long long)(ty + hh) * CDIM + tx];
    }
    __syncthreads();
    const long long dbase = (long long)b * CDIM * MROWS + (long long)d0 * MROWS + mm0;
#pragma unroll
    for (int hh = 0; hh < 32; hh += 8) {
        kth[dbase + (long long)(ty + hh) * MROWS + tx] = th[tx][ty + hh];
        ktl[dbase + (long long)(ty + hh) * MROWS + tx] = tl[tx][ty + hh];
    }
}

// ---------------------------------------------------------------------------
// Row softmax (4096) + post-softmax mask; emits split-bf16 probabilities.
// ---------------------------------------------------------------------------
__global__ void __launch_bounds__(256) softmax_split(
    const float* __restrict__ attn, const int* __restrict__ mask,
    __nv_bfloat16* __restrict__ ah, __nv_bfloat16* __restrict__ al)
{
    __shared__ float rmax[8];
    __shared__ float rsum[8];
    const float* p = attn + (long long)blockIdx.x * MROWS;
    const int t = threadIdx.x;

    float4 v[4];
    float mx = -1e30f;
#pragma unroll
    for (int u = 0; u < 4; u++) {
        v[u] = ((const float4*)p)[u * 256 + t];
        mx = fmaxf(mx, fmaxf(fmaxf(v[u].x, v[u].y), fmaxf(v[u].z, v[u].w)));
    }
#pragma unroll
    for (int o = 16; o > 0; o >>= 1) mx = fmaxf(mx, __shfl_xor_sync(0xffffffffu, mx, o));
    if ((t & 31) == 0) rmax[t >> 5] = mx;
    __syncthreads();
    mx = fmaxf(fmaxf(fmaxf(rmax[0], rmax[1]), fmaxf(rmax[2], rmax[3])),
               fmaxf(fmaxf(rmax[4], rmax[5]), fmaxf(rmax[6], rmax[7])));

    float s = 0.f;
#pragma unroll
    for (int u = 0; u < 4; u++) {
        v[u].x = expf(v[u].x - mx); v[u].y = expf(v[u].y - mx);
        v[u].z = expf(v[u].z - mx); v[u].w = expf(v[u].w - mx);
        s += v[u].x + v[u].y + v[u].z + v[u].w;
    }
#pragma unroll
    for (int o = 16; o > 0; o >>= 1) s += __shfl_xor_sync(0xffffffffu, s, o);
    if ((t & 31) == 0) rsum[t >> 5] = s;
    __syncthreads();
    s = (rsum[0] + rsum[1]) + (rsum[2] + rsum[3]) + (rsum[4] + rsum[5]) + (rsum[6] + rsum[7]);
    const float inv = 1.0f / s;

    __nv_bfloat16* bh = ah + (long long)blockIdx.x * MROWS;
    __nv_bfloat16* bl = al + (long long)blockIdx.x * MROWS;
#pragma unroll
    for (int u = 0; u < 4; u++) {
        const int i4 = u * 256 + t;
        const int4 mq = ((const int4*)mask)[i4];
        float o0 = v[u].x * inv * (mq.x != 0 ? 1.f : 0.f);
        float o1 = v[u].y * inv * (mq.y != 0 ? 1.f : 0.f);
        float o2 = v[u].z * inv * (mq.z != 0 ? 1.f : 0.f);
        float o3 = v[u].w * inv * (mq.w != 0 ? 1.f : 0.f);
        __nv_bfloat16 h0 = __float2bfloat16(o0), h1 = __float2bfloat16(o1);
        __nv_bfloat16 h2 = __float2bfloat16(o2), h3 = __float2bfloat16(o3);
        uint2 ph, pl;
        ph.x = bpack(__bfloat162float(h0), __bfloat162float(h1));
        ph.y = bpack(__bfloat162float(h2), __bfloat162float(h3));
        pl.x = bpack(o0 - __bfloat162float(h0), o1 - __bfloat162float(h1));
        pl.y = bpack(o2 - __bfloat162float(h2), o3 - __bfloat162float(h3));
        ((uint2*)bh)[i4] = ph;
        ((uint2*)bl)[i4] = pl;
    }
}

// ---------------------------------------------------------------------------
// Bug-faithful permute: o2[b, 8a+r, j] = o1[b, r*512 + j, a], split-bf16 out
// ---------------------------------------------------------------------------
__global__ void __launch_bounds__(256) permute_split(
    const float* __restrict__ o1, __nv_bfloat16* __restrict__ oh,
    __nv_bfloat16* __restrict__ ol)
{
    __shared__ float tile[32][33];
    const int br = blockIdx.z;
    const int b = br >> 3;
    const int r = br & 7;
    const float* src = o1 + (long long)b * NROWS * CDIM + (long long)r * 512 * CDIM;
    const long long dbase = (long long)b * NROWS * CDIM + r * CDIM;
    const int j0 = blockIdx.y * 32;
    const int a0 = blockIdx.x * 32;
    const int tx = threadIdx.x, ty = threadIdx.y;

#pragma unroll
    for (int hh = 0; hh < 32; hh += 8)
        tile[ty + hh][tx] = src[(long long)(j0 + ty + hh) * 512 + a0 + tx];
    __syncthreads();
#pragma unroll
    for (int hh = 0; hh < 32; hh += 8) {
        float v = tile[tx][ty + hh];
        long long off = dbase + (long long)(a0 + ty + hh) * 4096 + j0 + tx;
        __nv_bfloat16 hi = __float2bfloat16(v);
        oh[off] = hi;
        ol[off] = __float2bfloat16(v - __bfloat162float(hi));
    }
}

// ---------------------------------------------------------------------------
// Launch
// ---------------------------------------------------------------------------
extern "C" void kernel_launch(void* const* d_in, const int* in_sizes, int n_in,
                              void* d_out, int out_size)
{
    const float* x       = (const float*)d_in[0];
    const float* support = (const float*)d_in[1];
    const int*   mask    = (const int*)  d_in[2];
    const float* Wv      = (const float*)d_in[3];
    const float* Wp      = (const float*)d_in[4];
    const float* bp      = (const float*)d_in[5];
    float* out = (float*)d_out;

    float *attn, *o1;
    __nv_bfloat16 *xh, *xl, *sh, *sl, *wvh, *wvl, *wph, *wpl;
    __nv_bfloat16 *qh, *ql, *kh, *kl, *kth, *ktl, *ah, *al, *o2h, *o2l;
    cudaGetSymbolAddress((void**)&attn, g_attn);
    cudaGetSymbolAddress((void**)&o1,   g_o1);
    cudaGetSymbolAddress((void**)&xh, g_xh);   cudaGetSymbolAddress((void**)&xl, g_xl);
    cudaGetSymbolAddress((void**)&sh, g_sh);   cudaGetSymbolAddress((void**)&sl, g_sl);
    cudaGetSymbolAddress((void**)&wvh, g_wvh); cudaGetSymbolAddress((void**)&wvl, g_wvl);
    cudaGetSymbolAddress((void**)&wph, g_wph); cudaGetSymbolAddress((void**)&wpl, g_wpl);
    cudaGetSymbolAddress((void**)&qh, g_qh);   cudaGetSymbolAddress((void**)&ql, g_ql);
    cudaGetSymbolAddress((void**)&kh, g_kh);   cudaGetSymbolAddress((void**)&kl, g_kl);
    cudaGetSymbolAddress((void**)&kth, g_kth); cudaGetSymbolAddress((void**)&ktl, g_ktl);
    cudaGetSymbolAddress((void**)&ah, g_ah);   cudaGetSymbolAddress((void**)&al, g_al);
    cudaGetSymbolAddress((void**)&o2h, g_o2h); cudaGetSymbolAddress((void**)&o2l, g_o2l);

    cudaFuncSetAttribute(hmma_gemm<0>, cudaFuncAttributeMaxDynamicSharedMemorySize, SMEM_DYN);
    cudaFuncSetAttribute(hmma_gemm<1>, cudaFuncAttributeMaxDynamicSharedMemorySize, SMEM_DYN);
    cudaFuncSetAttribute(hmma_gemm<2>, cudaFuncAttributeMaxDynamicSharedMemorySize, SMEM_DYN);

    const long long sQK = (long long)NROWS * CDIM;
    const long long sAT = (long long)NROWS * MROWS;
    const long long sKT = (long long)CDIM * MROWS;

    // 1) conversions
    split_f32<<<TOTQ * CDIM / 4 / 256, 256>>>(x,       xh, xl, TOTQ * CDIM / 4);
    split_f32<<<TOTQ * CDIM / 4 / 256, 256>>>(support, sh, sl, TOTQ * CDIM / 4);
    split_f32<<<CDIM * CDIM / 4 / 256, 256>>>(Wv,      wvh, wvl, CDIM * CDIM / 4);
    split_f32<<<CDIM * CDIM / 4 / 256, 256>>>(Wp,      wph, wpl, CDIM * CDIM / 4);

    // 2) q = x @ Wv^T  (split out)
    hmma_gemm<2><<<dim3(4, 128, 1), 256, SMEM_DYN>>>(
        xh, xl, wvh, wvl, CDIM, CDIM, CDIM, CDIM, 1.0f, 0, 0, 0,
        nullptr, nullptr, qh, ql);

    // 3) k = support @ Wv^T  (split out)
    hmma_gemm<2><<<dim3(4, 128, 1), 256, SMEM_DYN>>>(
        sh, sl, wvh, wvl, CDIM, CDIM, CDIM, CDIM, 1.0f, 0, 0, 0,
        nullptr, nullptr, kh, kl);

    // 4) kT[b][d][m]
    transpose_split<<<dim3(128, 16, BB), dim3(32, 8)>>>(kh, kl, kth, ktl);

    // 5) attn = 0.125 * q @ k^T  (fp32, batched)
    hmma_gemm<0><<<dim3(32, 32, BB), 256, SMEM_DYN>>>(
        qh, ql, kh, kl, CDIM, CDIM, MROWS, CDIM, 0.125f, sQK, sQK, sAT,
        nullptr, attn, nullptr, nullptr);

    // 6) softmax + mask -> split-bf16 probs
    softmax_split<<<TOTQ, 256>>>(attn, mask, ah, al);

    // 7) o1 = attn @ v   (B operand = kT, [d][m] row-major)
    hmma_gemm<0><<<dim3(4, 32, BB), 256, SMEM_DYN>>>(
        ah, al, kth, ktl, MROWS, MROWS, CDIM, MROWS, 1.0f, sAT, sKT, sQK,
        nullptr, o1, nullptr, nullptr);

    // 8) bug-faithful permute -> split-bf16
    permute_split<<<dim3(16, 16, BB * 8), dim3(32, 8)>>>(o1, o2h, o2l);

    // 9) out = o2 @ Wp^T + bp
    hmma_gemm<1><<<dim3(4, 128, 1), 256, SMEM_DYN>>>(
        o2h, o2l, wph, wpl, CDIM, CDIM, CDIM, CDIM, 1.0f, 0, 0, 0,
        bp, out, nullptr, nullptr);
}

// round 5
// speedup vs baseline: 2.7435x; 1.3989x over previous
#include <cuda_runtime.h>
#include <cuda_bf16.h>
#include <cuda.h>

#define BB 4
#define NROWS 4096
#define MROWS 4096
#define CDIM 512
#define TOTQ (BB*NROWS)

// ---------------------------------------------------------------------------
// Device scratch
// ---------------------------------------------------------------------------
__device__ __align__(16) float g_attn[(size_t)BB * NROWS * MROWS];   // 268 MB
__device__ __align__(16) float g_o1[(size_t)TOTQ * CDIM];
__device__ __align__(16) __nv_bfloat16 g_xh[(size_t)TOTQ*CDIM], g_xl[(size_t)TOTQ*CDIM];
__device__ __align__(16) __nv_bfloat16 g_sh[(size_t)TOTQ*CDIM], g_sl[(size_t)TOTQ*CDIM];
__device__ __align__(16) __nv_bfloat16 g_wvh[CDIM*CDIM], g_wvl[CDIM*CDIM];
__device__ __align__(16) __nv_bfloat16 g_wph[CDIM*CDIM], g_wpl[CDIM*CDIM];
__device__ __align__(16) __nv_bfloat16 g_qh[(size_t)TOTQ*CDIM], g_ql[(size_t)TOTQ*CDIM];
__device__ __align__(16) __nv_bfloat16 g_kh[(size_t)TOTQ*CDIM], g_kl[(size_t)TOTQ*CDIM];
__device__ __align__(16) __nv_bfloat16 g_kth[(size_t)TOTQ*CDIM], g_ktl[(size_t)TOTQ*CDIM];
__device__ __align__(16) __nv_bfloat16 g_ah[(size_t)BB*NROWS*MROWS];  // 134 MB
__device__ __align__(16) __nv_bfloat16 g_al[(size_t)BB*NROWS*MROWS];  // 134 MB
__device__ __align__(16) __nv_bfloat16 g_o2h[(size_t)TOTQ*CDIM], g_o2l[(size_t)TOTQ*CDIM];

// ---------------------------------------------------------------------------
// device helpers
// ---------------------------------------------------------------------------
static __device__ __forceinline__ unsigned smem_u32(const void* p) {
    unsigned a;
    asm("{ .reg .u64 t; cvta.to.shared.u64 t, %1; cvt.u32.u64 %0, t; }" : "=r"(a) : "l"(p));
    return a;
}
static __device__ __forceinline__ void ldm_x4(unsigned& r0, unsigned& r1,
                                              unsigned& r2, unsigned& r3, unsigned a) {
    asm volatile("ldmatrix.sync.aligned.m8n8.x4.shared.b16 {%0,%1,%2,%3}, [%4];"
                 : "=r"(r0), "=r"(r1), "=r"(r2), "=r"(r3) : "r"(a));
}
static __device__ __forceinline__ void mma16816(float* c, const unsigned* a,
                                                const unsigned* b) {
    asm volatile(
        "mma.sync.aligned.m16n8k16.row.col.f32.bf16.bf16.f32 "
        "{%0,%1,%2,%3}, {%4,%5,%6,%7}, {%8,%9}, {%0,%1,%2,%3};"
        : "+f"(c[0]), "+f"(c[1]), "+f"(c[2]), "+f"(c[3])
        : "r"(a[0]), "r"(a[1]), "r"(a[2]), "r"(a[3]), "r"(b[0]), "r"(b[1]));
}
static __device__ __forceinline__ unsigned bpack(float a, float b) {
    __nv_bfloat162 t = __floats2bfloat162_rn(a, b);
    return *reinterpret_cast<unsigned*>(&t);
}
static __device__ __forceinline__ void mbar_wait(unsigned mbar, unsigned phase) {
    asm volatile(
        "{\n\t.reg .pred P1;\n\t"
        "LAB_WAIT_%=:\n\t"
        "mbarrier.try_wait.parity.acquire.cta.shared::cta.b64 P1, [%0], %1, 0x989680;\n\t"
        "@P1 bra.uni LAB_DONE_%=;\n\t"
        "bra.uni LAB_WAIT_%=;\n\t"
        "LAB_DONE_%=:\n\t}"
        :: "r"(mbar), "r"(phase) : "memory");
}
static __device__ __forceinline__ void tma3(unsigned dst, const CUtensorMap* m,
                                            int x, int y, int z, unsigned mb) {
    asm volatile(
        "cp.async.bulk.tensor.3d.shared::cluster.global.tile.mbarrier::complete_tx::bytes "
        "[%0], [%1, {%2, %3, %4}], [%5];"
        :: "r"(dst), "l"(m), "r"(x), "r"(y), "r"(z), "r"(mb) : "memory");
}

// ---------------------------------------------------------------------------
// Split-bf16 HMMA GEMM with TMA loads. CTA 128x128, warp tile 64x32,
// K-slab 64, 2-stage TMA double buffer, SW128 swizzled smem tiles.
// C = A @ B^T; A [rows,K] row-major, B [rows,K] row-major, hi/lo pairs.
// MODE 0: Cf = scale*acc (batched)  MODE 1: Cf = acc + bias
// MODE 2: (Ch,Cl) = split(acc)
// ---------------------------------------------------------------------------
#define TILEB 16384                 // one 128x64 bf16 SW128 tile
#define STG4  65536                 // 4 tiles per stage
#define SMEM_DYN (1024 + 2*STG4)    // align slack + 2 stages

template<int MODE>
__global__ void __launch_bounds__(256, 1) tma_gemm(
    const __grid_constant__ CUtensorMap mAh, const __grid_constant__ CUtensorMap mAl,
    const __grid_constant__ CUtensorMap mBh, const __grid_constant__ CUtensorMap mBl,
    int ldC, int Kdim, float scale, long long sC,
    const float* __restrict__ bias, float* __restrict__ Cf,
    __nv_bfloat16* __restrict__ Ch, __nv_bfloat16* __restrict__ Cl)
{
    extern __shared__ char smem[];
    __shared__ __align__(16) unsigned long long mbar[2];
    const unsigned sa = (smem_u32(smem) + 1023) & ~1023u;
    const unsigned mbq = smem_u32(mbar);
    const int tid = threadIdx.x;
    const int wid = tid >> 5;
    const int lane = tid & 31;
    const int m0 = blockIdx.y * 128;
    const int n0 = blockIdx.x * 128;
    const int bz = blockIdx.z;

    const int m_w = (wid >> 2) * 64;
    const int n_w = (wid & 3) * 32;

    if (tid == 0) {
        asm volatile("mbarrier.init.shared.b64 [%0], 1;" :: "r"(mbq) : "memory");
        asm volatile("mbarrier.init.shared.b64 [%0], 1;" :: "r"(mbq + 8) : "memory");
    }
    __syncthreads();

    const int nslab = Kdim / 64;
    auto issue = [&](int buf, int k0) {
        if (tid == 0) {
            const unsigned mb = mbq + buf * 8;
            asm volatile("mbarrier.arrive.expect_tx.shared.b64 _, [%0], %1;"
                         :: "r"(mb), "r"((unsigned)STG4) : "memory");
            const unsigned base = sa + buf * STG4;
            tma3(base,             &mAh, k0, m0, bz, mb);
            tma3(base + TILEB,     &mAl, k0, m0, bz, mb);
            tma3(base + 2 * TILEB, &mBh, k0, n0, bz, mb);
            tma3(base + 3 * TILEB, &mBl, k0, n0, bz, mb);
        }
    };

    issue(0, 0);
    if (nslab > 1) issue(1, 64);

    float acc[4][4][4];
#pragma unroll
    for (int i = 0; i < 4; i++)
#pragma unroll
        for (int j = 0; j < 4; j++)
#pragma unroll
            for (int p = 0; p < 4; p++) acc[i][j][p] = 0.f;

    // ldmatrix linear offsets + SW128 xor term (same for A and B: row&7 == lane&7)
    const unsigned aoffL = (unsigned)(m_w + (lane & 15)) * 128 + ((lane >> 4) * 16);
    const unsigned boffL = (unsigned)(n_w + (lane & 7) + ((lane >> 4) << 3)) * 128
                         + ((lane & 8) ? 16 : 0);
    const unsigned sxor = (unsigned)(lane & 7) << 4;

    int phase[2] = {0, 0};
    for (int s = 0; s < nslab; s++) {
        const int buf = s & 1;
        mbar_wait(mbq + buf * 8, (unsigned)phase[buf]);
        phase[buf] ^= 1;
        const unsigned st = sa + buf * STG4;
#pragma unroll
        for (int kk = 0; kk < 4; kk++) {
            unsigned ah[4][4], al[4][4], bh[4][2], bl[4][2];
#pragma unroll
            for (int mb = 0; mb < 4; mb++) {
                const unsigned a = st + ((aoffL + mb * 2048 + kk * 32) ^ sxor);
                ldm_x4(ah[mb][0], ah[mb][1], ah[mb][2], ah[mb][3], a);
                ldm_x4(al[mb][0], al[mb][1], al[mb][2], al[mb][3], a + TILEB);
            }
#pragma unroll
            for (int nbp = 0; nbp < 2; nbp++) {
                const unsigned b = st + 2 * TILEB
                                 + ((boffL + nbp * 2048 + kk * 32) ^ sxor);
                ldm_x4(bh[2*nbp][0], bh[2*nbp][1], bh[2*nbp+1][0], bh[2*nbp+1][1], b);
                ldm_x4(bl[2*nbp][0], bl[2*nbp][1], bl[2*nbp+1][0], bl[2*nbp+1][1],
                       b + TILEB);
            }
#pragma unroll
            for (int mb = 0; mb < 4; mb++)
#pragma unroll
                for (int nb = 0; nb < 4; nb++) {
                    mma16816(acc[mb][nb], ah[mb], bh[nb]);
                    mma16816(acc[mb][nb], ah[mb], bl[nb]);
                    mma16816(acc[mb][nb], al[mb], bh[nb]);
                }
        }
        __syncthreads();
        if (s + 2 < nslab) issue(buf, (s + 2) * 64);
    }

    // ---- epilogue: direct register -> global stores ----
#pragma unroll
    for (int mb = 0; mb < 4; mb++)
#pragma unroll
        for (int p = 0; p < 2; p++) {
            const long long row = m0 + m_w + mb * 16 + (lane >> 2) + p * 8;
#pragma unroll
            for (int nb = 0; nb < 4; nb++) {
                const int col = n0 + n_w + nb * 8 + (lane & 3) * 2;
                float v0 = acc[mb][nb][2 * p];
                float v1 = acc[mb][nb][2 * p + 1];
                if (MODE == 0) {
                    float2 o = make_float2(v0 * scale, v1 * scale);
                    *(float2*)&Cf[(long long)bz * sC + row * ldC + col] = o;
                } else if (MODE == 1) {
                    float2 o = make_float2(v0 + bias[col], v1 + bias[col + 1]);
                    *(float2*)&Cf[row * ldC + col] = o;
                } else {
                    __nv_bfloat16 h0 = __float2bfloat16(v0);
                    __nv_bfloat16 h1 = __float2bfloat16(v1);
                    unsigned ph = bpack(__bfloat162float(h0), __bfloat162float(h1));
                    unsigned pl = bpack(v0 - __bfloat162float(h0),
                                        v1 - __bfloat162float(h1));
                    *(unsigned*)&Ch[row * (long long)ldC + col] = ph;
                    *(unsigned*)&Cl[row * (long long)ldC + col] = pl;
                }
            }
        }
}

// ---------------------------------------------------------------------------
// fp32 -> split bf16 (hi/lo)
// ---------------------------------------------------------------------------
__global__ void __launch_bounds__(256) split_f32(
    const float* __restrict__ src, __nv_bfloat16* __restrict__ h,
    __nv_bfloat16* __restrict__ l, int n4)
{
    int i = blockIdx.x * 256 + threadIdx.x;
    if (i >= n4) return;
    float4 v = ((const float4*)src)[i];
    __nv_bfloat16 h0 = __float2bfloat16(v.x), h1 = __float2bfloat16(v.y);
    __nv_bfloat16 h2 = __float2bfloat16(v.z), h3 = __float2bfloat16(v.w);
    uint2 ph, pl;
    ph.x = bpack(__bfloat162float(h0), __bfloat162float(h1));
    ph.y = bpack(__bfloat162float(h2), __bfloat162float(h3));
    pl.x = bpack(v.x - __bfloat162float(h0), v.y - __bfloat162float(h1));
    pl.y = bpack(v.z - __bfloat162float(h2), v.w - __bfloat162float(h3));
    ((uint2*)h)[i] = ph;
    ((uint2*)l)[i] = pl;
}

// ---------------------------------------------------------------------------
// kT: kth[b][d][m] = kh[b*4096+m][d]
// ---------------------------------------------------------------------------
__global__ void __launch_bounds__(256) transpose_split(
    const __nv_bfloat16* __restrict__ kh, const __nv_bfloat16* __restrict__ kl,
    __nv_bfloat16* __restrict__ kth, __nv_bfloat16* __restrict__ ktl)
{
    __shared__ __nv_bfloat16 th[32][33], tl[32][33];
    const int b = blockIdx.z;
    const int mm0 = blockIdx.x * 32;
    const int d0 = blockIdx.y * 32;
    const int tx = threadIdx.x, ty = threadIdx.y;
    const long long sbase = (long long)(b * 4096 + mm0) * CDIM + d0;
#pragma unroll
    for (int hh = 0; hh < 32; hh += 8) {
        th[ty + hh][tx] = kh[sbase + (long long)(ty + hh) * CDIM + tx];
        tl[ty + hh][tx] = kl[sbase + (long long)(ty + hh) * CDIM + tx];
    }
    __syncthreads();
    const long long dbase = (long long)b * CDIM * MROWS + (long long)d0 * MROWS + mm0;
#pragma unroll
    for (int hh = 0; hh < 32; hh += 8) {
        kth[dbase + (long long)(ty + hh) * MROWS + tx] = th[tx][ty + hh];
        ktl[dbase + (long long)(ty + hh) * MROWS + tx] = tl[tx][ty + hh];
    }
}

// ---------------------------------------------------------------------------
// Row softmax (4096) + post-softmax mask; split-bf16 probability output.
// ---------------------------------------------------------------------------
__global__ void __launch_bounds__(256) softmax_split(
    const float* __restrict__ attn, const int* __restrict__ mask,
    __nv_bfloat16* __restrict__ ah, __nv_bfloat16* __restrict__ al)
{
    __shared__ float rmax[8];
    __shared__ float rsum[8];
    const float* p = attn + (long long)blockIdx.x * MROWS;
    const int t = threadIdx.x;

    float4 v[4];
    float mx = -1e30f;
#pragma unroll
    for (int u = 0; u < 4; u++) {
        v[u] = ((const float4*)p)[u * 256 + t];
        mx = fmaxf(mx, fmaxf(fmaxf(v[u].x, v[u].y), fmaxf(v[u].z, v[u].w)));
    }
#pragma unroll
    for (int o = 16; o > 0; o >>= 1) mx = fmaxf(mx, __shfl_xor_sync(0xffffffffu, mx, o));
    if ((t & 31) == 0) rmax[t >> 5] = mx;
    __syncthreads();
    mx = fmaxf(fmaxf(fmaxf(rmax[0], rmax[1]), fmaxf(rmax[2], rmax[3])),
               fmaxf(fmaxf(rmax[4], rmax[5]), fmaxf(rmax[6], rmax[7])));

    float s = 0.f;
#pragma unroll
    for (int u = 0; u < 4; u++) {
        v[u].x = expf(v[u].x - mx); v[u].y = expf(v[u].y - mx);
        v[u].z = expf(v[u].z - mx); v[u].w = expf(v[u].w - mx);
        s += v[u].x + v[u].y + v[u].z + v[u].w;
    }
#pragma unroll
    for (int o = 16; o > 0; o >>= 1) s += __shfl_xor_sync(0xffffffffu, s, o);
    if ((t & 31) == 0) rsum[t >> 5] = s;
    __syncthreads();
    s = (rsum[0] + rsum[1]) + (rsum[2] + rsum[3]) + (rsum[4] + rsum[5]) + (rsum[6] + rsum[7]);
    const float inv = 1.0f / s;

    __nv_bfloat16* bh = ah + (long long)blockIdx.x * MROWS;
    __nv_bfloat16* bl = al + (long long)blockIdx.x * MROWS;
#pragma unroll
    for (int u = 0; u < 4; u++) {
        const int i4 = u * 256 + t;
        const int4 mq = ((const int4*)mask)[i4];
        float o0 = v[u].x * inv * (mq.x != 0 ? 1.f : 0.f);
        float o1 = v[u].y * inv * (mq.y != 0 ? 1.f : 0.f);
        float o2 = v[u].z * inv * (mq.z != 0 ? 1.f : 0.f);
        float o3 = v[u].w * inv * (mq.w != 0 ? 1.f : 0.f);
        __nv_bfloat16 h0 = __float2bfloat16(o0), h1 = __float2bfloat16(o1);
        __nv_bfloat16 h2 = __float2bfloat16(o2), h3 = __float2bfloat16(o3);
        uint2 ph, pl;
        ph.x = bpack(__bfloat162float(h0), __bfloat162float(h1));
        ph.y = bpack(__bfloat162float(h2), __bfloat162float(h3));
        pl.x = bpack(o0 - __bfloat162float(h0), o1 - __bfloat162float(h1));
        pl.y = bpack(o2 - __bfloat162float(h2), o3 - __bfloat162float(h3));
        ((uint2*)bh)[i4] = ph;
        ((uint2*)bl)[i4] = pl;
    }
}

// ---------------------------------------------------------------------------
// Bug-faithful permute: o2[b, 8a+r, j] = o1[b, r*512 + j, a], split-bf16 out
// ---------------------------------------------------------------------------
__global__ void __launch_bounds__(256) permute_split(
    const float* __restrict__ o1, __nv_bfloat16* __restrict__ oh,
    __nv_bfloat16* __restrict__ ol)
{
    __shared__ float tile[32][33];
    const int br = blockIdx.z;
    const int b = br >> 3;
    const int r = br & 7;
    const float* src = o1 + (long long)b * NROWS * CDIM + (long long)r * 512 * CDIM;
    const long long dbase = (long long)b * NROWS * CDIM + r * CDIM;
    const int j0 = blockIdx.y * 32;
    const int a0 = blockIdx.x * 32;
    const int tx = threadIdx.x, ty = threadIdx.y;

#pragma unroll
    for (int hh = 0; hh < 32; hh += 8)
        tile[ty + hh][tx] = src[(long long)(j0 + ty + hh) * 512 + a0 + tx];
    __syncthreads();
#pragma unroll
    for (int hh = 0; hh < 32; hh += 8) {
        float v = tile[tx][ty + hh];
        long long off = dbase + (long long)(a0 + ty + hh) * 4096 + j0 + tx;
        __nv_bfloat16 hi = __float2bfloat16(v);
        oh[off] = hi;
        ol[off] = __float2bfloat16(v - __bfloat162float(hi));
    }
}

// ---------------------------------------------------------------------------
// Host: tensormap encode via driver entry point (no -lcuda needed)
// ---------------------------------------------------------------------------
typedef CUresult (*PFN_tmapEnc)(
    CUtensorMap*, CUtensorMapDataType, cuuint32_t, void*,
    const cuuint64_t*, const cuuint64_t*, const cuuint32_t*, const cuuint32_t*,
    CUtensorMapInterleave, CUtensorMapSwizzle, CUtensorMapL2promotion,
    CUtensorMapFloatOOBfill);

static void enc_map(PFN_tmapEnc fn, CUtensorMap* m, const void* ptr,
                    unsigned long long K, unsigned long long rows,
                    unsigned long long batches, unsigned long long ldElems,
                    unsigned long long bStrideElems)
{
    cuuint64_t dims[3] = {K, rows, batches};
    cuuint64_t strides[2] = {ldElems * 2ull, bStrideElems * 2ull};
    cuuint32_t box[3] = {64, 128, 1};
    cuuint32_t estr[3] = {1, 1, 1};
    fn(m, CU_TENSOR_MAP_DATA_TYPE_BFLOAT16, 3, (void*)ptr,
       dims, strides, box, estr,
       CU_TENSOR_MAP_INTERLEAVE_NONE, CU_TENSOR_MAP_SWIZZLE_128B,
       CU_TENSOR_MAP_L2_PROMOTION_L2_128B, CU_TENSOR_MAP_FLOAT_OOB_FILL_NONE);
}

extern "C" void kernel_launch(void* const* d_in, const int* in_sizes, int n_in,
                              void* d_out, int out_size)
{
    const float* x       = (const float*)d_in[0];
    const float* support = (const float*)d_in[1];
    const int*   mask    = (const int*)  d_in[2];
    const float* Wv      = (const float*)d_in[3];
    const float* Wp      = (const float*)d_in[4];
    const float* bp      = (const float*)d_in[5];
    float* out = (float*)d_out;

    float *attn, *o1;
    __nv_bfloat16 *xh, *xl, *sh, *sl, *wvh, *wvl, *wph, *wpl;
    __nv_bfloat16 *qh, *ql, *kh, *kl, *kth, *ktl, *ah, *al, *o2h, *o2l;
    cudaGetSymbolAddress((void**)&attn, g_attn);
    cudaGetSymbolAddress((void**)&o1,   g_o1);
    cudaGetSymbolAddress((void**)&xh, g_xh);   cudaGetSymbolAddress((void**)&xl, g_xl);
    cudaGetSymbolAddress((void**)&sh, g_sh);   cudaGetSymbolAddress((void**)&sl, g_sl);
    cudaGetSymbolAddress((void**)&wvh, g_wvh); cudaGetSymbolAddress((void**)&wvl, g_wvl);
    cudaGetSymbolAddress((void**)&wph, g_wph); cudaGetSymbolAddress((void**)&wpl, g_wpl);
    cudaGetSymbolAddress((void**)&qh, g_qh);   cudaGetSymbolAddress((void**)&ql, g_ql);
    cudaGetSymbolAddress((void**)&kh, g_kh);   cudaGetSymbolAddress((void**)&kl, g_kl);
    cudaGetSymbolAddress((void**)&kth, g_kth); cudaGetSymbolAddress((void**)&ktl, g_ktl);
    cudaGetSymbolAddress((void**)&ah, g_ah);   cudaGetSymbolAddress((void**)&al, g_al);
    cudaGetSymbolAddress((void**)&o2h, g_o2h); cudaGetSymbolAddress((void**)&o2l, g_o2l);

    // driver entry point for cuTensorMapEncodeTiled
    void* sym = nullptr;
    cudaDriverEntryPointQueryResult qres;
    cudaGetDriverEntryPointByVersion("cuTensorMapEncodeTiled", &sym, 12000,
                                     cudaEnableDefault, &qres);
    PFN_tmapEnc enc = (PFN_tmapEnc)sym;

    const long long sQK = (long long)NROWS * CDIM;
    const long long sAT = (long long)NROWS * MROWS;

    // tensormaps
    CUtensorMap tQh, tQl, tKh, tKl;           // QK^T
    enc_map(enc, &tQh, qh, CDIM, NROWS, BB, CDIM, sQK);
    enc_map(enc, &tQl, ql, CDIM, NROWS, BB, CDIM, sQK);
    enc_map(enc, &tKh, kh, CDIM, NROWS, BB, CDIM, sQK);
    enc_map(enc, &tKl, kl, CDIM, NROWS, BB, CDIM, sQK);
    CUtensorMap tXh, tXl, tSh, tSl, tWvh, tWvl, tWph, tWpl;
    enc_map(enc, &tXh, xh, CDIM, TOTQ, 1, CDIM, (long long)TOTQ * CDIM);
    enc_map(enc, &tXl, xl, CDIM, TOTQ, 1, CDIM, (long long)TOTQ * CDIM);
    enc_map(enc, &tSh, sh, CDIM, TOTQ, 1, CDIM, (long long)TOTQ * CDIM);
    enc_map(enc, &tSl, sl, CDIM, TOTQ, 1, CDIM, (long long)TOTQ * CDIM);
    enc_map(enc, &tWvh, wvh, CDIM, CDIM, 1, CDIM, (long long)CDIM * CDIM);
    enc_map(enc, &tWvl, wvl, CDIM, CDIM, 1, CDIM, (long long)CDIM * CDIM);
    enc_map(enc, &tWph, wph, CDIM, CDIM, 1, CDIM, (long long)CDIM * CDIM);
    enc_map(enc, &tWpl, wpl, CDIM, CDIM, 1, CDIM, (long long)CDIM * CDIM);
    CUtensorMap tAh, tAl, tKTh, tKTl;         // AV
    enc_map(enc, &tAh, ah, MROWS, NROWS, BB, MROWS, sAT);
    enc_map(enc, &tAl, al, MROWS, NROWS, BB, MROWS, sAT);
    enc_map(enc, &tKTh, kth, MROWS, CDIM, BB, MROWS, (long long)CDIM * MROWS);
    enc_map(enc, &tKTl, ktl, MROWS, CDIM, BB, MROWS, (long long)CDIM * MROWS);
    CUtensorMap tO2h, tO2l;                    // out proj
    enc_map(enc, &tO2h, o2h, CDIM, TOTQ, 1, CDIM, (long long)TOTQ * CDIM);
    enc_map(enc, &tO2l, o2l, CDIM, TOTQ, 1, CDIM, (long long)TOTQ * CDIM);

    cudaFuncSetAttribute(tma_gemm<0>, cudaFuncAttributeMaxDynamicSharedMemorySize, SMEM_DYN);
    cudaFuncSetAttribute(tma_gemm<1>, cudaFuncAttributeMaxDynamicSharedMemorySize, SMEM_DYN);
    cudaFuncSetAttribute(tma_gemm<2>, cudaFuncAttributeMaxDynamicSharedMemorySize, SMEM_DYN);

    // 1) conversions
    split_f32<<<TOTQ * CDIM / 4 / 256, 256>>>(x,       xh, xl, TOTQ * CDIM / 4);
    split_f32<<<TOTQ * CDIM / 4 / 256, 256>>>(support, sh, sl, TOTQ * CDIM / 4);
    split_f32<<<CDIM * CDIM / 4 / 256, 256>>>(Wv,      wvh, wvl, CDIM * CDIM / 4);
    split_f32<<<CDIM * CDIM / 4 / 256, 256>>>(Wp,      wph, wpl, CDIM * CDIM / 4);

    // 2) q = x @ Wv^T ; k = support @ Wv^T (split outs)
    tma_gemm<2><<<dim3(4, 128, 1), 256, SMEM_DYN>>>(
        tXh, tXl, tWvh, tWvl, CDIM, CDIM, 1.0f, 0, nullptr, nullptr, qh, ql);
    tma_gemm<2><<<dim3(4, 128, 1), 256, SMEM_DYN>>>(
        tSh, tSl, tWvh, tWvl, CDIM, CDIM, 1.0f, 0, nullptr, nullptr, kh, kl);

    // 3) kT[b][d][m]
    transpose_split<<<dim3(128, 16, BB), dim3(32, 8)>>>(kh, kl, kth, ktl);

    // 4) attn = 0.125 * q @ k^T (fp32, batched)
    tma_gemm<0><<<dim3(32, 32, BB), 256, SMEM_DYN>>>(
        tQh, tQl, tKh, tKl, MROWS, CDIM, 0.125f, sAT, nullptr, attn,
        nullptr, nullptr);

    // 5) softmax + mask -> split-bf16 probs
    softmax_split<<<TOTQ, 256>>>(attn, mask, ah, al);

    // 6) o1 = attn @ v   (B = kT)
    tma_gemm<0><<<dim3(4, 32, BB), 256, SMEM_DYN>>>(
        tAh, tAl, tKTh, tKTl, CDIM, MROWS, 1.0f, sQK, nullptr, o1,
        nullptr, nullptr);

    // 7) bug-faithful permute -> split-bf16
    permute_split<<<dim3(16, 16, BB * 8), dim3(32, 8)>>>(o1, o2h, o2l);

    // 8) out = o2 @ Wp^T + bp
    tma_gemm<1><<<dim3(4, 128, 1), 256, SMEM_DYN>>>(
        tO2h, tO2l, tWph, tWpl, CDIM, CDIM, 1.0f, 0, bp, out, nullptr, nullptr);
}

// round 6
// speedup vs baseline: 2.8785x; 1.0492x over previous
#include <cuda_runtime.h>
#include <cuda_bf16.h>
#include <cuda.h>

#define BB 4
#define NROWS 4096
#define MROWS 4096
#define CDIM 512
#define TOTQ (BB*NROWS)

// ---------------------------------------------------------------------------
// Device scratch
// ---------------------------------------------------------------------------
__device__ __align__(16) float g_attn[(size_t)BB * NROWS * MROWS];   // 268 MB
__device__ __align__(16) float g_o1[(size_t)TOTQ * CDIM];
__device__ __align__(16) __nv_bfloat16 g_xh[(size_t)TOTQ*CDIM], g_xl[(size_t)TOTQ*CDIM];
__device__ __align__(16) __nv_bfloat16 g_sh[(size_t)TOTQ*CDIM], g_sl[(size_t)TOTQ*CDIM];
__device__ __align__(16) __nv_bfloat16 g_wvh[CDIM*CDIM], g_wvl[CDIM*CDIM];
__device__ __align__(16) __nv_bfloat16 g_wph[CDIM*CDIM], g_wpl[CDIM*CDIM];
__device__ __align__(16) __nv_bfloat16 g_qh[(size_t)TOTQ*CDIM], g_ql[(size_t)TOTQ*CDIM];
__device__ __align__(16) __nv_bfloat16 g_kh[(size_t)TOTQ*CDIM], g_kl[(size_t)TOTQ*CDIM];
__device__ __align__(16) __nv_bfloat16 g_kth[(size_t)TOTQ*CDIM], g_ktl[(size_t)TOTQ*CDIM];
__device__ __align__(16) __nv_bfloat16 g_ah[(size_t)BB*NROWS*MROWS];  // 134 MB
__device__ __align__(16) __nv_bfloat16 g_al[(size_t)BB*NROWS*MROWS];  // 134 MB
__device__ __align__(16) __nv_bfloat16 g_o2h[(size_t)TOTQ*CDIM], g_o2l[(size_t)TOTQ*CDIM];

// ---------------------------------------------------------------------------
// device helpers
// ---------------------------------------------------------------------------
static __device__ __forceinline__ unsigned smem_u32(const void* p) {
    unsigned a;
    asm("{ .reg .u64 t; cvta.to.shared.u64 t, %1; cvt.u32.u64 %0, t; }" : "=r"(a) : "l"(p));
    return a;
}
static __device__ __forceinline__ void ldm_x4(unsigned& r0, unsigned& r1,
                                              unsigned& r2, unsigned& r3, unsigned a) {
    asm volatile("ldmatrix.sync.aligned.m8n8.x4.shared.b16 {%0,%1,%2,%3}, [%4];"
                 : "=r"(r0), "=r"(r1), "=r"(r2), "=r"(r3) : "r"(a));
}
static __device__ __forceinline__ void mma16816(float* c, const unsigned* a,
                                                const unsigned* b) {
    asm volatile(
        "mma.sync.aligned.m16n8k16.row.col.f32.bf16.bf16.f32 "
        "{%0,%1,%2,%3}, {%4,%5,%6,%7}, {%8,%9}, {%0,%1,%2,%3};"
        : "+f"(c[0]), "+f"(c[1]), "+f"(c[2]), "+f"(c[3])
        : "r"(a[0]), "r"(a[1]), "r"(a[2]), "r"(a[3]), "r"(b[0]), "r"(b[1]));
}
static __device__ __forceinline__ unsigned bpack(float a, float b) {
    __nv_bfloat162 t = __floats2bfloat162_rn(a, b);
    return *reinterpret_cast<unsigned*>(&t);
}
static __device__ __forceinline__ void mbar_wait(unsigned mbar, unsigned phase) {
    asm volatile(
        "{\n\t.reg .pred P1;\n\t"
        "LAB_WAIT_%=:\n\t"
        "mbarrier.try_wait.parity.acquire.cta.shared::cta.b64 P1, [%0], %1, 0x989680;\n\t"
        "@P1 bra.uni LAB_DONE_%=;\n\t"
        "bra.uni LAB_WAIT_%=;\n\t"
        "LAB_DONE_%=:\n\t}"
        :: "r"(mbar), "r"(phase) : "memory");
}
static __device__ __forceinline__ void tma3(unsigned dst, const CUtensorMap* m,
                                            int x, int y, int z, unsigned mb) {
    asm volatile(
        "cp.async.bulk.tensor.3d.shared::cluster.global.tile.mbarrier::complete_tx::bytes "
        "[%0], [%1, {%2, %3, %4}], [%5];"
        :: "r"(dst), "l"(m), "r"(x), "r"(y), "r"(z), "r"(mb) : "memory");
}

// ---------------------------------------------------------------------------
// Split-bf16 HMMA GEMM, TMA loads. CTA 128x256, warp tile 64x64 (2x4 warps),
// K-slab 64, 2-stage TMA double buffer, SW128 swizzled smem.
// C = A @ B^T; A [rows,K], B [rows,K] row-major, hi/lo bf16 pairs.
// MODE 0: Cf = scale*acc (batched)  MODE 1: Cf = acc + bias
// MODE 2: (Ch,Cl) = split(acc)
// ---------------------------------------------------------------------------
#define TILEA 16384                 // 128x64 bf16
#define TILEB2 32768                // 256x64 bf16
#define STGB (2*TILEA + 2*TILEB2)   // 98304 per stage
#define OFF_BH (2*TILEA)
#define OFF_BL (2*TILEA + TILEB2)
#define SMEM_DYN (1024 + 2*STGB)    // 197632

template<int MODE>
__global__ void __launch_bounds__(256, 1) tma_gemm(
    const __grid_constant__ CUtensorMap mAh, const __grid_constant__ CUtensorMap mAl,
    const __grid_constant__ CUtensorMap mBh, const __grid_constant__ CUtensorMap mBl,
    int ldC, int Kdim, float scale, long long sC,
    const float* __restrict__ bias, float* __restrict__ Cf,
    __nv_bfloat16* __restrict__ Ch, __nv_bfloat16* __restrict__ Cl)
{
    extern __shared__ char smem[];
    __shared__ __align__(16) unsigned long long mbar[2];
    const unsigned sa = (smem_u32(smem) + 1023) & ~1023u;
    const unsigned mbq = smem_u32(mbar);
    const int tid = threadIdx.x;
    const int wid = tid >> 5;
    const int lane = tid & 31;
    const int m0 = blockIdx.y * 128;
    const int n0 = blockIdx.x * 256;
    const int bz = blockIdx.z;

    const int m_w = (wid >> 2) * 64;   // 0 / 64
    const int n_w = (wid & 3) * 64;    // 0..192

    if (tid == 0) {
        asm volatile("mbarrier.init.shared.b64 [%0], 1;" :: "r"(mbq) : "memory");
        asm volatile("mbarrier.init.shared.b64 [%0], 1;" :: "r"(mbq + 8) : "memory");
    }
    __syncthreads();

    const int nslab = Kdim / 64;
    auto issue = [&](int buf, int k0) {
        if (tid == 0) {
            const unsigned mb = mbq + buf * 8;
            asm volatile("mbarrier.arrive.expect_tx.shared.b64 _, [%0], %1;"
                         :: "r"(mb), "r"((unsigned)STGB) : "memory");
            const unsigned base = sa + buf * STGB;
            tma3(base,          &mAh, k0, m0, bz, mb);
            tma3(base + TILEA,  &mAl, k0, m0, bz, mb);
            tma3(base + OFF_BH, &mBh, k0, n0, bz, mb);
            tma3(base + OFF_BL, &mBl, k0, n0, bz, mb);
        }
    };

    issue(0, 0);
    if (nslab > 1) issue(1, 64);

    float acc[4][8][4];
#pragma unroll
    for (int i = 0; i < 4; i++)
#pragma unroll
        for (int j = 0; j < 8; j++)
#pragma unroll
            for (int p = 0; p < 4; p++) acc[i][j][p] = 0.f;

    const unsigned aoffL = (unsigned)(m_w + (lane & 15)) * 128 + ((lane >> 4) * 16);
    const unsigned boffL = (unsigned)(n_w + (lane & 7) + ((lane >> 4) << 3)) * 128
                         + ((lane & 8) ? 16 : 0);
    const unsigned sxor = (unsigned)(lane & 7) << 4;

    int phase[2] = {0, 0};
    for (int s = 0; s < nslab; s++) {
        const int buf = s & 1;
        mbar_wait(mbq + buf * 8, (unsigned)phase[buf]);
        phase[buf] ^= 1;
        const unsigned st = sa + buf * STGB;
#pragma unroll
        for (int kk = 0; kk < 4; kk++) {
            unsigned ah[4][4], al[4][4];
#pragma unroll
            for (int mb = 0; mb < 4; mb++) {
                const unsigned a = st + ((aoffL + mb * 2048 + kk * 32) ^ sxor);
                ldm_x4(ah[mb][0], ah[mb][1], ah[mb][2], ah[mb][3], a);
                ldm_x4(al[mb][0], al[mb][1], al[mb][2], al[mb][3], a + TILEA);
            }
#pragma unroll
            for (int nbp = 0; nbp < 4; nbp++) {
                unsigned bh[2][2], bl[2][2];
                const unsigned b = st + OFF_BH + ((boffL + nbp * 2048 + kk * 32) ^ sxor);
                ldm_x4(bh[0][0], bh[0][1], bh[1][0], bh[1][1], b);
                ldm_x4(bl[0][0], bl[0][1], bl[1][0], bl[1][1], b + TILEB2);
#pragma unroll
                for (int mb = 0; mb < 4; mb++)
#pragma unroll
                    for (int j = 0; j < 2; j++) {
                        float* c = acc[mb][2 * nbp + j];
                        mma16816(c, ah[mb], bh[j]);
                        mma16816(c, ah[mb], bl[j]);
                        mma16816(c, al[mb], bh[j]);
                    }
            }
        }
        __syncthreads();
        if (s + 2 < nslab) issue(buf, (s + 2) * 64);
    }

    // ---- epilogue: direct register -> global stores ----
#pragma unroll
    for (int mb = 0; mb < 4; mb++)
#pragma unroll
        for (int p = 0; p < 2; p++) {
            const long long row = m0 + m_w + mb * 16 + (lane >> 2) + p * 8;
#pragma unroll
            for (int nb = 0; nb < 8; nb++) {
                const int col = n0 + n_w + nb * 8 + (lane & 3) * 2;
                float v0 = acc[mb][nb][2 * p];
                float v1 = acc[mb][nb][2 * p + 1];
                if (MODE == 0) {
                    float2 o = make_float2(v0 * scale, v1 * scale);
                    *(float2*)&Cf[(long long)bz * sC + row * ldC + col] = o;
                } else if (MODE == 1) {
                    float2 o = make_float2(v0 + bias[col], v1 + bias[col + 1]);
                    *(float2*)&Cf[row * ldC + col] = o;
                } else {
                    __nv_bfloat16 h0 = __float2bfloat16(v0);
                    __nv_bfloat16 h1 = __float2bfloat16(v1);
                    unsigned ph = bpack(__bfloat162float(h0), __bfloat162float(h1));
                    unsigned pl = bpack(v0 - __bfloat162float(h0),
                                        v1 - __bfloat162float(h1));
                    *(unsigned*)&Ch[row * (long long)ldC + col] = ph;
                    *(unsigned*)&Cl[row * (long long)ldC + col] = pl;
                }
            }
        }
}

// ---------------------------------------------------------------------------
// fp32 -> split bf16 (hi/lo)
// ---------------------------------------------------------------------------
__global__ void __launch_bounds__(256) split_f32(
    const float* __restrict__ src, __nv_bfloat16* __restrict__ h,
    __nv_bfloat16* __restrict__ l, int n4)
{
    int i = blockIdx.x * 256 + threadIdx.x;
    if (i >= n4) return;
    float4 v = ((const float4*)src)[i];
    __nv_bfloat16 h0 = __float2bfloat16(v.x), h1 = __float2bfloat16(v.y);
    __nv_bfloat16 h2 = __float2bfloat16(v.z), h3 = __float2bfloat16(v.w);
    uint2 ph, pl;
    ph.x = bpack(__bfloat162float(h0), __bfloat162float(h1));
    ph.y = bpack(__bfloat162float(h2), __bfloat162float(h3));
    pl.x = bpack(v.x - __bfloat162float(h0), v.y - __bfloat162float(h1));
    pl.y = bpack(v.z - __bfloat162float(h2), v.w - __bfloat162float(h3));
    ((uint2*)h)[i] = ph;
    ((uint2*)l)[i] = pl;
}

// ---------------------------------------------------------------------------
// kT: kth[b][d][m] = kh[b*4096+m][d]
// ---------------------------------------------------------------------------
__global__ void __launch_bounds__(256) transpose_split(
    const __nv_bfloat16* __restrict__ kh, const __nv_bfloat16* __restrict__ kl,
    __nv_bfloat16* __restrict__ kth, __nv_bfloat16* __restrict__ ktl)
{
    __shared__ __nv_bfloat16 th[32][33], tl[32][33];
    const int b = blockIdx.z;
    const int mm0 = blockIdx.x * 32;
    const int d0 = blockIdx.y * 32;
    const int tx = threadIdx.x, ty = threadIdx.y;
    const long long sbase = (long long)(b * 4096 + mm0) * CDIM + d0;
#pragma unroll
    for (int hh = 0; hh < 32; hh += 8) {
        th[ty + hh][tx] = kh[sbase + (long long)(ty + hh) * CDIM + tx];
        tl[ty + hh][tx] = kl[sbase + (long long)(ty + hh) * CDIM + tx];
    }
    __syncthreads();
    const long long dbase = (long long)b * CDIM * MROWS + (long long)d0 * MROWS + mm0;
#pragma unroll
    for (int hh = 0; hh < 32; hh += 8) {
        kth[dbase + (long long)(ty + hh) * MROWS + tx] = th[tx][ty + hh];
        ktl[dbase + (long long)(ty + hh) * MROWS + tx] = tl[tx][ty + hh];
    }
}

// ---------------------------------------------------------------------------
// Row softmax (4096) + post-softmax mask; split-bf16 probability output.
// ---------------------------------------------------------------------------
__global__ void __launch_bounds__(256) softmax_split(
    const float* __restrict__ attn, const int* __restrict__ mask,
    __nv_bfloat16* __restrict__ ah, __nv_bfloat16* __restrict__ al)
{
    __shared__ float rmax[8];
    __shared__ float rsum[8];
    const float* p = attn + (long long)blockIdx.x * MROWS;
    const int t = threadIdx.x;

    float4 v[4];
    float mx = -1e30f;
#pragma unroll
    for (int u = 0; u < 4; u++) {
        v[u] = ((const float4*)p)[u * 256 + t];
        mx = fmaxf(mx, fmaxf(fmaxf(v[u].x, v[u].y), fmaxf(v[u].z, v[u].w)));
    }
#pragma unroll
    for (int o = 16; o > 0; o >>= 1) mx = fmaxf(mx, __shfl_xor_sync(0xffffffffu, mx, o));
    if ((t & 31) == 0) rmax[t >> 5] = mx;
    __syncthreads();
    mx = fmaxf(fmaxf(fmaxf(rmax[0], rmax[1]), fmaxf(rmax[2], rmax[3])),
               fmaxf(fmaxf(rmax[4], rmax[5]), fmaxf(rmax[6], rmax[7])));

    float s = 0.f;
#pragma unroll
    for (int u = 0; u < 4; u++) {
        v[u].x = expf(v[u].x - mx); v[u].y = expf(v[u].y - mx);
        v[u].z = expf(v[u].z - mx); v[u].w = expf(v[u].w - mx);
        s += v[u].x + v[u].y + v[u].z + v[u].w;
    }
#pragma unroll
    for (int o = 16; o > 0; o >>= 1) s += __shfl_xor_sync(0xffffffffu, s, o);
    if ((t & 31) == 0) rsum[t >> 5] = s;
    __syncthreads();
    s = (rsum[0] + rsum[1]) + (rsum[2] + rsum[3]) + (rsum[4] + rsum[5]) + (rsum[6] + rsum[7]);
    const float inv = 1.0f / s;

    __nv_bfloat16* bh = ah + (long long)blockIdx.x * MROWS;
    __nv_bfloat16* bl = al + (long long)blockIdx.x * MROWS;
#pragma unroll
    for (int u = 0; u < 4; u++) {
        const int i4 = u * 256 + t;
        const int4 mq = ((const int4*)mask)[i4];
        float o0 = v[u].x * inv * (mq.x != 0 ? 1.f : 0.f);
        float o1 = v[u].y * inv * (mq.y != 0 ? 1.f : 0.f);
        float o2 = v[u].z * inv * (mq.z != 0 ? 1.f : 0.f);
        float o3 = v[u].w * inv * (mq.w != 0 ? 1.f : 0.f);
        __nv_bfloat16 h0 = __float2bfloat16(o0), h1 = __float2bfloat16(o1);
        __nv_bfloat16 h2 = __float2bfloat16(o2), h3 = __float2bfloat16(o3);
        uint2 ph, pl;
        ph.x = bpack(__bfloat162float(h0), __bfloat162float(h1));
        ph.y = bpack(__bfloat162float(h2), __bfloat162float(h3));
        pl.x = bpack(o0 - __bfloat162float(h0), o1 - __bfloat162float(h1));
        pl.y = bpack(o2 - __bfloat162float(h2), o3 - __bfloat162float(h3));
        ((uint2*)bh)[i4] = ph;
        ((uint2*)bl)[i4] = pl;
    }
}

// ---------------------------------------------------------------------------
// Bug-faithful permute: o2[b, 8a+r, j] = o1[b, r*512 + j, a], split-bf16 out
// ---------------------------------------------------------------------------
__global__ void __launch_bounds__(256) permute_split(
    const float* __restrict__ o1, __nv_bfloat16* __restrict__ oh,
    __nv_bfloat16* __restrict__ ol)
{
    __shared__ float tile[32][33];
    const int br = blockIdx.z;
    const int b = br >> 3;
    const int r = br & 7;
    const float* src = o1 + (long long)b * NROWS * CDIM + (long long)r * 512 * CDIM;
    const long long dbase = (long long)b * NROWS * CDIM + r * CDIM;
    const int j0 = blockIdx.y * 32;
    const int a0 = blockIdx.x * 32;
    const int tx = threadIdx.x, ty = threadIdx.y;

#pragma unroll
    for (int hh = 0; hh < 32; hh += 8)
        tile[ty + hh][tx] = src[(long long)(j0 + ty + hh) * 512 + a0 + tx];
    __syncthreads();
#pragma unroll
    for (int hh = 0; hh < 32; hh += 8) {
        float v = tile[tx][ty + hh];
        long long off = dbase + (long long)(a0 + ty + hh) * 4096 + j0 + tx;
        __nv_bfloat16 hi = __float2bfloat16(v);
        oh[off] = hi;
        ol[off] = __float2bfloat16(v - __bfloat162float(hi));
    }
}

// ---------------------------------------------------------------------------
// Host: tensormap encode via driver entry point
// ---------------------------------------------------------------------------
typedef CUresult (*PFN_tmapEnc)(
    CUtensorMap*, CUtensorMapDataType, cuuint32_t, void*,
    const cuuint64_t*, const cuuint64_t*, const cuuint32_t*, const cuuint32_t*,
    CUtensorMapInterleave, CUtensorMapSwizzle, CUtensorMapL2promotion,
    CUtensorMapFloatOOBfill);

static void enc_map(PFN_tmapEnc fn, CUtensorMap* m, const void* ptr,
                    unsigned long long K, unsigned long long rows,
                    unsigned long long batches, unsigned long long ldElems,
                    unsigned long long bStrideElems, unsigned boxRows)
{
    cuuint64_t dims[3] = {K, rows, batches};
    cuuint64_t strides[2] = {ldElems * 2ull, bStrideElems * 2ull};
    cuuint32_t box[3] = {64, boxRows, 1};
    cuuint32_t estr[3] = {1, 1, 1};
    fn(m, CU_TENSOR_MAP_DATA_TYPE_BFLOAT16, 3, (void*)ptr,
       dims, strides, box, estr,
       CU_TENSOR_MAP_INTERLEAVE_NONE, CU_TENSOR_MAP_SWIZZLE_128B,
       CU_TENSOR_MAP_L2_PROMOTION_L2_128B, CU_TENSOR_MAP_FLOAT_OOB_FILL_NONE);
}

extern "C" void kernel_launch(void* const* d_in, const int* in_sizes, int n_in,
                              void* d_out, int out_size)
{
    const float* x       = (const float*)d_in[0];
    const float* support = (const float*)d_in[1];
    const int*   mask    = (const int*)  d_in[2];
    const float* Wv      = (const float*)d_in[3];
    const float* Wp      = (const float*)d_in[4];
    const float* bp      = (const float*)d_in[5];
    float* out = (float*)d_out;

    float *attn, *o1;
    __nv_bfloat16 *xh, *xl, *sh, *sl, *wvh, *wvl, *wph, *wpl;
    __nv_bfloat16 *qh, *ql, *kh, *kl, *kth, *ktl, *ah, *al, *o2h, *o2l;
    cudaGetSymbolAddress((void**)&attn, g_attn);
    cudaGetSymbolAddress((void**)&o1,   g_o1);
    cudaGetSymbolAddress((void**)&xh, g_xh);   cudaGetSymbolAddress((void**)&xl, g_xl);
    cudaGetSymbolAddress((void**)&sh, g_sh);   cudaGetSymbolAddress((void**)&sl, g_sl);
    cudaGetSymbolAddress((void**)&wvh, g_wvh); cudaGetSymbolAddress((void**)&wvl, g_wvl);
    cudaGetSymbolAddress((void**)&wph, g_wph); cudaGetSymbolAddress((void**)&wpl, g_wpl);
    cudaGetSymbolAddress((void**)&qh, g_qh);   cudaGetSymbolAddress((void**)&ql, g_ql);
    cudaGetSymbolAddress((void**)&kh, g_kh);   cudaGetSymbolAddress((void**)&kl, g_kl);
    cudaGetSymbolAddress((void**)&kth, g_kth); cudaGetSymbolAddress((void**)&ktl, g_ktl);
    cudaGetSymbolAddress((void**)&ah, g_ah);   cudaGetSymbolAddress((void**)&al, g_al);
    cudaGetSymbolAddress((void**)&o2h, g_o2h); cudaGetSymbolAddress((void**)&o2l, g_o2l);

    void* sym = nullptr;
    cudaDriverEntryPointQueryResult qres;
    cudaGetDriverEntryPointByVersion("cuTensorMapEncodeTiled", &sym, 12000,
                                     cudaEnableDefault, &qres);
    PFN_tmapEnc enc = (PFN_tmapEnc)sym;

    const long long sQK = (long long)NROWS * CDIM;
    const long long sAT = (long long)NROWS * MROWS;

    // tensormaps: A operands box {64,128}, B operands box {64,256}
    CUtensorMap tQh, tQl, tKh, tKl;
    enc_map(enc, &tQh, qh, CDIM, NROWS, BB, CDIM, sQK, 128);
    enc_map(enc, &tQl, ql, CDIM, NROWS, BB, CDIM, sQK, 128);
    enc_map(enc, &tKh, kh, CDIM, NROWS, BB, CDIM, sQK, 256);
    enc_map(enc, &tKl, kl, CDIM, NROWS, BB, CDIM, sQK, 256);
    CUtensorMap tXh, tXl, tSh, tSl, tWvh, tWvl, tWph, tWpl;
    enc_map(enc, &tXh, xh, CDIM, TOTQ, 1, CDIM, (long long)TOTQ * CDIM, 128);
    enc_map(enc, &tXl, xl, CDIM, TOTQ, 1, CDIM, (long long)TOTQ * CDIM, 128);
    enc_map(enc, &tSh, sh, CDIM, TOTQ, 1, CDIM, (long long)TOTQ * CDIM, 128);
    enc_map(enc, &tSl, sl, CDIM, TOTQ, 1, CDIM, (long long)TOTQ * CDIM, 128);
    enc_map(enc, &tWvh, wvh, CDIM, CDIM, 1, CDIM, (long long)CDIM * CDIM, 256);
    enc_map(enc, &tWvl, wvl, CDIM, CDIM, 1, CDIM, (long long)CDIM * CDIM, 256);
    enc_map(enc, &tWph, wph, CDIM, CDIM, 1, CDIM, (long long)CDIM * CDIM, 256);
    enc_map(enc, &tWpl, wpl, CDIM, CDIM, 1, CDIM, (long long)CDIM * CDIM, 256);
    CUtensorMap tAh, tAl, tKTh, tKTl;
    enc_map(enc, &tAh, ah, MROWS, NROWS, BB, MROWS, sAT, 128);
    enc_map(enc, &tAl, al, MROWS, NROWS, BB, MROWS, sAT, 128);
    enc_map(enc, &tKTh, kth, MROWS, CDIM, BB, MROWS, (long long)CDIM * MROWS, 256);
    enc_map(enc, &tKTl, ktl, MROWS, CDIM, BB, MROWS, (long long)CDIM * MROWS, 256);
    CUtensorMap tO2h, tO2l;
    enc_map(enc, &tO2h, o2h, CDIM, TOTQ, 1, CDIM, (long long)TOTQ * CDIM, 128);
    enc_map(enc, &tO2l, o2l, CDIM, TOTQ, 1, CDIM, (long long)TOTQ * CDIM, 128);

    cudaFuncSetAttribute(tma_gemm<0>, cudaFuncAttributeMaxDynamicSharedMemorySize, SMEM_DYN);
    cudaFuncSetAttribute(tma_gemm<1>, cudaFuncAttributeMaxDynamicSharedMemorySize, SMEM_DYN);
    cudaFuncSetAttribute(tma_gemm<2>, cudaFuncAttributeMaxDynamicSharedMemorySize, SMEM_DYN);

    // 1) conversions
    split_f32<<<TOTQ * CDIM / 4 / 256, 256>>>(x,       xh, xl, TOTQ * CDIM / 4);
    split_f32<<<TOTQ * CDIM / 4 / 256, 256>>>(support, sh, sl, TOTQ * CDIM / 4);
    split_f32<<<CDIM * CDIM / 4 / 256, 256>>>(Wv,      wvh, wvl, CDIM * CDIM / 4);
    split_f32<<<CDIM * CDIM / 4 / 256, 256>>>(Wp,      wph, wpl, CDIM * CDIM / 4);

    // 2) q = x @ Wv^T ; k = support @ Wv^T (split outs)
    tma_gemm<2><<<dim3(2, 128, 1), 256, SMEM_DYN>>>(
        tXh, tXl, tWvh, tWvl, CDIM, CDIM, 1.0f, 0, nullptr, nullptr, qh, ql);
    tma_gemm<2><<<dim3(2, 128, 1), 256, SMEM_DYN>>>(
        tSh, tSl, tWvh, tWvl, CDIM, CDIM, 1.0f, 0, nullptr, nullptr, kh, kl);

    // 3) kT[b][d][m]
    transpose_split<<<dim3(128, 16, BB), dim3(32, 8)>>>(kh, kl, kth, ktl);

    // 4) attn = 0.125 * q @ k^T (fp32, batched)
    tma_gemm<0><<<dim3(16, 32, BB), 256, SMEM_DYN>>>(
        tQh, tQl, tKh, tKl, MROWS, CDIM, 0.125f, sAT, nullptr, attn,
        nullptr, nullptr);

    // 5) softmax + mask -> split-bf16 probs
    softmax_split<<<TOTQ, 256>>>(attn, mask, ah, al);

    // 6) o1 = attn @ v   (B = kT)
    tma_gemm<0><<<dim3(2, 32, BB), 256, SMEM_DYN>>>(
        tAh, tAl, tKTh, tKTl, CDIM, MROWS, 1.0f, sQK, nullptr, o1,
        nullptr, nullptr);

    // 7) bug-faithful permute -> split-bf16
    permute_split<<<dim3(16, 16, BB * 8), dim3(32, 8)>>>(o1, o2h, o2l);

    // 8) out = o2 @ Wp^T + bp
    tma_gemm<1><<<dim3(2, 128, 1), 256, SMEM_DYN>>>(
        tO2h, tO2l, tWph, tWpl, CDIM, CDIM, 1.0f, 0, bp, out, nullptr, nullptr);
}

// round 7
// speedup vs baseline: 3.7226x; 1.2932x over previous
#include <cuda_runtime.h>
#include <cuda_fp16.h>
#include <cuda.h>

#define BB 4
#define NROWS 4096
#define MROWS 4096
#define CDIM 512
#define TOTQ (BB*NROWS)

// ---------------------------------------------------------------------------
// Device scratch (fp16 split: hi/lo)
// ---------------------------------------------------------------------------
__device__ __align__(16) float g_attn[(size_t)BB * NROWS * MROWS];   // 268 MB
__device__ __align__(16) float g_o1[(size_t)TOTQ * CDIM];
__device__ __align__(16) __half g_xh[(size_t)TOTQ*CDIM], g_xl[(size_t)TOTQ*CDIM];
__device__ __align__(16) __half g_sh[(size_t)TOTQ*CDIM], g_sl[(size_t)TOTQ*CDIM];
__device__ __align__(16) __half g_wvh[CDIM*CDIM], g_wvl[CDIM*CDIM];
__device__ __align__(16) __half g_wph[CDIM*CDIM], g_wpl[CDIM*CDIM];
__device__ __align__(16) __half g_qh[(size_t)TOTQ*CDIM], g_ql[(size_t)TOTQ*CDIM];
__device__ __align__(16) __half g_kh[(size_t)TOTQ*CDIM];
__device__ __align__(16) __half g_kth[(size_t)TOTQ*CDIM];
__device__ __align__(16) __half g_ah[(size_t)BB*NROWS*MROWS];  // 134 MB
__device__ __align__(16) __half g_al[(size_t)BB*NROWS*MROWS];  // 134 MB
__device__ __align__(16) __half g_o2h[(size_t)TOTQ*CDIM], g_o2l[(size_t)TOTQ*CDIM];

// ---------------------------------------------------------------------------
// device helpers
// ---------------------------------------------------------------------------
static __device__ __forceinline__ unsigned smem_u32(const void* p) {
    unsigned a;
    asm("{ .reg .u64 t; cvta.to.shared.u64 t, %1; cvt.u32.u64 %0, t; }" : "=r"(a) : "l"(p));
    return a;
}
static __device__ __forceinline__ void ldm_x4(unsigned& r0, unsigned& r1,
                                              unsigned& r2, unsigned& r3, unsigned a) {
    asm volatile("ldmatrix.sync.aligned.m8n8.x4.shared.b16 {%0,%1,%2,%3}, [%4];"
                 : "=r"(r0), "=r"(r1), "=r"(r2), "=r"(r3) : "r"(a));
}
static __device__ __forceinline__ void mma16816(float* c, const unsigned* a,
                                                const unsigned* b) {
    asm volatile(
        "mma.sync.aligned.m16n8k16.row.col.f32.f16.f16.f32 "
        "{%0,%1,%2,%3}, {%4,%5,%6,%7}, {%8,%9}, {%0,%1,%2,%3};"
        : "+f"(c[0]), "+f"(c[1]), "+f"(c[2]), "+f"(c[3])
        : "r"(a[0]), "r"(a[1]), "r"(a[2]), "r"(a[3]), "r"(b[0]), "r"(b[1]));
}
static __device__ __forceinline__ unsigned hpack(float a, float b) {
    __half2 t = __floats2half2_rn(a, b);
    return *reinterpret_cast<unsigned*>(&t);
}
static __device__ __forceinline__ void mbar_wait(unsigned mbar, unsigned phase) {
    asm volatile(
        "{\n\t.reg .pred P1;\n\t"
        "LAB_WAIT_%=:\n\t"
        "mbarrier.try_wait.parity.acquire.cta.shared::cta.b64 P1, [%0], %1, 0x989680;\n\t"
        "@P1 bra.uni LAB_DONE_%=;\n\t"
        "bra.uni LAB_WAIT_%=;\n\t"
        "LAB_DONE_%=:\n\t}"
        :: "r"(mbar), "r"(phase) : "memory");
}
static __device__ __forceinline__ void tma3(unsigned dst, const CUtensorMap* m,
                                            int x, int y, int z, unsigned mb) {
    asm volatile(
        "cp.async.bulk.tensor.3d.shared::cluster.global.tile.mbarrier::complete_tx::bytes "
        "[%0], [%1, {%2, %3, %4}], [%5];"
        :: "r"(dst), "l"(m), "r"(x), "r"(y), "r"(z), "r"(mb) : "memory");
}

// ---------------------------------------------------------------------------
// Split-fp16 HMMA GEMM, TMA loads. CTA 128x256, warp tile 64x64 (2x4 warps),
// K-slab 64, 2-stage TMA double buffer, SW128 swizzled smem.
// C = A @ B^T; A,B [rows,K] row-major.
// NTERMS=3: acc = ah*bh + ah*bl + al*bh   (full correction)
// NTERMS=2: acc = ah*bh + al*bh           (A-only correction; Bl not loaded)
// MODE 0: Cf = scale*acc (batched)  MODE 1: Cf = acc + bias
// MODE 2: (Ch,Cl) = split(acc)      MODE 4: Ch = half(acc) only
// ---------------------------------------------------------------------------
#define TILEA 16384                 // 128x64 fp16
#define TILEB2 32768                // 256x64 fp16
#define OFF_BH (2*TILEA)

template<int MODE, int NTERMS>
__global__ void __launch_bounds__(256, 1) tma_gemm(
    const __grid_constant__ CUtensorMap mAh, const __grid_constant__ CUtensorMap mAl,
    const __grid_constant__ CUtensorMap mBh, const __grid_constant__ CUtensorMap mBl,
    int ldC, int Kdim, float scale, long long sC,
    const float* __restrict__ bias, float* __restrict__ Cf,
    __half* __restrict__ Ch, __half* __restrict__ Cl)
{
    constexpr unsigned STGX = 2 * TILEA + (NTERMS == 3 ? 2 : 1) * TILEB2;
    extern __shared__ char smem[];
    __shared__ __align__(16) unsigned long long mbar[2];
    const unsigned sa = (smem_u32(smem) + 1023) & ~1023u;
    const unsigned mbq = smem_u32(mbar);
    const int tid = threadIdx.x;
    const int wid = tid >> 5;
    const int lane = tid & 31;
    const int m0 = blockIdx.y * 128;
    const int n0 = blockIdx.x * 256;
    const int bz = blockIdx.z;

    const int m_w = (wid >> 2) * 64;
    const int n_w = (wid & 3) * 64;

    if (tid == 0) {
        asm volatile("mbarrier.init.shared.b64 [%0], 1;" :: "r"(mbq) : "memory");
        asm volatile("mbarrier.init.shared.b64 [%0], 1;" :: "r"(mbq + 8) : "memory");
    }
    __syncthreads();

    const int nslab = Kdim / 64;
    auto issue = [&](int buf, int k0) {
        if (tid == 0) {
            const unsigned mb = mbq + buf * 8;
            asm volatile("mbarrier.arrive.expect_tx.shared.b64 _, [%0], %1;"
                         :: "r"(mb), "r"(STGX) : "memory");
            const unsigned base = sa + buf * STGX;
            tma3(base,          &mAh, k0, m0, bz, mb);
            tma3(base + TILEA,  &mAl, k0, m0, bz, mb);
            tma3(base + OFF_BH, &mBh, k0, n0, bz, mb);
            if (NTERMS == 3)
                tma3(base + OFF_BH + TILEB2, &mBl, k0, n0, bz, mb);
        }
    };

    issue(0, 0);
    if (nslab > 1) issue(1, 64);

    float acc[4][8][4];
#pragma unroll
    for (int i = 0; i < 4; i++)
#pragma unroll
        for (int j = 0; j < 8; j++)
#pragma unroll
            for (int p = 0; p < 4; p++) acc[i][j][p] = 0.f;

    const unsigned aoffL = (unsigned)(m_w + (lane & 15)) * 128 + ((lane >> 4) * 16);
    const unsigned boffL = (unsigned)(n_w + (lane & 7) + ((lane >> 4) << 3)) * 128
                         + ((lane & 8) ? 16 : 0);
    const unsigned sxor = (unsigned)(lane & 7) << 4;

    int phase[2] = {0, 0};
    for (int s = 0; s < nslab; s++) {
        const int buf = s & 1;
        mbar_wait(mbq + buf * 8, (unsigned)phase[buf]);
        phase[buf] ^= 1;
        const unsigned st = sa + buf * STGX;
#pragma unroll
        for (int kk = 0; kk < 4; kk++) {
            unsigned ah[4][4], al[4][4];
#pragma unroll
            for (int mb = 0; mb < 4; mb++) {
                const unsigned a = st + ((aoffL + mb * 2048 + kk * 32) ^ sxor);
                ldm_x4(ah[mb][0], ah[mb][1], ah[mb][2], ah[mb][3], a);
                ldm_x4(al[mb][0], al[mb][1], al[mb][2], al[mb][3], a + TILEA);
            }
#pragma unroll
            for (int nbp = 0; nbp < 4; nbp++) {
                unsigned bh[2][2], bl[2][2];
                const unsigned b = st + OFF_BH + ((boffL + nbp * 2048 + kk * 32) ^ sxor);
                ldm_x4(bh[0][0], bh[0][1], bh[1][0], bh[1][1], b);
                if (NTERMS == 3)
                    ldm_x4(bl[0][0], bl[0][1], bl[1][0], bl[1][1], b + TILEB2);
#pragma unroll
                for (int mb = 0; mb < 4; mb++)
#pragma unroll
                    for (int j = 0; j < 2; j++) {
                        float* c = acc[mb][2 * nbp + j];
                        mma16816(c, ah[mb], bh[j]);
                        mma16816(c, al[mb], bh[j]);
                        if (NTERMS == 3) mma16816(c, ah[mb], bl[j]);
                    }
            }
        }
        __syncthreads();
        if (s + 2 < nslab) issue(buf, (s + 2) * 64);
    }

    // ---- epilogue ----
#pragma unroll
    for (int mb = 0; mb < 4; mb++)
#pragma unroll
        for (int p = 0; p < 2; p++) {
            const long long row = m0 + m_w + mb * 16 + (lane >> 2) + p * 8;
#pragma unroll
            for (int nb = 0; nb < 8; nb++) {
                const int col = n0 + n_w + nb * 8 + (lane & 3) * 2;
                float v0 = acc[mb][nb][2 * p];
                float v1 = acc[mb][nb][2 * p + 1];
                if (MODE == 0) {
                    float2 o = make_float2(v0 * scale, v1 * scale);
                    *(float2*)&Cf[(long long)bz * sC + row * ldC + col] = o;
                } else if (MODE == 1) {
                    float2 o = make_float2(v0 + bias[col], v1 + bias[col + 1]);
                    *(float2*)&Cf[row * ldC + col] = o;
                } else if (MODE == 2) {
                    __half h0 = __float2half(v0);
                    __half h1 = __float2half(v1);
                    *(unsigned*)&Ch[row * (long long)ldC + col] =
                        hpack(__half2float(h0), __half2float(h1));
                    *(unsigned*)&Cl[row * (long long)ldC + col] =
                        hpack(v0 - __half2float(h0), v1 - __half2float(h1));
                } else {   // MODE 4: hi only
                    *(unsigned*)&Ch[row * (long long)ldC + col] = hpack(v0, v1);
                }
            }
        }
}

// ---------------------------------------------------------------------------
// fp32 -> split fp16 (hi/lo)
// ---------------------------------------------------------------------------
__global__ void __launch_bounds__(256) split_f32(
    const float* __restrict__ src, __half* __restrict__ h,
    __half* __restrict__ l, int n4)
{
    int i = blockIdx.x * 256 + threadIdx.x;
    if (i >= n4) return;
    float4 v = ((const float4*)src)[i];
    __half h0 = __float2half(v.x), h1 = __float2half(v.y);
    __half h2 = __float2half(v.z), h3 = __float2half(v.w);
    uint2 ph, pl;
    ph.x = hpack(__half2float(h0), __half2float(h1));
    ph.y = hpack(__half2float(h2), __half2float(h3));
    pl.x = hpack(v.x - __half2float(h0), v.y - __half2float(h1));
    pl.y = hpack(v.z - __half2float(h2), v.w - __half2float(h3));
    ((uint2*)h)[i] = ph;
    ((uint2*)l)[i] = pl;
}

// ---------------------------------------------------------------------------
// kT (hi only): kth[b][d][m] = kh[b*4096+m][d]
// ---------------------------------------------------------------------------
__global__ void __launch_bounds__(256) transpose_hi(
    const __half* __restrict__ kh, __half* __restrict__ kth)
{
    __shared__ __half th[32][33];
    const int b = blockIdx.z;
    const int mm0 = blockIdx.x * 32;
    const int d0 = blockIdx.y * 32;
    const int tx = threadIdx.x, ty = threadIdx.y;
    const long long sbase = (long long)(b * 4096 + mm0) * CDIM + d0;
#pragma unroll
    for (int hh = 0; hh < 32; hh += 8)
        th[ty + hh][tx] = kh[sbase + (long long)(ty + hh) * CDIM + tx];
    __syncthreads();
    const long long dbase = (long long)b * CDIM * MROWS + (long long)d0 * MROWS + mm0;
#pragma unroll
    for (int hh = 0; hh < 32; hh += 8)
        kth[dbase + (long long)(ty + hh) * MROWS + tx] = th[tx][ty + hh];
}

// ---------------------------------------------------------------------------
// Row softmax (4096) + post-softmax mask; split-fp16 probability output.
// ---------------------------------------------------------------------------
__global__ void __launch_bounds__(256) softmax_split(
    const float* __restrict__ attn, const int* __restrict__ mask,
    __half* __restrict__ ah, __half* __restrict__ al)
{
    __shared__ float rmax[8];
    __shared__ float rsum[8];
    const float* p = attn + (long long)blockIdx.x * MROWS;
    const int t = threadIdx.x;

    float4 v[4];
    float mx = -1e30f;
#pragma unroll
    for (int u = 0; u < 4; u++) {
        v[u] = ((const float4*)p)[u * 256 + t];
        mx = fmaxf(mx, fmaxf(fmaxf(v[u].x, v[u].y), fmaxf(v[u].z, v[u].w)));
    }
#pragma unroll
    for (int o = 16; o > 0; o >>= 1) mx = fmaxf(mx, __shfl_xor_sync(0xffffffffu, mx, o));
    if ((t & 31) == 0) rmax[t >> 5] = mx;
    __syncthreads();
    mx = fmaxf(fmaxf(fmaxf(rmax[0], rmax[1]), fmaxf(rmax[2], rmax[3])),
               fmaxf(fmaxf(rmax[4], rmax[5]), fmaxf(rmax[6], rmax[7])));

    float s = 0.f;
#pragma unroll
    for (int u = 0; u < 4; u++) {
        v[u].x = expf(v[u].x - mx); v[u].y = expf(v[u].y - mx);
        v[u].z = expf(v[u].z - mx); v[u].w = expf(v[u].w - mx);
        s += v[u].x + v[u].y + v[u].z + v[u].w;
    }
#pragma unroll
    for (int o = 16; o > 0; o >>= 1) s += __shfl_xor_sync(0xffffffffu, s, o);
    if ((t & 31) == 0) rsum[t >> 5] = s;
    __syncthreads();
    s = (rsum[0] + rsum[1]) + (rsum[2] + rsum[3]) + (rsum[4] + rsum[5]) + (rsum[6] + rsum[7]);
    const float inv = 1.0f / s;

    __half* bh = ah + (long long)blockIdx.x * MROWS;
    __half* bl = al + (long long)blockIdx.x * MROWS;
#pragma unroll
    for (int u = 0; u < 4; u++) {
        const int i4 = u * 256 + t;
        const int4 mq = ((const int4*)mask)[i4];
        float o0 = v[u].x * inv * (mq.x != 0 ? 1.f : 0.f);
        float o1 = v[u].y * inv * (mq.y != 0 ? 1.f : 0.f);
        float o2 = v[u].z * inv * (mq.z != 0 ? 1.f : 0.f);
        float o3 = v[u].w * inv * (mq.w != 0 ? 1.f : 0.f);
        __half h0 = __float2half(o0), h1 = __float2half(o1);
        __half h2 = __float2half(o2), h3 = __float2half(o3);
        uint2 ph, pl;
        ph.x = hpack(__half2float(h0), __half2float(h1));
        ph.y = hpack(__half2float(h2), __half2float(h3));
        pl.x = hpack(o0 - __half2float(h0), o1 - __half2float(h1));
        pl.y = hpack(o2 - __half2float(h2), o3 - __half2float(h3));
        ((uint2*)bh)[i4] = ph;
        ((uint2*)bl)[i4] = pl;
    }
}

// ---------------------------------------------------------------------------
// Bug-faithful permute: o2[b, 8a+r, j] = o1[b, r*512 + j, a], split-fp16 out
// ---------------------------------------------------------------------------
__global__ void __launch_bounds__(256) permute_split(
    const float* __restrict__ o1, __half* __restrict__ oh,
    __half* __restrict__ ol)
{
    __shared__ float tile[32][33];
    const int br = blockIdx.z;
    const int b = br >> 3;
    const int r = br & 7;
    const float* src = o1 + (long long)b * NROWS * CDIM + (long long)r * 512 * CDIM;
    const long long dbase = (long long)b * NROWS * CDIM + r * CDIM;
    const int j0 = blockIdx.y * 32;
    const int a0 = blockIdx.x * 32;
    const int tx = threadIdx.x, ty = threadIdx.y;

#pragma unroll
    for (int hh = 0; hh < 32; hh += 8)
        tile[ty + hh][tx] = src[(long long)(j0 + ty + hh) * 512 + a0 + tx];
    __syncthreads();
#pragma unroll
    for (int hh = 0; hh < 32; hh += 8) {
        float v = tile[tx][ty + hh];
        long long off = dbase + (long long)(a0 + ty + hh) * 4096 + j0 + tx;
        __half hi = __float2half(v);
        oh[off] = hi;
        ol[off] = __float2half(v - __half2float(hi));
    }
}

// ---------------------------------------------------------------------------
// Host: tensormap encode via driver entry point
// ---------------------------------------------------------------------------
typedef CUresult (*PFN_tmapEnc)(
    CUtensorMap*, CUtensorMapDataType, cuuint32_t, void*,
    const cuuint64_t*, const cuuint64_t*, const cuuint32_t*, const cuuint32_t*,
    CUtensorMapInterleave, CUtensorMapSwizzle, CUtensorMapL2promotion,
    CUtensorMapFloatOOBfill);

static void enc_map(PFN_tmapEnc fn, CUtensorMap* m, const void* ptr,
                    unsigned long long K, unsigned long long rows,
                    unsigned long long batches, unsigned long long ldElems,
                    unsigned long long bStrideElems, unsigned boxRows)
{
    cuuint64_t dims[3] = {K, rows, batches};
    cuuint64_t strides[2] = {ldElems * 2ull, bStrideElems * 2ull};
    cuuint32_t box[3] = {64, boxRows, 1};
    cuuint32_t estr[3] = {1, 1, 1};
    fn(m, CU_TENSOR_MAP_DATA_TYPE_FLOAT16, 3, (void*)ptr,
       dims, strides, box, estr,
       CU_TENSOR_MAP_INTERLEAVE_NONE, CU_TENSOR_MAP_SWIZZLE_128B,
       CU_TENSOR_MAP_L2_PROMOTION_L2_128B, CU_TENSOR_MAP_FLOAT_OOB_FILL_NONE);
}

extern "C" void kernel_launch(void* const* d_in, const int* in_sizes, int n_in,
                              void* d_out, int out_size)
{
    const float* x       = (const float*)d_in[0];
    const float* support = (const float*)d_in[1];
    const int*   mask    = (const int*)  d_in[2];
    const float* Wv      = (const float*)d_in[3];
    const float* Wp      = (const float*)d_in[4];
    const float* bp      = (const float*)d_in[5];
    float* out = (float*)d_out;

    float *attn, *o1;
    __half *xh, *xl, *sh, *sl, *wvh, *wvl, *wph, *wpl;
    __half *qh, *ql, *kh, *kth, *ah, *al, *o2h, *o2l;
    cudaGetSymbolAddress((void**)&attn, g_attn);
    cudaGetSymbolAddress((void**)&o1,   g_o1);
    cudaGetSymbolAddress((void**)&xh, g_xh);   cudaGetSymbolAddress((void**)&xl, g_xl);
    cudaGetSymbolAddress((void**)&sh, g_sh);   cudaGetSymbolAddress((void**)&sl, g_sl);
    cudaGetSymbolAddress((void**)&wvh, g_wvh); cudaGetSymbolAddress((void**)&wvl, g_wvl);
    cudaGetSymbolAddress((void**)&wph, g_wph); cudaGetSymbolAddress((void**)&wpl, g_wpl);
    cudaGetSymbolAddress((void**)&qh, g_qh);   cudaGetSymbolAddress((void**)&ql, g_ql);
    cudaGetSymbolAddress((void**)&kh, g_kh);
    cudaGetSymbolAddress((void**)&kth, g_kth);
    cudaGetSymbolAddress((void**)&ah, g_ah);   cudaGetSymbolAddress((void**)&al, g_al);
    cudaGetSymbolAddress((void**)&o2h, g_o2h); cudaGetSymbolAddress((void**)&o2l, g_o2l);

    void* sym = nullptr;
    cudaDriverEntryPointQueryResult qres;
    cudaGetDriverEntryPointByVersion("cuTensorMapEncodeTiled", &sym, 12000,
                                     cudaEnableDefault, &qres);
    PFN_tmapEnc enc = (PFN_tmapEnc)sym;

    const long long sQK = (long long)NROWS * CDIM;
    const long long sAT = (long long)NROWS * MROWS;

    CUtensorMap tQh, tQl, tKh;
    enc_map(enc, &tQh, qh, CDIM, NROWS, BB, CDIM, sQK, 128);
    enc_map(enc, &tQl, ql, CDIM, NROWS, BB, CDIM, sQK, 128);
    enc_map(enc, &tKh, kh, CDIM, NROWS, BB, CDIM, sQK, 256);
    CUtensorMap tXh, tXl, tSh, tSl, tWvh, tWvl, tWph, tWpl;
    enc_map(enc, &tXh, xh, CDIM, TOTQ, 1, CDIM, (long long)TOTQ * CDIM, 128);
    enc_map(enc, &tXl, xl, CDIM, TOTQ, 1, CDIM, (long long)TOTQ * CDIM, 128);
    enc_map(enc, &tSh, sh, CDIM, TOTQ, 1, CDIM, (long long)TOTQ * CDIM, 128);
    enc_map(enc, &tSl, sl, CDIM, TOTQ, 1, CDIM, (long long)TOTQ * CDIM, 128);
    enc_map(enc, &tWvh, wvh, CDIM, CDIM, 1, CDIM, (long long)CDIM * CDIM, 256);
    enc_map(enc, &tWvl, wvl, CDIM, CDIM, 1, CDIM, (long long)CDIM * CDIM, 256);
    enc_map(enc, &tWph, wph, CDIM, CDIM, 1, CDIM, (long long)CDIM * CDIM, 256);
    enc_map(enc, &tWpl, wpl, CDIM, CDIM, 1, CDIM, (long long)CDIM * CDIM, 256);
    CUtensorMap tAh, tAl, tKTh;
    enc_map(enc, &tAh, ah, MROWS, NROWS, BB, MROWS, sAT, 128);
    enc_map(enc, &tAl, al, MROWS, NROWS, BB, MROWS, sAT, 128);
    enc_map(enc, &tKTh, kth, MROWS, CDIM, BB, MROWS, (long long)CDIM * MROWS, 256);
    CUtensorMap tO2h, tO2l;
    enc_map(enc, &tO2h, o2h, CDIM, TOTQ, 1, CDIM, (long long)TOTQ * CDIM, 128);
    enc_map(enc, &tO2l, o2l, CDIM, TOTQ, 1, CDIM, (long long)TOTQ * CDIM, 128);

    const int SMEM3 = 1024 + 2 * (2 * TILEA + 2 * TILEB2);   // 197632
    const int SMEM2 = 1024 + 2 * (2 * TILEA + TILEB2);       // 132096
    cudaFuncSetAttribute(tma_gemm<2,3>, cudaFuncAttributeMaxDynamicSharedMemorySize, SMEM3);
    cudaFuncSetAttribute(tma_gemm<4,3>, cudaFuncAttributeMaxDynamicSharedMemorySize, SMEM3);
    cudaFuncSetAttribute(tma_gemm<1,3>, cudaFuncAttributeMaxDynamicSharedMemorySize, SMEM3);
    cudaFuncSetAttribute(tma_gemm<0,2>, cudaFuncAttributeMaxDynamicSharedMemorySize, SMEM2);

    // 1) conversions
    split_f32<<<TOTQ * CDIM / 4 / 256, 256>>>(x,       xh, xl, TOTQ * CDIM / 4);
    split_f32<<<TOTQ * CDIM / 4 / 256, 256>>>(support, sh, sl, TOTQ * CDIM / 4);
    split_f32<<<CDIM * CDIM / 4 / 256, 256>>>(Wv,      wvh, wvl, CDIM * CDIM / 4);
    split_f32<<<CDIM * CDIM / 4 / 256, 256>>>(Wp,      wph, wpl, CDIM * CDIM / 4);

    // 2) q = x @ Wv^T (hi+lo out) ; k = support @ Wv^T (hi only)
    tma_gemm<2,3><<<dim3(2, 128, 1), 256, SMEM3>>>(
        tXh, tXl, tWvh, tWvl, CDIM, CDIM, 1.0f, 0, nullptr, nullptr, qh, ql);
    tma_gemm<4,3><<<dim3(2, 128, 1), 256, SMEM3>>>(
        tSh, tSl, tWvh, tWvl, CDIM, CDIM, 1.0f, 0, nullptr, nullptr, kh, nullptr);

    // 3) kT[b][d][m] (hi only)
    transpose_hi<<<dim3(128, 16, BB), dim3(32, 8)>>>(kh, kth);

    // 4) attn = 0.125 * q @ k^T (2-term, fp32 out, batched)
    tma_gemm<0,2><<<dim3(16, 32, BB), 256, SMEM2>>>(
        tQh, tQl, tKh, tKh, MROWS, CDIM, 0.125f, sAT, nullptr, attn,
        nullptr, nullptr);

    // 5) softmax + mask -> split-fp16 probs
    softmax_split<<<TOTQ, 256>>>(attn, mask, ah, al);

    // 6) o1 = attn @ v  (2-term, B = kT hi)
    tma_gemm<0,2><<<dim3(2, 32, BB), 256, SMEM2>>>(
        tAh, tAl, tKTh, tKTh, CDIM, MROWS, 1.0f, sQK, nullptr, o1,
        nullptr, nullptr);

    // 7) bug-faithful permute -> split-fp16
    permute_split<<<dim3(16, 16, BB * 8), dim3(32, 8)>>>(o1, o2h, o2l);

    // 8) out = o2 @ Wp^T + bp  (3-term)
    tma_gemm<1,3><<<dim3(2, 128, 1), 256, SMEM3>>>(
        tO2h, tO2l, tWph, tWpl, CDIM, CDIM, 1.0f, 0, bp, out, nullptr, nullptr);
}

// round 8
// speedup vs baseline: 3.8159x; 1.0251x over previous
#include <cuda_runtime.h>
#include <cuda_fp16.h>
#include <cuda.h>

#define BB 4
#define NROWS 4096
#define MROWS 4096
#define CDIM 512
#define TOTQ (BB*NROWS)

// ---------------------------------------------------------------------------
// Device scratch (fp16 split: hi/lo)
// ---------------------------------------------------------------------------
__device__ __align__(16) float g_attn[(size_t)BB * NROWS * MROWS];   // 268 MB
__device__ __align__(16) float g_o1[(size_t)TOTQ * CDIM];
__device__ __align__(16) __half g_xh[(size_t)TOTQ*CDIM], g_xl[(size_t)TOTQ*CDIM];
__device__ __align__(16) __half g_sh[(size_t)TOTQ*CDIM], g_sl[(size_t)TOTQ*CDIM];
__device__ __align__(16) __half g_wvh[CDIM*CDIM], g_wvl[CDIM*CDIM];
__device__ __align__(16) __half g_wph[CDIM*CDIM], g_wpl[CDIM*CDIM];
__device__ __align__(16) __half g_qh[(size_t)TOTQ*CDIM], g_ql[(size_t)TOTQ*CDIM];
__device__ __align__(16) __half g_kh[(size_t)TOTQ*CDIM];
__device__ __align__(16) __half g_kth[(size_t)TOTQ*CDIM];
__device__ __align__(16) __half g_ah[(size_t)BB*NROWS*MROWS];  // 134 MB
__device__ __align__(16) __half g_al[(size_t)BB*NROWS*MROWS];  // 134 MB
__device__ __align__(16) __half g_o2h[(size_t)TOTQ*CDIM], g_o2l[(size_t)TOTQ*CDIM];

// ---------------------------------------------------------------------------
// device helpers
// ---------------------------------------------------------------------------
static __device__ __forceinline__ unsigned smem_u32(const void* p) {
    unsigned a;
    asm("{ .reg .u64 t; cvta.to.shared.u64 t, %1; cvt.u32.u64 %0, t; }" : "=r"(a) : "l"(p));
    return a;
}
static __device__ __forceinline__ void ldm_x4(unsigned& r0, unsigned& r1,
                                              unsigned& r2, unsigned& r3, unsigned a) {
    asm volatile("ldmatrix.sync.aligned.m8n8.x4.shared.b16 {%0,%1,%2,%3}, [%4];"
                 : "=r"(r0), "=r"(r1), "=r"(r2), "=r"(r3) : "r"(a));
}
static __device__ __forceinline__ void mma16816(float* c, const unsigned* a,
                                                const unsigned* b) {
    asm volatile(
        "mma.sync.aligned.m16n8k16.row.col.f32.f16.f16.f32 "
        "{%0,%1,%2,%3}, {%4,%5,%6,%7}, {%8,%9}, {%0,%1,%2,%3};"
        : "+f"(c[0]), "+f"(c[1]), "+f"(c[2]), "+f"(c[3])
        : "r"(a[0]), "r"(a[1]), "r"(a[2]), "r"(a[3]), "r"(b[0]), "r"(b[1]));
}
static __device__ __forceinline__ unsigned hpack(float a, float b) {
    __half2 t = __floats2half2_rn(a, b);
    return *reinterpret_cast<unsigned*>(&t);
}
static __device__ __forceinline__ void mbar_wait(unsigned mbar, unsigned phase) {
    asm volatile(
        "{\n\t.reg .pred P1;\n\t"
        "LAB_WAIT_%=:\n\t"
        "mbarrier.try_wait.parity.acquire.cta.shared::cta.b64 P1, [%0], %1, 0x989680;\n\t"
        "@P1 bra.uni LAB_DONE_%=;\n\t"
        "bra.uni LAB_WAIT_%=;\n\t"
        "LAB_DONE_%=:\n\t}"
        :: "r"(mbar), "r"(phase) : "memory");
}
static __device__ __forceinline__ void tma3(unsigned dst, const CUtensorMap* m,
                                            int x, int y, int z, unsigned mb) {
    asm volatile(
        "cp.async.bulk.tensor.3d.shared::cluster.global.tile.mbarrier::complete_tx::bytes "
        "[%0], [%1, {%2, %3, %4}], [%5];"
        :: "r"(dst), "l"(m), "r"(x), "r"(y), "r"(z), "r"(mb) : "memory");
}

// ---------------------------------------------------------------------------
// Split-fp16 HMMA GEMM, TMA loads. CTA 128 x TN (TN=256: warp 64x64 occ1;
// TN=128: warp 64x32 occ2). K-slab 64, 2-stage TMA double buffer, SW128 smem.
// C = A @ B^T; A,B [rows,K] row-major.
// NTERMS=3: acc = ah*bh + al*bh + ah*bl ;  NTERMS=2: acc = ah*bh + al*bh
// MODE 0: Cf = scale*acc (batched)  MODE 1: Cf = acc + bias
// MODE 2: (Ch,Cl) = split(acc)      MODE 4: Ch = half(acc) only
// ---------------------------------------------------------------------------
#define TILEA 16384                 // 128x64 fp16

template<int MODE, int NTERMS, int TN, int MINB>
__global__ void __launch_bounds__(256, MINB) tma_gemm(
    const __grid_constant__ CUtensorMap mAh, const __grid_constant__ CUtensorMap mAl,
    const __grid_constant__ CUtensorMap mBh, const __grid_constant__ CUtensorMap mBl,
    int ldC, int Kdim, float scale, long long sC,
    const float* __restrict__ bias, float* __restrict__ Cf,
    __half* __restrict__ Ch, __half* __restrict__ Cl)
{
    constexpr unsigned TILEBN = TN * 64 * 2;
    constexpr unsigned OFF_BH = 2 * TILEA;
    constexpr unsigned STGX = 2 * TILEA + (NTERMS == 3 ? 2u : 1u) * TILEBN;
    constexpr int NBP = TN / 64;        // 16-col groups per warp
    constexpr int NBW = TN / 32;        // 8-col acc tiles per warp

    extern __shared__ char smem[];
    __shared__ __align__(16) unsigned long long mbar[2];
    const unsigned sa = (smem_u32(smem) + 1023) & ~1023u;
    const unsigned mbq = smem_u32(mbar);
    const int tid = threadIdx.x;
    const int wid = tid >> 5;
    const int lane = tid & 31;
    const int m0 = blockIdx.y * 128;
    const int n0 = blockIdx.x * TN;
    const int bz = blockIdx.z;

    const int m_w = (wid >> 2) * 64;
    const int n_w = (wid & 3) * (TN / 4);

    if (tid == 0) {
        asm volatile("mbarrier.init.shared.b64 [%0], 1;" :: "r"(mbq) : "memory");
        asm volatile("mbarrier.init.shared.b64 [%0], 1;" :: "r"(mbq + 8) : "memory");
    }
    __syncthreads();

    const int nslab = Kdim / 64;
    auto issue = [&](int buf, int k0) {
        if (tid == 0) {
            const unsigned mb = mbq + buf * 8;
            asm volatile("mbarrier.arrive.expect_tx.shared.b64 _, [%0], %1;"
                         :: "r"(mb), "r"(STGX) : "memory");
            const unsigned base = sa + buf * STGX;
            tma3(base,          &mAh, k0, m0, bz, mb);
            tma3(base + TILEA,  &mAl, k0, m0, bz, mb);
            tma3(base + OFF_BH, &mBh, k0, n0, bz, mb);
            if (NTERMS == 3)
                tma3(base + OFF_BH + TILEBN, &mBl, k0, n0, bz, mb);
        }
    };

    issue(0, 0);
    if (nslab > 1) issue(1, 64);

    float acc[4][NBW][4];
#pragma unroll
    for (int i = 0; i < 4; i++)
#pragma unroll
        for (int j = 0; j < NBW; j++)
#pragma unroll
            for (int p = 0; p < 4; p++) acc[i][j][p] = 0.f;

    const unsigned aoffL = (unsigned)(m_w + (lane & 15)) * 128 + ((lane >> 4) * 16);
    const unsigned boffL = (unsigned)(n_w + (lane & 7) + ((lane >> 4) << 3)) * 128
                         + ((lane & 8) ? 16 : 0);
    const unsigned sxor = (unsigned)(lane & 7) << 4;

    int phase[2] = {0, 0};
    for (int s = 0; s < nslab; s++) {
        const int buf = s & 1;
        mbar_wait(mbq + buf * 8, (unsigned)phase[buf]);
        phase[buf] ^= 1;
        const unsigned st = sa + buf * STGX;
#pragma unroll
        for (int kk = 0; kk < 4; kk++) {
            unsigned ah[4][4], al[4][4];
#pragma unroll
            for (int mb = 0; mb < 4; mb++) {
                const unsigned a = st + ((aoffL + mb * 2048 + kk * 32) ^ sxor);
                ldm_x4(ah[mb][0], ah[mb][1], ah[mb][2], ah[mb][3], a);
                ldm_x4(al[mb][0], al[mb][1], al[mb][2], al[mb][3], a + TILEA);
            }
#pragma unroll
            for (int nbp = 0; nbp < NBP; nbp++) {
                unsigned bh[2][2], bl[2][2];
                const unsigned b = st + OFF_BH + ((boffL + nbp * 2048 + kk * 32) ^ sxor);
                ldm_x4(bh[0][0], bh[0][1], bh[1][0], bh[1][1], b);
                if (NTERMS == 3)
                    ldm_x4(bl[0][0], bl[0][1], bl[1][0], bl[1][1], b + TILEBN);
#pragma unroll
                for (int mb = 0; mb < 4; mb++)
#pragma unroll
                    for (int j = 0; j < 2; j++) {
                        float* c = acc[mb][2 * nbp + j];
                        mma16816(c, ah[mb], bh[j]);
                        mma16816(c, al[mb], bh[j]);
                        if (NTERMS == 3) mma16816(c, ah[mb], bl[j]);
                    }
            }
        }
        __syncthreads();
        if (s + 2 < nslab) issue(buf, (s + 2) * 64);
    }

    // ---- epilogue ----
#pragma unroll
    for (int mb = 0; mb < 4; mb++)
#pragma unroll
        for (int p = 0; p < 2; p++) {
            const long long row = m0 + m_w + mb * 16 + (lane >> 2) + p * 8;
#pragma unroll
            for (int nb = 0; nb < NBW; nb++) {
                const int col = n0 + n_w + nb * 8 + (lane & 3) * 2;
                float v0 = acc[mb][nb][2 * p];
                float v1 = acc[mb][nb][2 * p + 1];
                if (MODE == 0) {
                    float2 o = make_float2(v0 * scale, v1 * scale);
                    *(float2*)&Cf[(long long)bz * sC + row * ldC + col] = o;
                } else if (MODE == 1) {
                    float2 o = make_float2(v0 + bias[col], v1 + bias[col + 1]);
                    *(float2*)&Cf[row * ldC + col] = o;
                } else if (MODE == 2) {
                    __half h0 = __float2half(v0);
                    __half h1 = __float2half(v1);
                    *(unsigned*)&Ch[row * (long long)ldC + col] =
                        hpack(__half2float(h0), __half2float(h1));
                    *(unsigned*)&Cl[row * (long long)ldC + col] =
                        hpack(v0 - __half2float(h0), v1 - __half2float(h1));
                } else {   // MODE 4: hi only
                    *(unsigned*)&Ch[row * (long long)ldC + col] = hpack(v0, v1);
                }
            }
        }
}

// ---------------------------------------------------------------------------
// fp32 -> split fp16 (hi/lo)
// ---------------------------------------------------------------------------
__global__ void __launch_bounds__(256) split_f32(
    const float* __restrict__ src, __half* __restrict__ h,
    __half* __restrict__ l, int n4)
{
    int i = blockIdx.x * 256 + threadIdx.x;
    if (i >= n4) return;
    float4 v = ((const float4*)src)[i];
    __half h0 = __float2half(v.x), h1 = __float2half(v.y);
    __half h2 = __float2half(v.z), h3 = __float2half(v.w);
    uint2 ph, pl;
    ph.x = hpack(__half2float(h0), __half2float(h1));
    ph.y = hpack(__half2float(h2), __half2float(h3));
    pl.x = hpack(v.x - __half2float(h0), v.y - __half2float(h1));
    pl.y = hpack(v.z - __half2float(h2), v.w - __half2float(h3));
    ((uint2*)h)[i] = ph;
    ((uint2*)l)[i] = pl;
}

// ---------------------------------------------------------------------------
// kT (hi only): kth[b][d][m] = kh[b*4096+m][d]
// ---------------------------------------------------------------------------
__global__ void __launch_bounds__(256) transpose_hi(
    const __half* __restrict__ kh, __half* __restrict__ kth)
{
    __shared__ __half th[32][33];
    const int b = blockIdx.z;
    const int mm0 = blockIdx.x * 32;
    const int d0 = blockIdx.y * 32;
    const int tx = threadIdx.x, ty = threadIdx.y;
    const long long sbase = (long long)(b * 4096 + mm0) * CDIM + d0;
#pragma unroll
    for (int hh = 0; hh < 32; hh += 8)
        th[ty + hh][tx] = kh[sbase + (long long)(ty + hh) * CDIM + tx];
    __syncthreads();
    const long long dbase = (long long)b * CDIM * MROWS + (long long)d0 * MROWS + mm0;
#pragma unroll
    for (int hh = 0; hh < 32; hh += 8)
        kth[dbase + (long long)(ty + hh) * MROWS + tx] = th[tx][ty + hh];
}

// ---------------------------------------------------------------------------
// Row softmax (4096) + post-softmax mask; split-fp16 probability output.
// ---------------------------------------------------------------------------
__global__ void __launch_bounds__(256) softmax_split(
    const float* __restrict__ attn, const int* __restrict__ mask,
    __half* __restrict__ ah, __half* __restrict__ al)
{
    __shared__ float rmax[8];
    __shared__ float rsum[8];
    const float* p = attn + (long long)blockIdx.x * MROWS;
    const int t = threadIdx.x;

    float4 v[4];
    float mx = -1e30f;
#pragma unroll
    for (int u = 0; u < 4; u++) {
        v[u] = ((const float4*)p)[u * 256 + t];
        mx = fmaxf(mx, fmaxf(fmaxf(v[u].x, v[u].y), fmaxf(v[u].z, v[u].w)));
    }
#pragma unroll
    for (int o = 16; o > 0; o >>= 1) mx = fmaxf(mx, __shfl_xor_sync(0xffffffffu, mx, o));
    if ((t & 31) == 0) rmax[t >> 5] = mx;
    __syncthreads();
    mx = fmaxf(fmaxf(fmaxf(rmax[0], rmax[1]), fmaxf(rmax[2], rmax[3])),
               fmaxf(fmaxf(rmax[4], rmax[5]), fmaxf(rmax[6], rmax[7])));

    float s = 0.f;
#pragma unroll
    for (int u = 0; u < 4; u++) {
        v[u].x = expf(v[u].x - mx); v[u].y = expf(v[u].y - mx);
        v[u].z = expf(v[u].z - mx); v[u].w = expf(v[u].w - mx);
        s += v[u].x + v[u].y + v[u].z + v[u].w;
    }
#pragma unroll
    for (int o = 16; o > 0; o >>= 1) s += __shfl_xor_sync(0xffffffffu, s, o);
    if ((t & 31) == 0) rsum[t >> 5] = s;
    __syncthreads();
    s = (rsum[0] + rsum[1]) + (rsum[2] + rsum[3]) + (rsum[4] + rsum[5]) + (rsum[6] + rsum[7]);
    const float inv = 1.0f / s;

    __half* bh = ah + (long long)blockIdx.x * MROWS;
    __half* bl = al + (long long)blockIdx.x * MROWS;
#pragma unroll
    for (int u = 0; u < 4; u++) {
        const int i4 = u * 256 + t;
        const int4 mq = ((const int4*)mask)[i4];
        float o0 = v[u].x * inv * (mq.x != 0 ? 1.f : 0.f);
        float o1 = v[u].y * inv * (mq.y != 0 ? 1.f : 0.f);
        float o2 = v[u].z * inv * (mq.z != 0 ? 1.f : 0.f);
        float o3 = v[u].w * inv * (mq.w != 0 ? 1.f : 0.f);
        __half h0 = __float2half(o0), h1 = __float2half(o1);
        __half h2 = __float2half(o2), h3 = __float2half(o3);
        uint2 ph, pl;
        ph.x = hpack(__half2float(h0), __half2float(h1));
        ph.y = hpack(__half2float(h2), __half2float(h3));
        pl.x = hpack(o0 - __half2float(h0), o1 - __half2float(h1));
        pl.y = hpack(o2 - __half2float(h2), o3 - __half2float(h3));
        ((uint2*)bh)[i4] = ph;
        ((uint2*)bl)[i4] = pl;
    }
}

// ---------------------------------------------------------------------------
// Bug-faithful permute: o2[b, 8a+r, j] = o1[b, r*512 + j, a], split-fp16 out
// ---------------------------------------------------------------------------
__global__ void __launch_bounds__(256) permute_split(
    const float* __restrict__ o1, __half* __restrict__ oh,
    __half* __restrict__ ol)
{
    __shared__ float tile[32][33];
    const int br = blockIdx.z;
    const int b = br >> 3;
    const int r = br & 7;
    const float* src = o1 + (long long)b * NROWS * CDIM + (long long)r * 512 * CDIM;
    const long long dbase = (long long)b * NROWS * CDIM + r * CDIM;
    const int j0 = blockIdx.y * 32;
    const int a0 = blockIdx.x * 32;
    const int tx = threadIdx.x, ty = threadIdx.y;

#pragma unroll
    for (int hh = 0; hh < 32; hh += 8)
        tile[ty + hh][tx] = src[(long long)(j0 + ty + hh) * 512 + a0 + tx];
    __syncthreads();
#pragma unroll
    for (int hh = 0; hh < 32; hh += 8) {
        float v = tile[tx][ty + hh];
        long long off = dbase + (long long)(a0 + ty + hh) * 4096 + j0 + tx;
        __half hi = __float2half(v);
        oh[off] = hi;
        ol[off] = __float2half(v - __half2float(hi));
    }
}

// ---------------------------------------------------------------------------
// Host: tensormap encode via driver entry point
// ---------------------------------------------------------------------------
typedef CUresult (*PFN_tmapEnc)(
    CUtensorMap*, CUtensorMapDataType, cuuint32_t, void*,
    const cuuint64_t*, const cuuint64_t*, const cuuint32_t*, const cuuint32_t*,
    CUtensorMapInterleave, CUtensorMapSwizzle, CUtensorMapL2promotion,
    CUtensorMapFloatOOBfill);

static void enc_map(PFN_tmapEnc fn, CUtensorMap* m, const void* ptr,
                    unsigned long long K, unsigned long long rows,
                    unsigned long long batches, unsigned long long ldElems,
                    unsigned long long bStrideElems, unsigned boxRows)
{
    cuuint64_t dims[3] = {K, rows, batches};
    cuuint64_t strides[2] = {ldElems * 2ull, bStrideElems * 2ull};
    cuuint32_t box[3] = {64, boxRows, 1};
    cuuint32_t estr[3] = {1, 1, 1};
    fn(m, CU_TENSOR_MAP_DATA_TYPE_FLOAT16, 3, (void*)ptr,
       dims, strides, box, estr,
       CU_TENSOR_MAP_INTERLEAVE_NONE, CU_TENSOR_MAP_SWIZZLE_128B,
       CU_TENSOR_MAP_L2_PROMOTION_L2_128B, CU_TENSOR_MAP_FLOAT_OOB_FILL_NONE);
}

extern "C" void kernel_launch(void* const* d_in, const int* in_sizes, int n_in,
                              void* d_out, int out_size)
{
    const float* x       = (const float*)d_in[0];
    const float* support = (const float*)d_in[1];
    const int*   mask    = (const int*)  d_in[2];
    const float* Wv      = (const float*)d_in[3];
    const float* Wp      = (const float*)d_in[4];
    const float* bp      = (const float*)d_in[5];
    float* out = (float*)d_out;

    float *attn, *o1;
    __half *xh, *xl, *sh, *sl, *wvh, *wvl, *wph, *wpl;
    __half *qh, *ql, *kh, *kth, *ah, *al, *o2h, *o2l;
    cudaGetSymbolAddress((void**)&attn, g_attn);
    cudaGetSymbolAddress((void**)&o1,   g_o1);
    cudaGetSymbolAddress((void**)&xh, g_xh);   cudaGetSymbolAddress((void**)&xl, g_xl);
    cudaGetSymbolAddress((void**)&sh, g_sh);   cudaGetSymbolAddress((void**)&sl, g_sl);
    cudaGetSymbolAddress((void**)&wvh, g_wvh); cudaGetSymbolAddress((void**)&wvl, g_wvl);
    cudaGetSymbolAddress((void**)&wph, g_wph); cudaGetSymbolAddress((void**)&wpl, g_wpl);
    cudaGetSymbolAddress((void**)&qh, g_qh);   cudaGetSymbolAddress((void**)&ql, g_ql);
    cudaGetSymbolAddress((void**)&kh, g_kh);
    cudaGetSymbolAddress((void**)&kth, g_kth);
    cudaGetSymbolAddress((void**)&ah, g_ah);   cudaGetSymbolAddress((void**)&al, g_al);
    cudaGetSymbolAddress((void**)&o2h, g_o2h); cudaGetSymbolAddress((void**)&o2l, g_o2l);

    void* sym = nullptr;
    cudaDriverEntryPointQueryResult qres;
    cudaGetDriverEntryPointByVersion("cuTensorMapEncodeTiled", &sym, 12000,
                                     cudaEnableDefault, &qres);
    PFN_tmapEnc enc = (PFN_tmapEnc)sym;

    const long long sQK = (long long)NROWS * CDIM;
    const long long sAT = (long long)NROWS * MROWS;

    // tensormaps: B-operand box rows = 128 for big GEMMs (TN=128), 256 for proj
    CUtensorMap tQh, tQl, tKh;
    enc_map(enc, &tQh, qh, CDIM, NROWS, BB, CDIM, sQK, 128);
    enc_map(enc, &tQl, ql, CDIM, NROWS, BB, CDIM, sQK, 128);
    enc_map(enc, &tKh, kh, CDIM, NROWS, BB, CDIM, sQK, 128);
    CUtensorMap tXh, tXl, tSh, tSl, tWvh, tWvl, tWph, tWpl;
    enc_map(enc, &tXh, xh, CDIM, TOTQ, 1, CDIM, (long long)TOTQ * CDIM, 128);
    enc_map(enc, &tXl, xl, CDIM, TOTQ, 1, CDIM, (long long)TOTQ * CDIM, 128);
    enc_map(enc, &tSh, sh, CDIM, TOTQ, 1, CDIM, (long long)TOTQ * CDIM, 128);
    enc_map(enc, &tSl, sl, CDIM, TOTQ, 1, CDIM, (long long)TOTQ * CDIM, 128);
    enc_map(enc, &tWvh, wvh, CDIM, CDIM, 1, CDIM, (long long)CDIM * CDIM, 256);
    enc_map(enc, &tWvl, wvl, CDIM, CDIM, 1, CDIM, (long long)CDIM * CDIM, 256);
    enc_map(enc, &tWph, wph, CDIM, CDIM, 1, CDIM, (long long)CDIM * CDIM, 256);
    enc_map(enc, &tWpl, wpl, CDIM, CDIM, 1, CDIM, (long long)CDIM * CDIM, 256);
    CUtensorMap tAh, tAl, tKTh;
    enc_map(enc, &tAh, ah, MROWS, NROWS, BB, MROWS, sAT, 128);
    enc_map(enc, &tAl, al, MROWS, NROWS, BB, MROWS, sAT, 128);
    enc_map(enc, &tKTh, kth, MROWS, CDIM, BB, MROWS, (long long)CDIM * MROWS, 128);
    CUtensorMap tO2h, tO2l;
    enc_map(enc, &tO2h, o2h, CDIM, TOTQ, 1, CDIM, (long long)TOTQ * CDIM, 128);
    enc_map(enc, &tO2l, o2l, CDIM, TOTQ, 1, CDIM, (long long)TOTQ * CDIM, 128);

    // smem sizes
    const int SMEM_P = 1024 + 2 * (2 * TILEA + 2 * (256 * 64 * 2));  // proj: 197632
    const int SMEM_B = 1024 + 2 * (2 * TILEA + (128 * 64 * 2));      // big:   99328
    cudaFuncSetAttribute((const void*)tma_gemm<2,3,256,1>, cudaFuncAttributeMaxDynamicSharedMemorySize, SMEM_P);
    cudaFuncSetAttribute((const void*)tma_gemm<4,3,256,1>, cudaFuncAttributeMaxDynamicSharedMemorySize, SMEM_P);
    cudaFuncSetAttribute((const void*)tma_gemm<1,3,256,1>, cudaFuncAttributeMaxDynamicSharedMemorySize, SMEM_P);
    cudaFuncSetAttribute((const void*)tma_gemm<0,2,128,2>, cudaFuncAttributeMaxDynamicSharedMemorySize, SMEM_B);

    // 1) conversions
    split_f32<<<TOTQ * CDIM / 4 / 256, 256>>>(x,       xh, xl, TOTQ * CDIM / 4);
    split_f32<<<TOTQ * CDIM / 4 / 256, 256>>>(support, sh, sl, TOTQ * CDIM / 4);
    split_f32<<<CDIM * CDIM / 4 / 256, 256>>>(Wv,      wvh, wvl, CDIM * CDIM / 4);
    split_f32<<<CDIM * CDIM / 4 / 256, 256>>>(Wp,      wph, wpl, CDIM * CDIM / 4);

    // 2) q = x @ Wv^T (hi+lo) ; k = support @ Wv^T (hi only)
    tma_gemm<2,3,256,1><<<dim3(2, 128, 1), 256, SMEM_P>>>(
        tXh, tXl, tWvh, tWvl, CDIM, CDIM, 1.0f, 0, nullptr, nullptr, qh, ql);
    tma_gemm<4,3,256,1><<<dim3(2, 128, 1), 256, SMEM_P>>>(
        tSh, tSl, tWvh, tWvl, CDIM, CDIM, 1.0f, 0, nullptr, nullptr, kh, nullptr);

    // 3) kT[b][d][m] (hi only)
    transpose_hi<<<dim3(128, 16, BB), dim3(32, 8)>>>(kh, kth);

    // 4) attn = 0.125 * q @ k^T (2-term, occ-2, fp32 out, batched)
    tma_gemm<0,2,128,2><<<dim3(32, 32, BB), 256, SMEM_B>>>(
        tQh, tQl, tKh, tKh, MROWS, CDIM, 0.125f, sAT, nullptr, attn,
        nullptr, nullptr);

    // 5) softmax + mask -> split-fp16 probs
    softmax_split<<<TOTQ, 256>>>(attn, mask, ah, al);

    // 6) o1 = attn @ v  (2-term, occ-2, B = kT hi)
    tma_gemm<0,2,128,2><<<dim3(4, 32, BB), 256, SMEM_B>>>(
        tAh, tAl, tKTh, tKTh, CDIM, MROWS, 1.0f, sQK, nullptr, o1,
        nullptr, nullptr);

    // 7) bug-faithful permute -> split-fp16
    permute_split<<<dim3(16, 16, BB * 8), dim3(32, 8)>>>(o1, o2h, o2l);

    // 8) out = o2 @ Wp^T + bp  (3-term)
    tma_gemm<1,3,256,1><<<dim3(2, 128, 1), 256, SMEM_P>>>(
        tO2h, tO2l, tWph, tWpl, CDIM, CDIM, 1.0f, 0, bp, out, nullptr, nullptr);
}

// round 9
// speedup vs baseline: 4.6050x; 1.2068x over previous
#include <cuda_runtime.h>
#include <cuda_fp16.h>
#include <cuda.h>

#define BB 4
#define NROWS 4096
#define MROWS 4096
#define CDIM 512
#define TOTQ (BB*NROWS)

// ---------------------------------------------------------------------------
// Device scratch (fp16 split: hi/lo)
// ---------------------------------------------------------------------------
__device__ __align__(16) float g_attn[(size_t)BB * NROWS * MROWS];   // 268 MB
__device__ __align__(16) float g_o1[(size_t)TOTQ * CDIM];
__device__ __align__(16) __half g_inh[(size_t)2*TOTQ*CDIM];   // x rows 0..16383, support 16384..32767
__device__ __align__(16) __half g_inl[(size_t)2*TOTQ*CDIM];
__device__ __align__(16) __half g_wvh[CDIM*CDIM], g_wvl[CDIM*CDIM];
__device__ __align__(16) __half g_wph[CDIM*CDIM], g_wpl[CDIM*CDIM];
__device__ __align__(16) __half g_qkh[(size_t)2*TOTQ*CDIM];   // q rows 0.., k rows 16384..
__device__ __align__(16) __half g_qkl[(size_t)2*TOTQ*CDIM];
__device__ __align__(16) __half g_kth[(size_t)TOTQ*CDIM];
__device__ __align__(16) __half g_ah[(size_t)BB*NROWS*MROWS];  // 134 MB (hi only)
__device__ __align__(16) __half g_o2h[(size_t)TOTQ*CDIM], g_o2l[(size_t)TOTQ*CDIM];

// ---------------------------------------------------------------------------
// device helpers
// ---------------------------------------------------------------------------
static __device__ __forceinline__ unsigned smem_u32(const void* p) {
    unsigned a;
    asm("{ .reg .u64 t; cvta.to.shared.u64 t, %1; cvt.u32.u64 %0, t; }" : "=r"(a) : "l"(p));
    return a;
}
static __device__ __forceinline__ void ldm_x4(unsigned& r0, unsigned& r1,
                                              unsigned& r2, unsigned& r3, unsigned a) {
    asm volatile("ldmatrix.sync.aligned.m8n8.x4.shared.b16 {%0,%1,%2,%3}, [%4];"
                 : "=r"(r0), "=r"(r1), "=r"(r2), "=r"(r3) : "r"(a));
}
static __device__ __forceinline__ void mma16816(float* c, const unsigned* a,
                                                const unsigned* b) {
    asm volatile(
        "mma.sync.aligned.m16n8k16.row.col.f32.f16.f16.f32 "
        "{%0,%1,%2,%3}, {%4,%5,%6,%7}, {%8,%9}, {%0,%1,%2,%3};"
        : "+f"(c[0]), "+f"(c[1]), "+f"(c[2]), "+f"(c[3])
        : "r"(a[0]), "r"(a[1]), "r"(a[2]), "r"(a[3]), "r"(b[0]), "r"(b[1]));
}
static __device__ __forceinline__ unsigned hpack(float a, float b) {
    __half2 t = __floats2half2_rn(a, b);
    return *reinterpret_cast<unsigned*>(&t);
}
static __device__ __forceinline__ void mbar_wait(unsigned mbar, unsigned phase) {
    asm volatile(
        "{\n\t.reg .pred P1;\n\t"
        "LAB_WAIT_%=:\n\t"
        "mbarrier.try_wait.parity.acquire.cta.shared::cta.b64 P1, [%0], %1, 0x989680;\n\t"
        "@P1 bra.uni LAB_DONE_%=;\n\t"
        "bra.uni LAB_WAIT_%=;\n\t"
        "LAB_DONE_%=:\n\t}"
        :: "r"(mbar), "r"(phase) : "memory");
}
static __device__ __forceinline__ void tma3(unsigned dst, const CUtensorMap* m,
                                            int x, int y, int z, unsigned mb) {
    asm volatile(
        "cp.async.bulk.tensor.3d.shared::cluster.global.tile.mbarrier::complete_tx::bytes "
        "[%0], [%1, {%2, %3, %4}], [%5];"
        :: "r"(dst), "l"(m), "r"(x), "r"(y), "r"(z), "r"(mb) : "memory");
}

// ---------------------------------------------------------------------------
// Split-fp16 HMMA GEMM, TMA loads. CTA 128 x TN. K-slab 64, 2-stage double
// buffer, SW128 smem. C = A @ B^T; A,B [rows,K] row-major.
// NTERMS=3: ah*bh + al*bh + ah*bl ; NTERMS=2: ah*bh + al*bh ; NTERMS=1: ah*bh
// MODE 0: Cf=scale*acc (batched)  MODE 1: Cf=acc+bias  MODE 2: split(acc)
// ---------------------------------------------------------------------------
#define TILEA 16384                 // 128x64 fp16

template<int MODE, int NTERMS, int TN, int MINB>
__global__ void __launch_bounds__(256, MINB) tma_gemm(
    const __grid_constant__ CUtensorMap mAh, const __grid_constant__ CUtensorMap mAl,
    const __grid_constant__ CUtensorMap mBh, const __grid_constant__ CUtensorMap mBl,
    int ldC, int Kdim, float scale, long long sC,
    const float* __restrict__ bias, float* __restrict__ Cf,
    __half* __restrict__ Ch, __half* __restrict__ Cl)
{
    constexpr unsigned TILEBN = TN * 64 * 2;
    constexpr unsigned NA = (NTERMS >= 2) ? 2u : 1u;
    constexpr unsigned NB = (NTERMS == 3) ? 2u : 1u;
    constexpr unsigned OFF_BH = NA * TILEA;
    constexpr unsigned STGX = NA * TILEA + NB * TILEBN;
    constexpr int NBP = TN / 64;
    constexpr int NBW = TN / 32;

    extern __shared__ char smem[];
    __shared__ __align__(16) unsigned long long mbar[2];
    const unsigned sa = (smem_u32(smem) + 1023) & ~1023u;
    const unsigned mbq = smem_u32(mbar);
    const int tid = threadIdx.x;
    const int wid = tid >> 5;
    const int lane = tid & 31;
    const int m0 = blockIdx.y * 128;
    const int n0 = blockIdx.x * TN;
    const int bz = blockIdx.z;

    const int m_w = (wid >> 2) * 64;
    const int n_w = (wid & 3) * (TN / 4);

    if (tid == 0) {
        asm volatile("mbarrier.init.shared.b64 [%0], 1;" :: "r"(mbq) : "memory");
        asm volatile("mbarrier.init.shared.b64 [%0], 1;" :: "r"(mbq + 8) : "memory");
    }
    __syncthreads();

    const int nslab = Kdim / 64;
    auto issue = [&](int buf, int k0) {
        if (tid == 0) {
            const unsigned mb = mbq + buf * 8;
            asm volatile("mbarrier.arrive.expect_tx.shared.b64 _, [%0], %1;"
                         :: "r"(mb), "r"(STGX) : "memory");
            const unsigned base = sa + buf * STGX;
            tma3(base, &mAh, k0, m0, bz, mb);
            if (NTERMS >= 2) tma3(base + TILEA, &mAl, k0, m0, bz, mb);
            tma3(base + OFF_BH, &mBh, k0, n0, bz, mb);
            if (NTERMS == 3) tma3(base + OFF_BH + TILEBN, &mBl, k0, n0, bz, mb);
        }
    };

    issue(0, 0);
    if (nslab > 1) issue(1, 64);

    float acc[4][NBW][4];
#pragma unroll
    for (int i = 0; i < 4; i++)
#pragma unroll
        for (int j = 0; j < NBW; j++)
#pragma unroll
            for (int p = 0; p < 4; p++) acc[i][j][p] = 0.f;

    const unsigned aoffL = (unsigned)(m_w + (lane & 15)) * 128 + ((lane >> 4) * 16);
    const unsigned boffL = (unsigned)(n_w + (lane & 7) + ((lane >> 4) << 3)) * 128
                         + ((lane & 8) ? 16 : 0);
    const unsigned sxor = (unsigned)(lane & 7) << 4;

    int phase[2] = {0, 0};
    for (int s = 0; s < nslab; s++) {
        const int buf = s & 1;
        mbar_wait(mbq + buf * 8, (unsigned)phase[buf]);
        phase[buf] ^= 1;
        const unsigned st = sa + buf * STGX;
#pragma unroll
        for (int kk = 0; kk < 4; kk++) {
            unsigned ah[4][4], al[4][4];
#pragma unroll
            for (int mb = 0; mb < 4; mb++) {
                const unsigned a = st + ((aoffL + mb * 2048 + kk * 32) ^ sxor);
                ldm_x4(ah[mb][0], ah[mb][1], ah[mb][2], ah[mb][3], a);
                if (NTERMS >= 2)
                    ldm_x4(al[mb][0], al[mb][1], al[mb][2], al[mb][3], a + TILEA);
            }
#pragma unroll
            for (int nbp = 0; nbp < NBP; nbp++) {
                unsigned bh[2][2], bl[2][2];
                const unsigned b = st + OFF_BH + ((boffL + nbp * 2048 + kk * 32) ^ sxor);
                ldm_x4(bh[0][0], bh[0][1], bh[1][0], bh[1][1], b);
                if (NTERMS == 3)
                    ldm_x4(bl[0][0], bl[0][1], bl[1][0], bl[1][1], b + TILEBN);
#pragma unroll
                for (int mb = 0; mb < 4; mb++)
#pragma unroll
                    for (int j = 0; j < 2; j++) {
                        float* c = acc[mb][2 * nbp + j];
                        mma16816(c, ah[mb], bh[j]);
                        if (NTERMS >= 2) mma16816(c, al[mb], bh[j]);
                        if (NTERMS == 3) mma16816(c, ah[mb], bl[j]);
                    }
            }
        }
        __syncthreads();
        if (s + 2 < nslab) issue(buf, (s + 2) * 64);
    }

    // ---- epilogue ----
#pragma unroll
    for (int mb = 0; mb < 4; mb++)
#pragma unroll
        for (int p = 0; p < 2; p++) {
            const long long row = m0 + m_w + mb * 16 + (lane >> 2) + p * 8;
#pragma unroll
            for (int nb = 0; nb < NBW; nb++) {
                const int col = n0 + n_w + nb * 8 + (lane & 3) * 2;
                float v0 = acc[mb][nb][2 * p];
                float v1 = acc[mb][nb][2 * p + 1];
                if (MODE == 0) {
                    float2 o = make_float2(v0 * scale, v1 * scale);
                    *(float2*)&Cf[(long long)bz * sC + row * ldC + col] = o;
                } else if (MODE == 1) {
                    float2 o = make_float2(v0 + bias[col], v1 + bias[col + 1]);
                    *(float2*)&Cf[row * ldC + col] = o;
                } else {
                    __half h0 = __float2half(v0);
                    __half h1 = __float2half(v1);
                    *(unsigned*)&Ch[row * (long long)ldC + col] =
                        hpack(__half2float(h0), __half2float(h1));
                    *(unsigned*)&Cl[row * (long long)ldC + col] =
                        hpack(v0 - __half2float(h0), v1 - __half2float(h1));
                }
            }
        }
}

// ---------------------------------------------------------------------------
// fp32 -> split fp16 (hi/lo)
// ---------------------------------------------------------------------------
__global__ void __launch_bounds__(256) split_f32(
    const float* __restrict__ src, __half* __restrict__ h,
    __half* __restrict__ l, int n4)
{
    int i = blockIdx.x * 256 + threadIdx.x;
    if (i >= n4) return;
    float4 v = ((const float4*)src)[i];
    __half h0 = __float2half(v.x), h1 = __float2half(v.y);
    __half h2 = __float2half(v.z), h3 = __float2half(v.w);
    uint2 ph, pl;
    ph.x = hpack(__half2float(h0), __half2float(h1));
    ph.y = hpack(__half2float(h2), __half2float(h3));
    pl.x = hpack(v.x - __half2float(h0), v.y - __half2float(h1));
    pl.y = hpack(v.z - __half2float(h2), v.w - __half2float(h3));
    ((uint2*)h)[i] = ph;
    ((uint2*)l)[i] = pl;
}

// ---------------------------------------------------------------------------
// kT (hi only): kth[b][d][m] = kh[b*4096+m][d]
// ---------------------------------------------------------------------------
__global__ void __launch_bounds__(256) transpose_hi(
    const __half* __restrict__ kh, __half* __restrict__ kth)
{
    __shared__ __half th[32][33];
    const int b = blockIdx.z;
    const int mm0 = blockIdx.x * 32;
    const int d0 = blockIdx.y * 32;
    const int tx = threadIdx.x, ty = threadIdx.y;
    const long long sbase = (long long)(b * 4096 + mm0) * CDIM + d0;
#pragma unroll
    for (int hh = 0; hh < 32; hh += 8)
        th[ty + hh][tx] = kh[sbase + (long long)(ty + hh) * CDIM + tx];
    __syncthreads();
    const long long dbase = (long long)b * CDIM * MROWS + (long long)d0 * MROWS + mm0;
#pragma unroll
    for (int hh = 0; hh < 32; hh += 8)
        kth[dbase + (long long)(ty + hh) * MROWS + tx] = th[tx][ty + hh];
}

// ---------------------------------------------------------------------------
// Row softmax (4096) + post-softmax mask; fp16 hi-only probability output.
// ---------------------------------------------------------------------------
__global__ void __launch_bounds__(256) softmax_hi(
    const float* __restrict__ attn, const int* __restrict__ mask,
    __half* __restrict__ ah)
{
    __shared__ float rmax[8];
    __shared__ float rsum[8];
    const float* p = attn + (long long)blockIdx.x * MROWS;
    const int t = threadIdx.x;

    float4 v[4];
    float mx = -1e30f;
#pragma unroll
    for (int u = 0; u < 4; u++) {
        v[u] = ((const float4*)p)[u * 256 + t];
        mx = fmaxf(mx, fmaxf(fmaxf(v[u].x, v[u].y), fmaxf(v[u].z, v[u].w)));
    }
#pragma unroll
    for (int o = 16; o > 0; o >>= 1) mx = fmaxf(mx, __shfl_xor_sync(0xffffffffu, mx, o));
    if ((t & 31) == 0) rmax[t >> 5] = mx;
    __syncthreads();
    mx = fmaxf(fmaxf(fmaxf(rmax[0], rmax[1]), fmaxf(rmax[2], rmax[3])),
               fmaxf(fmaxf(rmax[4], rmax[5]), fmaxf(rmax[6], rmax[7])));

    float s = 0.f;
#pragma unroll
    for (int u = 0; u < 4; u++) {
        v[u].x = expf(v[u].x - mx); v[u].y = expf(v[u].y - mx);
        v[u].z = expf(v[u].z - mx); v[u].w = expf(v[u].w - mx);
        s += v[u].x + v[u].y + v[u].z + v[u].w;
    }
#pragma unroll
    for (int o = 16; o > 0; o >>= 1) s += __shfl_xor_sync(0xffffffffu, s, o);
    if ((t & 31) == 0) rsum[t >> 5] = s;
    __syncthreads();
    s = (rsum[0] + rsum[1]) + (rsum[2] + rsum[3]) + (rsum[4] + rsum[5]) + (rsum[6] + rsum[7]);
    const float inv = 1.0f / s;

    __half* bh = ah + (long long)blockIdx.x * MROWS;
#pragma unroll
    for (int u = 0; u < 4; u++) {
        const int i4 = u * 256 + t;
        const int4 mq = ((const int4*)mask)[i4];
        float o0 = v[u].x * inv * (mq.x != 0 ? 1.f : 0.f);
        float o1 = v[u].y * inv * (mq.y != 0 ? 1.f : 0.f);
        float o2 = v[u].z * inv * (mq.z != 0 ? 1.f : 0.f);
        float o3 = v[u].w * inv * (mq.w != 0 ? 1.f : 0.f);
        uint2 ph;
        ph.x = hpack(o0, o1);
        ph.y = hpack(o2, o3);
        ((uint2*)bh)[i4] = ph;
    }
}

// ---------------------------------------------------------------------------
// Bug-faithful permute: o2[b, 8a+r, j] = o1[b, r*512 + j, a], split-fp16 out
// ---------------------------------------------------------------------------
__global__ void __launch_bounds__(256) permute_split(
    const float* __restrict__ o1, __half* __restrict__ oh,
    __half* __restrict__ ol)
{
    __shared__ float tile[32][33];
    const int br = blockIdx.z;
    const int b = br >> 3;
    const int r = br & 7;
    const float* src = o1 + (long long)b * NROWS * CDIM + (long long)r * 512 * CDIM;
    const long long dbase = (long long)b * NROWS * CDIM + r * CDIM;
    const int j0 = blockIdx.y * 32;
    const int a0 = blockIdx.x * 32;
    const int tx = threadIdx.x, ty = threadIdx.y;

#pragma unroll
    for (int hh = 0; hh < 32; hh += 8)
        tile[ty + hh][tx] = src[(long long)(j0 + ty + hh) * 512 + a0 + tx];
    __syncthreads();
#pragma unroll
    for (int hh = 0; hh < 32; hh += 8) {
        float v = tile[tx][ty + hh];
        long long off = dbase + (long long)(a0 + ty + hh) * 4096 + j0 + tx;
        __half hi = __float2half(v);
        oh[off] = hi;
        ol[off] = __float2half(v - __half2float(hi));
    }
}

// ---------------------------------------------------------------------------
// Host: tensormap encode via driver entry point
// ---------------------------------------------------------------------------
typedef CUresult (*PFN_tmapEnc)(
    CUtensorMap*, CUtensorMapDataType, cuuint32_t, void*,
    const cuuint64_t*, const cuuint64_t*, const cuuint32_t*, const cuuint32_t*,
    CUtensorMapInterleave, CUtensorMapSwizzle, CUtensorMapL2promotion,
    CUtensorMapFloatOOBfill);

static void enc_map(PFN_tmapEnc fn, CUtensorMap* m, const void* ptr,
                    unsigned long long K, unsigned long long rows,
                    unsigned long long batches, unsigned long long ldElems,
                    unsigned long long bStrideElems, unsigned boxRows)
{
    cuuint64_t dims[3] = {K, rows, batches};
    cuuint64_t strides[2] = {ldElems * 2ull, bStrideElems * 2ull};
    cuuint32_t box[3] = {64, boxRows, 1};
    cuuint32_t estr[3] = {1, 1, 1};
    fn(m, CU_TENSOR_MAP_DATA_TYPE_FLOAT16, 3, (void*)ptr,
       dims, strides, box, estr,
       CU_TENSOR_MAP_INTERLEAVE_NONE, CU_TENSOR_MAP_SWIZZLE_128B,
       CU_TENSOR_MAP_L2_PROMOTION_L2_128B, CU_TENSOR_MAP_FLOAT_OOB_FILL_NONE);
}

extern "C" void kernel_launch(void* const* d_in, const int* in_sizes, int n_in,
                              void* d_out, int out_size)
{
    const float* x       = (const float*)d_in[0];
    const float* support = (const float*)d_in[1];
    const int*   mask    = (const int*)  d_in[2];
    const float* Wv      = (const float*)d_in[3];
    const float* Wp      = (const float*)d_in[4];
    const float* bp      = (const float*)d_in[5];
    float* out = (float*)d_out;

    float *attn, *o1;
    __half *inh, *inl, *wvh, *wvl, *wph, *wpl;
    __half *qkh, *qkl, *kth, *ah, *o2h, *o2l;
    cudaGetSymbolAddress((void**)&attn, g_attn);
    cudaGetSymbolAddress((void**)&o1,   g_o1);
    cudaGetSymbolAddress((void**)&inh, g_inh); cudaGetSymbolAddress((void**)&inl, g_inl);
    cudaGetSymbolAddress((void**)&wvh, g_wvh); cudaGetSymbolAddress((void**)&wvl, g_wvl);
    cudaGetSymbolAddress((void**)&wph, g_wph); cudaGetSymbolAddress((void**)&wpl, g_wpl);
    cudaGetSymbolAddress((void**)&qkh, g_qkh); cudaGetSymbolAddress((void**)&qkl, g_qkl);
    cudaGetSymbolAddress((void**)&kth, g_kth);
    cudaGetSymbolAddress((void**)&ah, g_ah);
    cudaGetSymbolAddress((void**)&o2h, g_o2h); cudaGetSymbolAddress((void**)&o2l, g_o2l);

    __half* kh = qkh + (size_t)TOTQ * CDIM;   // k = second half of qk

    void* sym = nullptr;
    cudaDriverEntryPointQueryResult qres;
    cudaGetDriverEntryPointByVersion("cuTensorMapEncodeTiled", &sym, 12000,
                                     cudaEnableDefault, &qres);
    PFN_tmapEnc enc = (PFN_tmapEnc)sym;

    const long long sQK = (long long)NROWS * CDIM;
    const long long sAT = (long long)NROWS * MROWS;

    // projection (merged q+k): A = stacked inputs [32768, 512]
    CUtensorMap tInh, tInl, tWvh, tWvl, tWph, tWpl;
    enc_map(enc, &tInh, inh, CDIM, 2 * TOTQ, 1, CDIM, (long long)2 * TOTQ * CDIM, 128);
    enc_map(enc, &tInl, inl, CDIM, 2 * TOTQ, 1, CDIM, (long long)2 * TOTQ * CDIM, 128);
    enc_map(enc, &tWvh, wvh, CDIM, CDIM, 1, CDIM, (long long)CDIM * CDIM, 256);
    enc_map(enc, &tWvl, wvl, CDIM, CDIM, 1, CDIM, (long long)CDIM * CDIM, 256);
    enc_map(enc, &tWph, wph, CDIM, CDIM, 1, CDIM, (long long)CDIM * CDIM, 256);
    enc_map(enc, &tWpl, wpl, CDIM, CDIM, 1, CDIM, (long long)CDIM * CDIM, 256);
    // QK^T
    CUtensorMap tQh, tQl, tKh;
    enc_map(enc, &tQh, qkh, CDIM, NROWS, BB, CDIM, sQK, 128);
    enc_map(enc, &tQl, qkl, CDIM, NROWS, BB, CDIM, sQK, 128);
    enc_map(enc, &tKh, kh,  CDIM, NROWS, BB, CDIM, sQK, 128);
    // AV
    CUtensorMap tAh, tKTh;
    enc_map(enc, &tAh, ah, MROWS, NROWS, BB, MROWS, sAT, 128);
    enc_map(enc, &tKTh, kth, MROWS, CDIM, BB, MROWS, (long long)CDIM * MROWS, 128);
    // out proj
    CUtensorMap tO2h, tO2l;
    enc_map(enc, &tO2h, o2h, CDIM, TOTQ, 1, CDIM, (long long)TOTQ * CDIM, 128);
    enc_map(enc, &tO2l, o2l, CDIM, TOTQ, 1, CDIM, (long long)TOTQ * CDIM, 128);

    // smem sizes
    const int SMEM_P  = 1024 + 2 * (2 * TILEA + 2 * (256 * 64 * 2));  // 197632, occ1
    const int SMEM_QK = 1024 + 2 * (2 * TILEA + (128 * 64 * 2));      //  99328, occ2
    const int SMEM_AV = 1024 + 2 * (TILEA + (128 * 64 * 2));          //  66560, occ2
    cudaFuncSetAttribute((const void*)tma_gemm<2,3,256,1>, cudaFuncAttributeMaxDynamicSharedMemorySize, SMEM_P);
    cudaFuncSetAttribute((const void*)tma_gemm<1,3,256,1>, cudaFuncAttributeMaxDynamicSharedMemorySize, SMEM_P);
    cudaFuncSetAttribute((const void*)tma_gemm<0,2,128,2>, cudaFuncAttributeMaxDynamicSharedMemorySize, SMEM_QK);
    cudaFuncSetAttribute((const void*)tma_gemm<0,1,128,2>, cudaFuncAttributeMaxDynamicSharedMemorySize, SMEM_AV);

    // 1) conversions (x -> rows 0..16383, support -> rows 16384..32767)
    split_f32<<<TOTQ * CDIM / 4 / 256, 256>>>(x, inh, inl, TOTQ * CDIM / 4);
    split_f32<<<TOTQ * CDIM / 4 / 256, 256>>>(support,
        inh + (size_t)TOTQ * CDIM, inl + (size_t)TOTQ * CDIM, TOTQ * CDIM / 4);
    split_f32<<<CDIM * CDIM / 4 / 256, 256>>>(Wv, wvh, wvl, CDIM * CDIM / 4);
    split_f32<<<CDIM * CDIM / 4 / 256, 256>>>(Wp, wph, wpl, CDIM * CDIM / 4);

    // 2) merged projection: [q;k] = [x;support] @ Wv^T  (split out)
    tma_gemm<2,3,256,1><<<dim3(2, 256, 1), 256, SMEM_P>>>(
        tInh, tInl, tWvh, tWvl, CDIM, CDIM, 1.0f, 0, nullptr, nullptr, qkh, qkl);

    // 3) kT[b][d][m] (hi only)
    transpose_hi<<<dim3(128, 16, BB), dim3(32, 8)>>>(kh, kth);

    // 4) attn = 0.125 * q @ k^T (2-term, occ-2, fp32 out, batched)
    tma_gemm<0,2,128,2><<<dim3(32, 32, BB), 256, SMEM_QK>>>(
        tQh, tQl, tKh, tKh, MROWS, CDIM, 0.125f, sAT, nullptr, attn,
        nullptr, nullptr);

    // 5) softmax + mask -> fp16 hi probs
    softmax_hi<<<TOTQ, 256>>>(attn, mask, ah);

    // 6) o1 = attn @ v  (1-term, occ-2, B = kT hi)
    tma_gemm<0,1,128,2><<<dim3(4, 32, BB), 256, SMEM_AV>>>(
        tAh, tAh, tKTh, tKTh, CDIM, MROWS, 1.0f, sQK, nullptr, o1,
        nullptr, nullptr);

    // 7) bug-faithful permute -> split-fp16
    permute_split<<<dim3(16, 16, BB * 8), dim3(32, 8)>>>(o1, o2h, o2l);

    // 8) out = o2 @ Wp^T + bp  (3-term)
    tma_gemm<1,3,256,1><<<dim3(2, 128, 1), 256, SMEM_P>>>(
        tO2h, tO2l, tWph, tWpl, CDIM, CDIM, 1.0f, 0, bp, out, nullptr, nullptr);
}

// round 12
// speedup vs baseline: 4.6509x; 1.0100x over previous
#include <cuda_runtime.h>
#include <cuda_fp16.h>
#include <cuda.h>

#define BB 4
#define NROWS 4096
#define MROWS 4096
#define CDIM 512
#define TOTQ (BB*NROWS)

// ---------------------------------------------------------------------------
// Device scratch
// ---------------------------------------------------------------------------
__device__ __align__(16) float g_attn[(size_t)BB * NROWS * MROWS];   // 268 MB
__device__ __align__(16) __half g_inh[(size_t)2*TOTQ*CDIM];    // x | support
__device__ __align__(16) __half g_inl[(size_t)2*TOTQ*CDIM];
__device__ __align__(16) __half g_wvh[CDIM*CDIM], g_wvl[CDIM*CDIM];
__device__ __align__(16) __half g_wph[CDIM*CDIM], g_wpl[CDIM*CDIM];
__device__ __align__(16) __half g_qkh[(size_t)2*TOTQ*CDIM];    // q | k
__device__ __align__(16) __half g_qkl[(size_t)2*TOTQ*CDIM];
__device__ __align__(16) __half g_kth[(size_t)TOTQ*CDIM];
__device__ __align__(16) __half g_ah[(size_t)BB*NROWS*MROWS];  // normalized probs (hi)
__device__ __align__(16) __half g_o2h[(size_t)TOTQ*CDIM], g_o2l[(size_t)TOTQ*CDIM];

// ---------------------------------------------------------------------------
// device helpers
// ---------------------------------------------------------------------------
static __device__ __forceinline__ unsigned smem_u32(const void* p) {
    unsigned a;
    asm("{ .reg .u64 t; cvta.to.shared.u64 t, %1; cvt.u32.u64 %0, t; }" : "=r"(a) : "l"(p));
    return a;
}
static __device__ __forceinline__ void ldm_x4(unsigned& r0, unsigned& r1,
                                              unsigned& r2, unsigned& r3, unsigned a) {
    asm volatile("ldmatrix.sync.aligned.m8n8.x4.shared.b16 {%0,%1,%2,%3}, [%4];"
                 : "=r"(r0), "=r"(r1), "=r"(r2), "=r"(r3) : "r"(a));
}
static __device__ __forceinline__ void mma16816(float* c, const unsigned* a,
                                                const unsigned* b) {
    asm volatile(
        "mma.sync.aligned.m16n8k16.row.col.f32.f16.f16.f32 "
        "{%0,%1,%2,%3}, {%4,%5,%6,%7}, {%8,%9}, {%0,%1,%2,%3};"
        : "+f"(c[0]), "+f"(c[1]), "+f"(c[2]), "+f"(c[3])
        : "r"(a[0]), "r"(a[1]), "r"(a[2]), "r"(a[3]), "r"(b[0]), "r"(b[1]));
}
static __device__ __forceinline__ unsigned hpack(float a, float b) {
    __half2 t = __floats2half2_rn(a, b);
    return *reinterpret_cast<unsigned*>(&t);
}
static __device__ __forceinline__ unsigned hsplitpack(float v) {
    __half h = __float2half(v);
    float lo = v - __half2float(h);
    __half l = __float2half(lo);
    return (unsigned)(*reinterpret_cast<unsigned short*>(&h))
         | ((unsigned)(*reinterpret_cast<unsigned short*>(&l)) << 16);
}
static __device__ __forceinline__ void mbar_wait(unsigned mbar, unsigned phase) {
    asm volatile(
        "{\n\t.reg .pred P1;\n\t"
        "LAB_WAIT_%=:\n\t"
        "mbarrier.try_wait.parity.acquire.cta.shared::cta.b64 P1, [%0], %1, 0x989680;\n\t"
        "@P1 bra.uni LAB_DONE_%=;\n\t"
        "bra.uni LAB_WAIT_%=;\n\t"
        "LAB_DONE_%=:\n\t}"
        :: "r"(mbar), "r"(phase) : "memory");
}
static __device__ __forceinline__ void tma3(unsigned dst, const CUtensorMap* m,
                                            int x, int y, int z, unsigned mb) {
    asm volatile(
        "cp.async.bulk.tensor.3d.shared::cluster.global.tile.mbarrier::complete_tx::bytes "
        "[%0], [%1, {%2, %3, %4}], [%5];"
        :: "r"(dst), "l"(m), "r"(x), "r"(y), "r"(z), "r"(mb) : "memory");
}

// ---------------------------------------------------------------------------
// Split-fp16 HMMA GEMM, TMA loads. CTA 128 x TN, K-slab 64, 2-stage buffer.
// C = A @ B^T; A,B [rows,K] row-major.
// NTERMS=3: ah*bh+al*bh+ah*bl ; 2: ah*bh+al*bh ; 1: ah*bh
// MODE 0: Cf = scale*acc (batched)
// MODE 1: Cf = acc + bias
// MODE 2: (Ch,Cl) = split(acc)
// MODE 6: bug-faithful permuted split write of scale*acc into (Ch,Cl)
// ---------------------------------------------------------------------------
#define TILEA 16384                 // 128x64 fp16

template<int MODE, int NTERMS, int TN, int MINB>
__global__ void __launch_bounds__(256, MINB) tma_gemm(
    const __grid_constant__ CUtensorMap mAh, const __grid_constant__ CUtensorMap mAl,
    const __grid_constant__ CUtensorMap mBh, const __grid_constant__ CUtensorMap mBl,
    int ldC, int Kdim, float scale, long long sC,
    const float* __restrict__ bias, float* __restrict__ Cf,
    __half* __restrict__ Ch, __half* __restrict__ Cl)
{
    constexpr unsigned TILEBN = TN * 64 * 2;
    constexpr unsigned NA = (NTERMS >= 2) ? 2u : 1u;
    constexpr unsigned NB = (NTERMS == 3) ? 2u : 1u;
    constexpr unsigned OFF_BH = NA * TILEA;
    constexpr unsigned STGX = NA * TILEA + NB * TILEBN;
    constexpr int NBP = TN / 64;
    constexpr int NBW = TN / 32;

    extern __shared__ char smem[];
    __shared__ __align__(16) unsigned long long mbar[2];
    const unsigned sa = (smem_u32(smem) + 1023) & ~1023u;
    const unsigned mbq = smem_u32(mbar);
    const int tid = threadIdx.x;
    const int wid = tid >> 5;
    const int lane = tid & 31;
    const int m0 = blockIdx.y * 128;
    const int n0 = blockIdx.x * TN;
    const int bz = blockIdx.z;

    const int m_w = (wid >> 2) * 64;
    const int n_w = (wid & 3) * (TN / 4);

    if (tid == 0) {
        asm volatile("mbarrier.init.shared.b64 [%0], 1;" :: "r"(mbq) : "memory");
        asm volatile("mbarrier.init.shared.b64 [%0], 1;" :: "r"(mbq + 8) : "memory");
    }
    __syncthreads();

    const int nslab = Kdim / 64;
    auto issue = [&](int buf, int k0) {
        if (tid == 0) {
            const unsigned mb = mbq + buf * 8;
            asm volatile("mbarrier.arrive.expect_tx.shared.b64 _, [%0], %1;"
                         :: "r"(mb), "r"(STGX) : "memory");
            const unsigned base = sa + buf * STGX;
            tma3(base, &mAh, k0, m0, bz, mb);
            if (NTERMS >= 2) tma3(base + TILEA, &mAl, k0, m0, bz, mb);
            tma3(base + OFF_BH, &mBh, k0, n0, bz, mb);
            if (NTERMS == 3) tma3(base + OFF_BH + TILEBN, &mBl, k0, n0, bz, mb);
        }
    };

    issue(0, 0);
    if (nslab > 1) issue(1, 64);

    float acc[4][NBW][4];
#pragma unroll
    for (int i = 0; i < 4; i++)
#pragma unroll
        for (int j = 0; j < NBW; j++)
#pragma unroll
            for (int p = 0; p < 4; p++) acc[i][j][p] = 0.f;

    const unsigned aoffL = (unsigned)(m_w + (lane & 15)) * 128 + ((lane >> 4) * 16);
    const unsigned boffL = (unsigned)(n_w + (lane & 7) + ((lane >> 4) << 3)) * 128
                         + ((lane & 8) ? 16 : 0);
    const unsigned sxor = (unsigned)(lane & 7) << 4;

    int phase[2] = {0, 0};
    for (int s = 0; s < nslab; s++) {
        const int buf = s & 1;
        mbar_wait(mbq + buf * 8, (unsigned)phase[buf]);
        phase[buf] ^= 1;
        const unsigned st = sa + buf * STGX;
#pragma unroll
        for (int kk = 0; kk < 4; kk++) {
            unsigned ah[4][4], al[4][4];
#pragma unroll
            for (int mb = 0; mb < 4; mb++) {
                const unsigned a = st + ((aoffL + mb * 2048 + kk * 32) ^ sxor);
                ldm_x4(ah[mb][0], ah[mb][1], ah[mb][2], ah[mb][3], a);
                if (NTERMS >= 2)
                    ldm_x4(al[mb][0], al[mb][1], al[mb][2], al[mb][3], a + TILEA);
            }
#pragma unroll
            for (int nbp = 0; nbp < NBP; nbp++) {
                unsigned bh[2][2], bl[2][2];
                const unsigned b = st + OFF_BH + ((boffL + nbp * 2048 + kk * 32) ^ sxor);
                ldm_x4(bh[0][0], bh[0][1], bh[1][0], bh[1][1], b);
                if (NTERMS == 3)
                    ldm_x4(bl[0][0], bl[0][1], bl[1][0], bl[1][1], b + TILEBN);
#pragma unroll
                for (int mb = 0; mb < 4; mb++)
#pragma unroll
                    for (int j = 0; j < 2; j++) {
                        float* c = acc[mb][2 * nbp + j];
                        mma16816(c, ah[mb], bh[j]);
                        if (NTERMS >= 2) mma16816(c, al[mb], bh[j]);
                        if (NTERMS == 3) mma16816(c, ah[mb], bl[j]);
                    }
            }
        }
        __syncthreads();
        if (s + 2 < nslab) issue(buf, (s + 2) * 64);
    }

    // ======================= epilogues =======================
    if (MODE == 0 || MODE == 1 || MODE == 2) {
#pragma unroll
        for (int mb = 0; mb < 4; mb++)
#pragma unroll
            for (int p = 0; p < 2; p++) {
                const long long row = m0 + m_w + mb * 16 + (lane >> 2) + p * 8;
#pragma unroll
                for (int nb = 0; nb < NBW; nb++) {
                    const int col = n0 + n_w + nb * 8 + (lane & 3) * 2;
                    float v0 = acc[mb][nb][2 * p];
                    float v1 = acc[mb][nb][2 * p + 1];
                    if (MODE == 0) {
                        float2 o = make_float2(v0 * scale, v1 * scale);
                        *(float2*)&Cf[(long long)bz * sC + row * ldC + col] = o;
                    } else if (MODE == 1) {
                        float2 o = make_float2(v0 + bias[col], v1 + bias[col + 1]);
                        *(float2*)&Cf[row * ldC + col] = o;
                    } else {
                        __half h0 = __float2half(v0);
                        __half h1 = __float2half(v1);
                        *(unsigned*)&Ch[row * (long long)ldC + col] =
                            hpack(__half2float(h0), __half2float(h1));
                        *(unsigned*)&Cl[row * (long long)ldC + col] =
                            hpack(v0 - __half2float(h0), v1 - __half2float(h1));
                    }
                }
            }
    }

    if (MODE == 6) {
        // scale, in-CTA transpose, bug-faithful permuted split-fp16 write
        char* smal = smem + (int)(sa - smem_u32(smem));
        unsigned* S = (unsigned*)smal;
#pragma unroll
        for (int mb = 0; mb < 4; mb++)
#pragma unroll
            for (int p = 0; p < 2; p++) {
                const int row = m0 + m_w + mb * 16 + (lane >> 2) + p * 8;
                const int jl = row - m0;
#pragma unroll
                for (int nb = 0; nb < NBW; nb++) {
                    const int col = n0 + n_w + nb * 8 + (lane & 3) * 2;
                    float v0 = acc[mb][nb][2 * p] * scale;
                    float v1 = acc[mb][nb][2 * p + 1] * scale;
                    S[(col - n0) * 132 + jl] = hsplitpack(v0);
                    S[(col + 1 - n0) * 132 + jl] = hsplitpack(v1);
                }
            }
        __syncthreads();
        const int rr = m0 >> 9;
        const int j0 = m0 & 511;
        const long long ob = (long long)bz * ((long long)NROWS * CDIM) + j0;
#pragma unroll 4
        for (int rp = wid; rp < 256; rp += 8) {
            const int dl = rp >> 1;
            const int pl = rp & 1;
            uint4 q = *(uint4*)&S[dl * 132 + 4 * lane];
            unsigned a0, a1;
            if (pl == 0) {
                a0 = (q.x & 0xFFFFu) | (q.y << 16);
                a1 = (q.z & 0xFFFFu) | (q.w << 16);
            } else {
                a0 = (q.x >> 16) | (q.y & 0xFFFF0000u);
                a1 = (q.z >> 16) | (q.w & 0xFFFF0000u);
            }
            __half* dst = (pl ? Cl : Ch) + ob
                        + (long long)((((n0 + dl) << 3) + rr)) * 512;
            *(uint2*)(dst + 4 * lane) = make_uint2(a0, a1);
        }
    }
}

// ---------------------------------------------------------------------------
// fp32 -> split fp16 (hi/lo)
// ---------------------------------------------------------------------------
__global__ void __launch_bounds__(256) split_f32(
    const float* __restrict__ src, __half* __restrict__ h,
    __half* __restrict__ l, int n4)
{
    int i = blockIdx.x * 256 + threadIdx.x;
    if (i >= n4) return;
    float4 v = ((const float4*)src)[i];
    __half h0 = __float2half(v.x), h1 = __float2half(v.y);
    __half h2 = __float2half(v.z), h3 = __float2half(v.w);
    uint2 ph, pl;
    ph.x = hpack(__half2float(h0), __half2float(h1));
    ph.y = hpack(__half2float(h2), __half2float(h3));
    pl.x = hpack(v.x - __half2float(h0), v.y - __half2float(h1));
    pl.y = hpack(v.z - __half2float(h2), v.w - __half2float(h3));
    ((uint2*)h)[i] = ph;
    ((uint2*)l)[i] = pl;
}

// ---------------------------------------------------------------------------
// kT (hi only): kth[b][d][m] = kh[b*4096+m][d]
// ---------------------------------------------------------------------------
__global__ void __launch_bounds__(256) transpose_hi(
    const __half* __restrict__ kh, __half* __restrict__ kth)
{
    __shared__ __half th[32][33];
    const int b = blockIdx.z;
    const int mm0 = blockIdx.x * 32;
    const int d0 = blockIdx.y * 32;
    const int tx = threadIdx.x, ty = threadIdx.y;
    const long long sbase = (long long)(b * 4096 + mm0) * CDIM + d0;
#pragma unroll
    for (int hh = 0; hh < 32; hh += 8)
        th[ty + hh][tx] = kh[sbase + (long long)(ty + hh) * CDIM + tx];
    __syncthreads();
    const long long dbase = (long long)b * CDIM * MROWS + (long long)d0 * MROWS + mm0;
#pragma unroll
    for (int hh = 0; hh < 32; hh += 8)
        kth[dbase + (long long)(ty + hh) * MROWS + tx] = th[tx][ty + hh];
}

// ---------------------------------------------------------------------------
// Row softmax (4096) + post-softmax mask; fp16 hi-only probability output.
// ---------------------------------------------------------------------------
__global__ void __launch_bounds__(256) softmax_hi(
    const float* __restrict__ attn, const int* __restrict__ mask,
    __half* __restrict__ ah)
{
    __shared__ float rmax[8];
    __shared__ float rsum[8];
    const float* p = attn + (long long)blockIdx.x * MROWS;
    const int t = threadIdx.x;

    float4 v[4];
    float mx = -1e30f;
#pragma unroll
    for (int u = 0; u < 4; u++) {
        v[u] = ((const float4*)p)[u * 256 + t];
        mx = fmaxf(mx, fmaxf(fmaxf(v[u].x, v[u].y), fmaxf(v[u].z, v[u].w)));
    }
#pragma unroll
    for (int o = 16; o > 0; o >>= 1) mx = fmaxf(mx, __shfl_xor_sync(0xffffffffu, mx, o));
    if ((t & 31) == 0) rmax[t >> 5] = mx;
    __syncthreads();
    mx = fmaxf(fmaxf(fmaxf(rmax[0], rmax[1]), fmaxf(rmax[2], rmax[3])),
               fmaxf(fmaxf(rmax[4], rmax[5]), fmaxf(rmax[6], rmax[7])));

    float s = 0.f;
#pragma unroll
    for (int u = 0; u < 4; u++) {
        v[u].x = expf(v[u].x - mx); v[u].y = expf(v[u].y - mx);
        v[u].z = expf(v[u].z - mx); v[u].w = expf(v[u].w - mx);
        s += v[u].x + v[u].y + v[u].z + v[u].w;
    }
#pragma unroll
    for (int o = 16; o > 0; o >>= 1) s += __shfl_xor_sync(0xffffffffu, s, o);
    if ((t & 31) == 0) rsum[t >> 5] = s;
    __syncthreads();
    s = (rsum[0] + rsum[1]) + (rsum[2] + rsum[3]) + (rsum[4] + rsum[5]) + (rsum[6] + rsum[7]);
    const float inv = 1.0f / s;

    __half* bh = ah + (long long)blockIdx.x * MROWS;
#pragma unroll
    for (int u = 0; u < 4; u++) {
        const int i4 = u * 256 + t;
        const int4 mq = ((const int4*)mask)[i4];
        float o0 = v[u].x * inv * (mq.x != 0 ? 1.f : 0.f);
        float o1 = v[u].y * inv * (mq.y != 0 ? 1.f : 0.f);
        float o2 = v[u].z * inv * (mq.z != 0 ? 1.f : 0.f);
        float o3 = v[u].w * inv * (mq.w != 0 ? 1.f : 0.f);
        uint2 ph;
        ph.x = hpack(o0, o1);
        ph.y = hpack(o2, o3);
        ((uint2*)bh)[i4] = ph;
    }
}

// ---------------------------------------------------------------------------
// Host: tensormap encode via driver entry point
// ---------------------------------------------------------------------------
typedef CUresult (*PFN_tmapEnc)(
    CUtensorMap*, CUtensorMapDataType, cuuint32_t, void*,
    const cuuint64_t*, const cuuint64_t*, const cuuint32_t*, const cuuint32_t*,
    CUtensorMapInterleave, CUtensorMapSwizzle, CUtensorMapL2promotion,
    CUtensorMapFloatOOBfill);

static void enc_map(PFN_tmapEnc fn, CUtensorMap* m, const void* ptr,
                    unsigned long long K, unsigned long long rows,
                    unsigned long long batches, unsigned long long ldElems,
                    unsigned long long bStrideElems, unsigned boxRows)
{
    cuuint64_t dims[3] = {K, rows, batches};
    cuuint64_t strides[2] = {ldElems * 2ull, bStrideElems * 2ull};
    cuuint32_t box[3] = {64, boxRows, 1};
    cuuint32_t estr[3] = {1, 1, 1};
    fn(m, CU_TENSOR_MAP_DATA_TYPE_FLOAT16, 3, (void*)ptr,
       dims, strides, box, estr,
       CU_TENSOR_MAP_INTERLEAVE_NONE, CU_TENSOR_MAP_SWIZZLE_128B,
       CU_TENSOR_MAP_L2_PROMOTION_L2_128B, CU_TENSOR_MAP_FLOAT_OOB_FILL_NONE);
}

extern "C" void kernel_launch(void* const* d_in, const int* in_sizes, int n_in,
                              void* d_out, int out_size)
{
    const float* x       = (const float*)d_in[0];
    const float* support = (const float*)d_in[1];
    const int*   mask    = (const int*)  d_in[2];
    const float* Wv      = (const float*)d_in[3];
    const float* Wp      = (const float*)d_in[4];
    const float* bp      = (const float*)d_in[5];
    float* out = (float*)d_out;

    float* attn;
    __half *inh, *inl, *wvh, *wvl, *wph, *wpl;
    __half *qkh, *qkl, *kth, *ah, *o2h, *o2l;
    cudaGetSymbolAddress((void**)&attn, g_attn);
    cudaGetSymbolAddress((void**)&inh, g_inh); cudaGetSymbolAddress((void**)&inl, g_inl);
    cudaGetSymbolAddress((void**)&wvh, g_wvh); cudaGetSymbolAddress((void**)&wvl, g_wvl);
    cudaGetSymbolAddress((void**)&wph, g_wph); cudaGetSymbolAddress((void**)&wpl, g_wpl);
    cudaGetSymbolAddress((void**)&qkh, g_qkh); cudaGetSymbolAddress((void**)&qkl, g_qkl);
    cudaGetSymbolAddress((void**)&kth, g_kth);
    cudaGetSymbolAddress((void**)&ah, g_ah);
    cudaGetSymbolAddress((void**)&o2h, g_o2h); cudaGetSymbolAddress((void**)&o2l, g_o2l);

    __half* kh = qkh + (size_t)TOTQ * CDIM;

    void* sym = nullptr;
    cudaDriverEntryPointQueryResult qres;
    cudaGetDriverEntryPointByVersion("cuTensorMapEncodeTiled", &sym, 12000,
                                     cudaEnableDefault, &qres);
    PFN_tmapEnc enc = (PFN_tmapEnc)sym;

    const long long sQK = (long long)NROWS * CDIM;
    const long long sAT = (long long)NROWS * MROWS;

    CUtensorMap tInh, tInl, tWvh, tWvl, tWph, tWpl;
    enc_map(enc, &tInh, inh, CDIM, 2 * TOTQ, 1, CDIM, (long long)2 * TOTQ * CDIM, 128);
    enc_map(enc, &tInl, inl, CDIM, 2 * TOTQ, 1, CDIM, (long long)2 * TOTQ * CDIM, 128);
    enc_map(enc, &tWvh, wvh, CDIM, CDIM, 1, CDIM, (long long)CDIM * CDIM, 256);
    enc_map(enc, &tWvl, wvl, CDIM, CDIM, 1, CDIM, (long long)CDIM * CDIM, 256);
    enc_map(enc, &tWph, wph, CDIM, CDIM, 1, CDIM, (long long)CDIM * CDIM, 256);
    enc_map(enc, &tWpl, wpl, CDIM, CDIM, 1, CDIM, (long long)CDIM * CDIM, 256);
    CUtensorMap tQh, tQl, tKh;
    enc_map(enc, &tQh, qkh, CDIM, NROWS, BB, CDIM, sQK, 128);
    enc_map(enc, &tQl, qkl, CDIM, NROWS, BB, CDIM, sQK, 128);
    enc_map(enc, &tKh, kh,  CDIM, NROWS, BB, CDIM, sQK, 128);
    CUtensorMap tAh, tKTh;
    enc_map(enc, &tAh, ah, MROWS, NROWS, BB, MROWS, sAT, 128);
    enc_map(enc, &tKTh, kth, MROWS, CDIM, BB, MROWS, (long long)CDIM * MROWS, 128);
    CUtensorMap tO2h, tO2l;
    enc_map(enc, &tO2h, o2h, CDIM, TOTQ, 1, CDIM, (long long)TOTQ * CDIM, 128);
    enc_map(enc, &tO2l, o2l, CDIM, TOTQ, 1, CDIM, (long long)TOTQ * CDIM, 128);

    const int SMEM_P  = 1024 + 2 * (2 * TILEA + 2 * (256 * 64 * 2));  // 197632, occ1
    const int SMEM_QK = 1024 + 2 * (2 * TILEA + (128 * 64 * 2));      //  99328, occ2
    const int SMEM_AV = 1024 + 128 * 132 * 4;                         //  68608, occ2
    cudaFuncSetAttribute((const void*)tma_gemm<2,3,256,1>, cudaFuncAttributeMaxDynamicSharedMemorySize, SMEM_P);
    cudaFuncSetAttribute((const void*)tma_gemm<1,3,256,1>, cudaFuncAttributeMaxDynamicSharedMemorySize, SMEM_P);
    cudaFuncSetAttribute((const void*)tma_gemm<0,2,128,2>, cudaFuncAttributeMaxDynamicSharedMemorySize, SMEM_QK);
    cudaFuncSetAttribute((const void*)tma_gemm<6,1,128,2>, cudaFuncAttributeMaxDynamicSharedMemorySize, SMEM_AV);

    // 1) conversions
    split_f32<<<TOTQ * CDIM / 4 / 256, 256>>>(x, inh, inl, TOTQ * CDIM / 4);
    split_f32<<<TOTQ * CDIM / 4 / 256, 256>>>(support,
        inh + (size_t)TOTQ * CDIM, inl + (size_t)TOTQ * CDIM, TOTQ * CDIM / 4);
    split_f32<<<CDIM * CDIM / 4 / 256, 256>>>(Wv, wvh, wvl, CDIM * CDIM / 4);
    split_f32<<<CDIM * CDIM / 4 / 256, 256>>>(Wp, wph, wpl, CDIM * CDIM / 4);

    // 2) merged projection: [q;k] = [x;support] @ Wv^T  (split out)
    tma_gemm<2,3,256,1><<<dim3(2, 256, 1), 256, SMEM_P>>>(
        tInh, tInl, tWvh, tWvl, CDIM, CDIM, 1.0f, 0,
        nullptr, nullptr, qkh, qkl);

    // 3) kT[b][d][m] (hi only)
    transpose_hi<<<dim3(128, 16, BB), dim3(32, 8)>>>(kh, kth);

    // 4) attn = 0.125 * q @ k^T (2-term, occ-2, fp32 out, batched)
    tma_gemm<0,2,128,2><<<dim3(32, 32, BB), 256, SMEM_QK>>>(
        tQh, tQl, tKh, tKh, MROWS, CDIM, 0.125f, sAT,
        nullptr, attn, nullptr, nullptr);

    // 5) softmax + mask -> fp16 hi probs (normalized: no overflow possible)
    softmax_hi<<<TOTQ, 256>>>(attn, mask, ah);

    // 6) fused AV + bug-faithful permute -> split-fp16 o2 (1-term, occ-2)
    tma_gemm<6,1,128,2><<<dim3(4, 32, BB), 256, SMEM_AV>>>(
        tAh, tAh, tKTh, tKTh, CDIM, MROWS, 1.0f, sQK,
        nullptr, nullptr, o2h, o2l);

    // 7) out = o2 @ Wp^T + bp  (3-term)
    tma_gemm<1,3,256,1><<<dim3(2, 128, 1), 256, SMEM_P>>>(
        tO2h, tO2l, tWph, tWpl, CDIM, CDIM, 1.0f, 0,
        bp, out, nullptr, nullptr);
}

// round 13
// speedup vs baseline: 5.0355x; 1.0827x over previous
#include <cuda_runtime.h>
#include <cuda_fp16.h>
#include <cuda.h>

#define BB 4
#define NROWS 4096
#define MROWS 4096
#define CDIM 512
#define TOTQ (BB*NROWS)

// ---------------------------------------------------------------------------
// Device scratch
// ---------------------------------------------------------------------------
__device__ __align__(16) float g_attn[(size_t)BB * NROWS * MROWS];   // 268 MB
__device__ __align__(16) __half g_inh[(size_t)2*TOTQ*CDIM];    // x | support
__device__ __align__(16) __half g_inl[(size_t)2*TOTQ*CDIM];
__device__ __align__(16) __half g_wvh[CDIM*CDIM];
__device__ __align__(16) __half g_wph[CDIM*CDIM];
__device__ __align__(16) __half g_qkh[(size_t)2*TOTQ*CDIM];    // q | k
__device__ __align__(16) __half g_qkl[(size_t)2*TOTQ*CDIM];
__device__ __align__(16) __half g_kth[(size_t)TOTQ*CDIM];
__device__ __align__(16) __half g_ah[(size_t)BB*NROWS*MROWS];  // normalized probs (hi)
__device__ __align__(16) __half g_o2h[(size_t)TOTQ*CDIM], g_o2l[(size_t)TOTQ*CDIM];

// ---------------------------------------------------------------------------
// device helpers
// ---------------------------------------------------------------------------
static __device__ __forceinline__ unsigned smem_u32(const void* p) {
    unsigned a;
    asm("{ .reg .u64 t; cvta.to.shared.u64 t, %1; cvt.u32.u64 %0, t; }" : "=r"(a) : "l"(p));
    return a;
}
static __device__ __forceinline__ void ldm_x4(unsigned& r0, unsigned& r1,
                                              unsigned& r2, unsigned& r3, unsigned a) {
    asm volatile("ldmatrix.sync.aligned.m8n8.x4.shared.b16 {%0,%1,%2,%3}, [%4];"
                 : "=r"(r0), "=r"(r1), "=r"(r2), "=r"(r3) : "r"(a));
}
static __device__ __forceinline__ void mma16816(float* c, const unsigned* a,
                                                const unsigned* b) {
    asm volatile(
        "mma.sync.aligned.m16n8k16.row.col.f32.f16.f16.f32 "
        "{%0,%1,%2,%3}, {%4,%5,%6,%7}, {%8,%9}, {%0,%1,%2,%3};"
        : "+f"(c[0]), "+f"(c[1]), "+f"(c[2]), "+f"(c[3])
        : "r"(a[0]), "r"(a[1]), "r"(a[2]), "r"(a[3]), "r"(b[0]), "r"(b[1]));
}
static __device__ __forceinline__ unsigned hpack(float a, float b) {
    __half2 t = __floats2half2_rn(a, b);
    return *reinterpret_cast<unsigned*>(&t);
}
static __device__ __forceinline__ unsigned hsplitpack(float v) {
    __half h = __float2half(v);
    float lo = v - __half2float(h);
    __half l = __float2half(lo);
    return (unsigned)(*reinterpret_cast<unsigned short*>(&h))
         | ((unsigned)(*reinterpret_cast<unsigned short*>(&l)) << 16);
}
static __device__ __forceinline__ void mbar_wait(unsigned mbar, unsigned phase) {
    asm volatile(
        "{\n\t.reg .pred P1;\n\t"
        "LAB_WAIT_%=:\n\t"
        "mbarrier.try_wait.parity.acquire.cta.shared::cta.b64 P1, [%0], %1, 0x989680;\n\t"
        "@P1 bra.uni LAB_DONE_%=;\n\t"
        "bra.uni LAB_WAIT_%=;\n\t"
        "LAB_DONE_%=:\n\t}"
        :: "r"(mbar), "r"(phase) : "memory");
}
static __device__ __forceinline__ void tma3(unsigned dst, const CUtensorMap* m,
                                            int x, int y, int z, unsigned mb) {
    asm volatile(
        "cp.async.bulk.tensor.3d.shared::cluster.global.tile.mbarrier::complete_tx::bytes "
        "[%0], [%1, {%2, %3, %4}], [%5];"
        :: "r"(dst), "l"(m), "r"(x), "r"(y), "r"(z), "r"(mb) : "memory");
}

// ---------------------------------------------------------------------------
// Split-fp16 HMMA GEMM, TMA loads. CTA 128 x TN, K-slab 64, 2-stage buffer.
// C = A @ B^T; A,B [rows,K] row-major.
// NTERMS=3: ah*bh+al*bh+ah*bl ; 2: ah*bh+al*bh ; 1: ah*bh
// MODE 0: Cf = scale*acc (batched)
// MODE 1: Cf = acc + bias
// MODE 2: (Ch,Cl) = split(acc)
// MODE 6: bug-faithful permuted split write of scale*acc into (Ch,Cl)
// ---------------------------------------------------------------------------
#define TILEA 16384                 // 128x64 fp16

template<int MODE, int NTERMS, int TN, int MINB>
__global__ void __launch_bounds__(256, MINB) tma_gemm(
    const __grid_constant__ CUtensorMap mAh, const __grid_constant__ CUtensorMap mAl,
    const __grid_constant__ CUtensorMap mBh, const __grid_constant__ CUtensorMap mBl,
    int ldC, int Kdim, float scale, long long sC,
    const float* __restrict__ bias, float* __restrict__ Cf,
    __half* __restrict__ Ch, __half* __restrict__ Cl)
{
    constexpr unsigned TILEBN = TN * 64 * 2;
    constexpr unsigned NA = (NTERMS >= 2) ? 2u : 1u;
    constexpr unsigned NB = (NTERMS == 3) ? 2u : 1u;
    constexpr unsigned OFF_BH = NA * TILEA;
    constexpr unsigned STGX = NA * TILEA + NB * TILEBN;
    constexpr int NBP = TN / 64;
    constexpr int NBW = TN / 32;

    extern __shared__ char smem[];
    __shared__ __align__(16) unsigned long long mbar[2];
    const unsigned sa = (smem_u32(smem) + 1023) & ~1023u;
    const unsigned mbq = smem_u32(mbar);
    const int tid = threadIdx.x;
    const int wid = tid >> 5;
    const int lane = tid & 31;
    const int m0 = blockIdx.y * 128;
    const int n0 = blockIdx.x * TN;
    const int bz = blockIdx.z;

    const int m_w = (wid >> 2) * 64;
    const int n_w = (wid & 3) * (TN / 4);

    if (tid == 0) {
        asm volatile("mbarrier.init.shared.b64 [%0], 1;" :: "r"(mbq) : "memory");
        asm volatile("mbarrier.init.shared.b64 [%0], 1;" :: "r"(mbq + 8) : "memory");
    }
    __syncthreads();

    const int nslab = Kdim / 64;
    auto issue = [&](int buf, int k0) {
        if (tid == 0) {
            const unsigned mb = mbq + buf * 8;
            asm volatile("mbarrier.arrive.expect_tx.shared.b64 _, [%0], %1;"
                         :: "r"(mb), "r"(STGX) : "memory");
            const unsigned base = sa + buf * STGX;
            tma3(base, &mAh, k0, m0, bz, mb);
            if (NTERMS >= 2) tma3(base + TILEA, &mAl, k0, m0, bz, mb);
            tma3(base + OFF_BH, &mBh, k0, n0, bz, mb);
            if (NTERMS == 3) tma3(base + OFF_BH + TILEBN, &mBl, k0, n0, bz, mb);
        }
    };

    issue(0, 0);
    if (nslab > 1) issue(1, 64);

    float acc[4][NBW][4];
#pragma unroll
    for (int i = 0; i < 4; i++)
#pragma unroll
        for (int j = 0; j < NBW; j++)
#pragma unroll
            for (int p = 0; p < 4; p++) acc[i][j][p] = 0.f;

    const unsigned aoffL = (unsigned)(m_w + (lane & 15)) * 128 + ((lane >> 4) * 16);
    const unsigned boffL = (unsigned)(n_w + (lane & 7) + ((lane >> 4) << 3)) * 128
                         + ((lane & 8) ? 16 : 0);
    const unsigned sxor = (unsigned)(lane & 7) << 4;

    int phase[2] = {0, 0};
    for (int s = 0; s < nslab; s++) {
        const int buf = s & 1;
        mbar_wait(mbq + buf * 8, (unsigned)phase[buf]);
        phase[buf] ^= 1;
        const unsigned st = sa + buf * STGX;
#pragma unroll
        for (int kk = 0; kk < 4; kk++) {
            unsigned ah[4][4], al[4][4];
#pragma unroll
            for (int mb = 0; mb < 4; mb++) {
                const unsigned a = st + ((aoffL + mb * 2048 + kk * 32) ^ sxor);
                ldm_x4(ah[mb][0], ah[mb][1], ah[mb][2], ah[mb][3], a);
                if (NTERMS >= 2)
                    ldm_x4(al[mb][0], al[mb][1], al[mb][2], al[mb][3], a + TILEA);
            }
#pragma unroll
            for (int nbp = 0; nbp < NBP; nbp++) {
                unsigned bh[2][2], bl[2][2];
                const unsigned b = st + OFF_BH + ((boffL + nbp * 2048 + kk * 32) ^ sxor);
                ldm_x4(bh[0][0], bh[0][1], bh[1][0], bh[1][1], b);
                if (NTERMS == 3)
                    ldm_x4(bl[0][0], bl[0][1], bl[1][0], bl[1][1], b + TILEBN);
#pragma unroll
                for (int mb = 0; mb < 4; mb++)
#pragma unroll
                    for (int j = 0; j < 2; j++) {
                        float* c = acc[mb][2 * nbp + j];
                        mma16816(c, ah[mb], bh[j]);
                        if (NTERMS >= 2) mma16816(c, al[mb], bh[j]);
                        if (NTERMS == 3) mma16816(c, ah[mb], bl[j]);
                    }
            }
        }
        __syncthreads();
        if (s + 2 < nslab) issue(buf, (s + 2) * 64);
    }

    // ======================= epilogues =======================
    if (MODE == 0 || MODE == 1 || MODE == 2) {
#pragma unroll
        for (int mb = 0; mb < 4; mb++)
#pragma unroll
            for (int p = 0; p < 2; p++) {
                const long long row = m0 + m_w + mb * 16 + (lane >> 2) + p * 8;
#pragma unroll
                for (int nb = 0; nb < NBW; nb++) {
                    const int col = n0 + n_w + nb * 8 + (lane & 3) * 2;
                    float v0 = acc[mb][nb][2 * p];
                    float v1 = acc[mb][nb][2 * p + 1];
                    if (MODE == 0) {
                        float2 o = make_float2(v0 * scale, v1 * scale);
                        *(float2*)&Cf[(long long)bz * sC + row * ldC + col] = o;
                    } else if (MODE == 1) {
                        float2 o = make_float2(v0 + bias[col], v1 + bias[col + 1]);
                        *(float2*)&Cf[row * ldC + col] = o;
                    } else {
                        __half h0 = __float2half(v0);
                        __half h1 = __float2half(v1);
                        *(unsigned*)&Ch[row * (long long)ldC + col] =
                            hpack(__half2float(h0), __half2float(h1));
                        *(unsigned*)&Cl[row * (long long)ldC + col] =
                            hpack(v0 - __half2float(h0), v1 - __half2float(h1));
                    }
                }
            }
    }

    if (MODE == 6) {
        // scale, in-CTA transpose, bug-faithful permuted split-fp16 write
        char* smal = smem + (int)(sa - smem_u32(smem));
        unsigned* S = (unsigned*)smal;
#pragma unroll
        for (int mb = 0; mb < 4; mb++)
#pragma unroll
            for (int p = 0; p < 2; p++) {
                const int row = m0 + m_w + mb * 16 + (lane >> 2) + p * 8;
                const int jl = row - m0;
#pragma unroll
                for (int nb = 0; nb < NBW; nb++) {
                    const int col = n0 + n_w + nb * 8 + (lane & 3) * 2;
                    float v0 = acc[mb][nb][2 * p] * scale;
                    float v1 = acc[mb][nb][2 * p + 1] * scale;
                    S[(col - n0) * 132 + jl] = hsplitpack(v0);
                    S[(col + 1 - n0) * 132 + jl] = hsplitpack(v1);
                }
            }
        __syncthreads();
        const int rr = m0 >> 9;
        const int j0 = m0 & 511;
        const long long ob = (long long)bz * ((long long)NROWS * CDIM) + j0;
#pragma unroll 4
        for (int rp = wid; rp < 256; rp += 8) {
            const int dl = rp >> 1;
            const int pl = rp & 1;
            uint4 q = *(uint4*)&S[dl * 132 + 4 * lane];
            unsigned a0, a1;
            if (pl == 0) {
                a0 = (q.x & 0xFFFFu) | (q.y << 16);
                a1 = (q.z & 0xFFFFu) | (q.w << 16);
            } else {
                a0 = (q.x >> 16) | (q.y & 0xFFFF0000u);
                a1 = (q.z >> 16) | (q.w & 0xFFFF0000u);
            }
            __half* dst = (pl ? Cl : Ch) + ob
                        + (long long)((((n0 + dl) << 3) + rr)) * 512;
            *(uint2*)(dst + 4 * lane) = make_uint2(a0, a1);
        }
    }
}

// ---------------------------------------------------------------------------
// Merged conversion: x, support -> (inh,inl) stacked ; Wv,Wp -> hi planes only
// ---------------------------------------------------------------------------
__global__ void __launch_bounds__(256) split_all(
    const float* __restrict__ x, const float* __restrict__ sup,
    const float* __restrict__ Wv, const float* __restrict__ Wp,
    __half* __restrict__ inh, __half* __restrict__ inl,
    __half* __restrict__ wvh, __half* __restrict__ wph)
{
    const int N1 = TOTQ * CDIM / 4;          // per input tensor (float4 units)
    const int NW = CDIM * CDIM / 4;
    int i = blockIdx.x * 256 + threadIdx.x;
    if (i < 2 * N1) {
        const float* src = (i < N1) ? x : sup;
        int j = (i < N1) ? i : i - N1;
        float4 v = ((const float4*)src)[j];
        __half h0 = __float2half(v.x), h1 = __float2half(v.y);
        __half h2 = __float2half(v.z), h3 = __float2half(v.w);
        uint2 ph, pl;
        ph.x = hpack(__half2float(h0), __half2float(h1));
        ph.y = hpack(__half2float(h2), __half2float(h3));
        pl.x = hpack(v.x - __half2float(h0), v.y - __half2float(h1));
        pl.y = hpack(v.z - __half2float(h2), v.w - __half2float(h3));
        ((uint2*)inh)[i] = ph;
        ((uint2*)inl)[i] = pl;
    } else {
        int j = i - 2 * N1;
        if (j >= 2 * NW) return;
        const float* src = (j < NW) ? Wv : Wp;
        __half* dst = (j < NW) ? wvh : wph;
        int k = (j < NW) ? j : j - NW;
        float4 v = ((const float4*)src)[k];
        uint2 ph;
        ph.x = hpack(v.x, v.y);
        ph.y = hpack(v.z, v.w);
        ((uint2*)dst)[k] = ph;
    }
}

// ---------------------------------------------------------------------------
// kT (hi only): kth[b][d][m] = kh[b*4096+m][d]
// ---------------------------------------------------------------------------
__global__ void __launch_bounds__(256) transpose_hi(
    const __half* __restrict__ kh, __half* __restrict__ kth)
{
    __shared__ __half th[32][33];
    const int b = blockIdx.z;
    const int mm0 = blockIdx.x * 32;
    const int d0 = blockIdx.y * 32;
    const int tx = threadIdx.x, ty = threadIdx.y;
    const long long sbase = (long long)(b * 4096 + mm0) * CDIM + d0;
#pragma unroll
    for (int hh = 0; hh < 32; hh += 8)
        th[ty + hh][tx] = kh[sbase + (long long)(ty + hh) * CDIM + tx];
    __syncthreads();
    const long long dbase = (long long)b * CDIM * MROWS + (long long)d0 * MROWS + mm0;
#pragma unroll
    for (int hh = 0; hh < 32; hh += 8)
        kth[dbase + (long long)(ty + hh) * MROWS + tx] = th[tx][ty + hh];
}

// ---------------------------------------------------------------------------
// Row softmax (4096) + post-softmax mask; fp16 hi-only probability output.
// ---------------------------------------------------------------------------
__global__ void __launch_bounds__(256) softmax_hi(
    const float* __restrict__ attn, const int* __restrict__ mask,
    __half* __restrict__ ah)
{
    __shared__ float rmax[8];
    __shared__ float rsum[8];
    const float* p = attn + (long long)blockIdx.x * MROWS;
    const int t = threadIdx.x;

    float4 v[4];
    float mx = -1e30f;
#pragma unroll
    for (int u = 0; u < 4; u++) {
        v[u] = ((const float4*)p)[u * 256 + t];
        mx = fmaxf(mx, fmaxf(fmaxf(v[u].x, v[u].y), fmaxf(v[u].z, v[u].w)));
    }
#pragma unroll
    for (int o = 16; o > 0; o >>= 1) mx = fmaxf(mx, __shfl_xor_sync(0xffffffffu, mx, o));
    if ((t & 31) == 0) rmax[t >> 5] = mx;
    __syncthreads();
    mx = fmaxf(fmaxf(fmaxf(rmax[0], rmax[1]), fmaxf(rmax[2], rmax[3])),
               fmaxf(fmaxf(rmax[4], rmax[5]), fmaxf(rmax[6], rmax[7])));

    float s = 0.f;
#pragma unroll
    for (int u = 0; u < 4; u++) {
        v[u].x = expf(v[u].x - mx); v[u].y = expf(v[u].y - mx);
        v[u].z = expf(v[u].z - mx); v[u].w = expf(v[u].w - mx);
        s += v[u].x + v[u].y + v[u].z + v[u].w;
    }
#pragma unroll
    for (int o = 16; o > 0; o >>= 1) s += __shfl_xor_sync(0xffffffffu, s, o);
    if ((t & 31) == 0) rsum[t >> 5] = s;
    __syncthreads();
    s = (rsum[0] + rsum[1]) + (rsum[2] + rsum[3]) + (rsum[4] + rsum[5]) + (rsum[6] + rsum[7]);
    const float inv = 1.0f / s;

    __half* bh = ah + (long long)blockIdx.x * MROWS;
#pragma unroll
    for (int u = 0; u < 4; u++) {
        const int i4 = u * 256 + t;
        const int4 mq = ((const int4*)mask)[i4];
        float o0 = v[u].x * inv * (mq.x != 0 ? 1.f : 0.f);
        float o1 = v[u].y * inv * (mq.y != 0 ? 1.f : 0.f);
        float o2 = v[u].z * inv * (mq.z != 0 ? 1.f : 0.f);
        float o3 = v[u].w * inv * (mq.w != 0 ? 1.f : 0.f);
        uint2 ph;
        ph.x = hpack(o0, o1);
        ph.y = hpack(o2, o3);
        ((uint2*)bh)[i4] = ph;
    }
}

// ---------------------------------------------------------------------------
// Host: tensormap encode via driver entry point
// ---------------------------------------------------------------------------
typedef CUresult (*PFN_tmapEnc)(
    CUtensorMap*, CUtensorMapDataType, cuuint32_t, void*,
    const cuuint64_t*, const cuuint64_t*, const cuuint32_t*, const cuuint32_t*,
    CUtensorMapInterleave, CUtensorMapSwizzle, CUtensorMapL2promotion,
    CUtensorMapFloatOOBfill);

static void enc_map(PFN_tmapEnc fn, CUtensorMap* m, const void* ptr,
                    unsigned long long K, unsigned long long rows,
                    unsigned long long batches, unsigned long long ldElems,
                    unsigned long long bStrideElems, unsigned boxRows)
{
    cuuint64_t dims[3] = {K, rows, batches};
    cuuint64_t strides[2] = {ldElems * 2ull, bStrideElems * 2ull};
    cuuint32_t box[3] = {64, boxRows, 1};
    cuuint32_t estr[3] = {1, 1, 1};
    fn(m, CU_TENSOR_MAP_DATA_TYPE_FLOAT16, 3, (void*)ptr,
       dims, strides, box, estr,
       CU_TENSOR_MAP_INTERLEAVE_NONE, CU_TENSOR_MAP_SWIZZLE_128B,
       CU_TENSOR_MAP_L2_PROMOTION_L2_128B, CU_TENSOR_MAP_FLOAT_OOB_FILL_NONE);
}

extern "C" void kernel_launch(void* const* d_in, const int* in_sizes, int n_in,
                              void* d_out, int out_size)
{
    const float* x       = (const float*)d_in[0];
    const float* support = (const float*)d_in[1];
    const int*   mask    = (const int*)  d_in[2];
    const float* Wv      = (const float*)d_in[3];
    const float* Wp      = (const float*)d_in[4];
    const float* bp      = (const float*)d_in[5];
    float* out = (float*)d_out;

    float* attn;
    __half *inh, *inl, *wvh, *wph;
    __half *qkh, *qkl, *kth, *ah, *o2h, *o2l;
    cudaGetSymbolAddress((void**)&attn, g_attn);
    cudaGetSymbolAddress((void**)&inh, g_inh); cudaGetSymbolAddress((void**)&inl, g_inl);
    cudaGetSymbolAddress((void**)&wvh, g_wvh);
    cudaGetSymbolAddress((void**)&wph, g_wph);
    cudaGetSymbolAddress((void**)&qkh, g_qkh); cudaGetSymbolAddress((void**)&qkl, g_qkl);
    cudaGetSymbolAddress((void**)&kth, g_kth);
    cudaGetSymbolAddress((void**)&ah, g_ah);
    cudaGetSymbolAddress((void**)&o2h, g_o2h); cudaGetSymbolAddress((void**)&o2l, g_o2l);

    __half* kh = qkh + (size_t)TOTQ * CDIM;

    void* sym = nullptr;
    cudaDriverEntryPointQueryResult qres;
    cudaGetDriverEntryPointByVersion("cuTensorMapEncodeTiled", &sym, 12000,
                                     cudaEnableDefault, &qres);
    PFN_tmapEnc enc = (PFN_tmapEnc)sym;

    const long long sQK = (long long)NROWS * CDIM;
    const long long sAT = (long long)NROWS * MROWS;

    CUtensorMap tInh, tInl, tWvh, tWph;
    enc_map(enc, &tInh, inh, CDIM, 2 * TOTQ, 1, CDIM, (long long)2 * TOTQ * CDIM, 128);
    enc_map(enc, &tInl, inl, CDIM, 2 * TOTQ, 1, CDIM, (long long)2 * TOTQ * CDIM, 128);
    enc_map(enc, &tWvh, wvh, CDIM, CDIM, 1, CDIM, (long long)CDIM * CDIM, 256);
    enc_map(enc, &tWph, wph, CDIM, CDIM, 1, CDIM, (long long)CDIM * CDIM, 256);
    CUtensorMap tQh, tQl, tKh;
    enc_map(enc, &tQh, qkh, CDIM, NROWS, BB, CDIM, sQK, 128);
    enc_map(enc, &tQl, qkl, CDIM, NROWS, BB, CDIM, sQK, 128);
    enc_map(enc, &tKh, kh,  CDIM, NROWS, BB, CDIM, sQK, 128);
    CUtensorMap tAh, tKTh;
    enc_map(enc, &tAh, ah, MROWS, NROWS, BB, MROWS, sAT, 128);
    enc_map(enc, &tKTh, kth, MROWS, CDIM, BB, MROWS, (long long)CDIM * MROWS, 128);
    CUtensorMap tO2h, tO2l;
    enc_map(enc, &tO2h, o2h, CDIM, TOTQ, 1, CDIM, (long long)TOTQ * CDIM, 128);
    enc_map(enc, &tO2l, o2l, CDIM, TOTQ, 1, CDIM, (long long)TOTQ * CDIM, 128);

    // smem: proj/outproj now 2-term TN=256: stage = 2*16K + 32K = 64K
    const int SMEM_P  = 1024 + 2 * (2 * TILEA + (256 * 64 * 2));      // 132096, occ1
    const int SMEM_QK = 1024 + 2 * (2 * TILEA + (128 * 64 * 2));      //  99328, occ2
    const int SMEM_AV = 1024 + 128 * 132 * 4;                         //  68608, occ2
    cudaFuncSetAttribute((const void*)tma_gemm<2,2,256,1>, cudaFuncAttributeMaxDynamicSharedMemorySize, SMEM_P);
    cudaFuncSetAttribute((const void*)tma_gemm<1,2,256,1>, cudaFuncAttributeMaxDynamicSharedMemorySize, SMEM_P);
    cudaFuncSetAttribute((const void*)tma_gemm<0,2,128,2>, cudaFuncAttributeMaxDynamicSharedMemorySize, SMEM_QK);
    cudaFuncSetAttribute((const void*)tma_gemm<6,1,128,2>, cudaFuncAttributeMaxDynamicSharedMemorySize, SMEM_AV);

    // 1) merged conversions (x, support -> split; Wv, Wp -> hi only)
    {
        const int total = 2 * (TOTQ * CDIM / 4) + 2 * (CDIM * CDIM / 4);
        split_all<<<(total + 255) / 256, 256>>>(x, support, Wv, Wp,
                                                inh, inl, wvh, wph);
    }

    // 2) merged projection: [q;k] = [x;support] @ Wv-hi^T  (2-term, split out)
    tma_gemm<2,2,256,1><<<dim3(2, 256, 1), 256, SMEM_P>>>(
        tInh, tInl, tWvh, tWvh, CDIM, CDIM, 1.0f, 0,
        nullptr, nullptr, qkh, qkl);

    // 3) kT[b][d][m] (hi only)
    transpose_hi<<<dim3(128, 16, BB), dim3(32, 8)>>>(kh, kth);

    // 4) attn = 0.125 * q @ k^T (2-term, occ-2, fp32 out, batched)
    tma_gemm<0,2,128,2><<<dim3(32, 32, BB), 256, SMEM_QK>>>(
        tQh, tQl, tKh, tKh, MROWS, CDIM, 0.125f, sAT,
        nullptr, attn, nullptr, nullptr);

    // 5) softmax + mask -> fp16 hi probs
    softmax_hi<<<TOTQ, 256>>>(attn, mask, ah);

    // 6) fused AV + bug-faithful permute -> split-fp16 o2 (1-term, occ-2)
    tma_gemm<6,1,128,2><<<dim3(4, 32, BB), 256, SMEM_AV>>>(
        tAh, tAh, tKTh, tKTh, CDIM, MROWS, 1.0f, sQK,
        nullptr, nullptr, o2h, o2l);

    // 7) out = o2 @ Wp-hi^T + bp  (2-term)
    tma_gemm<1,2,256,1><<<dim3(2, 128, 1), 256, SMEM_P>>>(
        tO2h, tO2l, tWph, tWph, CDIM, CDIM, 1.0f, 0,
        bp, out, nullptr, nullptr);
}

// round 14
// speedup vs baseline: 5.4080x; 1.0740x over previous
#include <cuda_runtime.h>
#include <cuda_fp16.h>
#include <cuda.h>

#define BB 4
#define NROWS 4096
#define MROWS 4096
#define CDIM 512
#define TOTQ (BB*NROWS)

// ---------------------------------------------------------------------------
// Device scratch
// ---------------------------------------------------------------------------
__device__ __align__(16) float g_rowsum[TOTQ];                 // 64 KB
__device__ __align__(16) __half g_inh[(size_t)2*TOTQ*CDIM];    // x | support
__device__ __align__(16) __half g_inl[(size_t)2*TOTQ*CDIM];
__device__ __align__(16) __half g_wvh[CDIM*CDIM];
__device__ __align__(16) __half g_wph[CDIM*CDIM];
__device__ __align__(16) __half g_qkh[(size_t)2*TOTQ*CDIM];    // q | k
__device__ __align__(16) __half g_qkl[(size_t)2*TOTQ*CDIM];
__device__ __align__(16) __half g_kth[(size_t)TOTQ*CDIM];
__device__ __align__(16) __half g_ah[(size_t)BB*NROWS*MROWS];  // scaled exp (hi), masked
__device__ __align__(16) __half g_o2h[(size_t)TOTQ*CDIM], g_o2l[(size_t)TOTQ*CDIM];

// ---------------------------------------------------------------------------
// device helpers
// ---------------------------------------------------------------------------
static __device__ __forceinline__ unsigned smem_u32(const void* p) {
    unsigned a;
    asm("{ .reg .u64 t; cvta.to.shared.u64 t, %1; cvt.u32.u64 %0, t; }" : "=r"(a) : "l"(p));
    return a;
}
static __device__ __forceinline__ void ldm_x4(unsigned& r0, unsigned& r1,
                                              unsigned& r2, unsigned& r3, unsigned a) {
    asm volatile("ldmatrix.sync.aligned.m8n8.x4.shared.b16 {%0,%1,%2,%3}, [%4];"
                 : "=r"(r0), "=r"(r1), "=r"(r2), "=r"(r3) : "r"(a));
}
static __device__ __forceinline__ void mma16816(float* c, const unsigned* a,
                                                const unsigned* b) {
    asm volatile(
        "mma.sync.aligned.m16n8k16.row.col.f32.f16.f16.f32 "
        "{%0,%1,%2,%3}, {%4,%5,%6,%7}, {%8,%9}, {%0,%1,%2,%3};"
        : "+f"(c[0]), "+f"(c[1]), "+f"(c[2]), "+f"(c[3])
        : "r"(a[0]), "r"(a[1]), "r"(a[2]), "r"(a[3]), "r"(b[0]), "r"(b[1]));
}
static __device__ __forceinline__ unsigned hpack(float a, float b) {
    __half2 t = __floats2half2_rn(a, b);
    return *reinterpret_cast<unsigned*>(&t);
}
static __device__ __forceinline__ unsigned hsplitpack(float v) {
    __half h = __float2half(v);
    float lo = v - __half2float(h);
    __half l = __float2half(lo);
    return (unsigned)(*reinterpret_cast<unsigned short*>(&h))
         | ((unsigned)(*reinterpret_cast<unsigned short*>(&l)) << 16);
}
static __device__ __forceinline__ void mbar_wait(unsigned mbar, unsigned phase) {
    asm volatile(
        "{\n\t.reg .pred P1;\n\t"
        "LAB_WAIT_%=:\n\t"
        "mbarrier.try_wait.parity.acquire.cta.shared::cta.b64 P1, [%0], %1, 0x989680;\n\t"
        "@P1 bra.uni LAB_DONE_%=;\n\t"
        "bra.uni LAB_WAIT_%=;\n\t"
        "LAB_DONE_%=:\n\t}"
        :: "r"(mbar), "r"(phase) : "memory");
}
static __device__ __forceinline__ void tma3(unsigned dst, const CUtensorMap* m,
                                            int x, int y, int z, unsigned mb) {
    asm volatile(
        "cp.async.bulk.tensor.3d.shared::cluster.global.tile.mbarrier::complete_tx::bytes "
        "[%0], [%1, {%2, %3, %4}], [%5];"
        :: "r"(dst), "l"(m), "r"(x), "r"(y), "r"(z), "r"(mb) : "memory");
}

// ---------------------------------------------------------------------------
// Split-fp16 HMMA GEMM, TMA loads. CTA 128 x TN, K-slab 64, 2-stage buffer.
// C = A @ B^T; A,B [rows,K] row-major.
// NTERMS=3: ah*bh+al*bh+ah*bl ; 2: ah*bh+al*bh ; 1: ah*bh
// MODE 1: Cf = acc + bias
// MODE 2: (Ch,Cl) = split(acc)
// MODE 5: E = exp(scale*acc)*2^-21 clamped; Ch = fp16(E)*mask;
//         rowsum(Cf) += fp16-rounded E (pre-mask, atomic)
// MODE 6: bug-faithful permuted split write of acc/rowsum(bias) into (Ch,Cl)
// ---------------------------------------------------------------------------
#define TILEA 16384                 // 128x64 fp16

template<int MODE, int NTERMS, int TN, int MINB>
__global__ void __launch_bounds__(256, MINB) tma_gemm(
    const __grid_constant__ CUtensorMap mAh, const __grid_constant__ CUtensorMap mAl,
    const __grid_constant__ CUtensorMap mBh, const __grid_constant__ CUtensorMap mBl,
    int ldC, int Kdim, float scale, long long sC,
    const float* __restrict__ bias, const int* __restrict__ maskp,
    float* __restrict__ Cf,
    __half* __restrict__ Ch, __half* __restrict__ Cl)
{
    constexpr unsigned TILEBN = TN * 64 * 2;
    constexpr unsigned NA = (NTERMS >= 2) ? 2u : 1u;
    constexpr unsigned NB = (NTERMS == 3) ? 2u : 1u;
    constexpr unsigned OFF_BH = NA * TILEA;
    constexpr unsigned STGX = NA * TILEA + NB * TILEBN;
    constexpr int NBP = TN / 64;
    constexpr int NBW = TN / 32;

    extern __shared__ char smem[];
    __shared__ __align__(16) unsigned long long mbar[2];
    const unsigned sa = (smem_u32(smem) + 1023) & ~1023u;
    const unsigned mbq = smem_u32(mbar);
    const int tid = threadIdx.x;
    const int wid = tid >> 5;
    const int lane = tid & 31;
    const int m0 = blockIdx.y * 128;
    const int n0 = blockIdx.x * TN;
    const int bz = blockIdx.z;

    const int m_w = (wid >> 2) * 64;
    const int n_w = (wid & 3) * (TN / 4);

    if (tid == 0) {
        asm volatile("mbarrier.init.shared.b64 [%0], 1;" :: "r"(mbq) : "memory");
        asm volatile("mbarrier.init.shared.b64 [%0], 1;" :: "r"(mbq + 8) : "memory");
    }
    __syncthreads();

    const int nslab = Kdim / 64;
    auto issue = [&](int buf, int k0) {
        if (tid == 0) {
            const unsigned mb = mbq + buf * 8;
            asm volatile("mbarrier.arrive.expect_tx.shared.b64 _, [%0], %1;"
                         :: "r"(mb), "r"(STGX) : "memory");
            const unsigned base = sa + buf * STGX;
            tma3(base, &mAh, k0, m0, bz, mb);
            if (NTERMS >= 2) tma3(base + TILEA, &mAl, k0, m0, bz, mb);
            tma3(base + OFF_BH, &mBh, k0, n0, bz, mb);
            if (NTERMS == 3) tma3(base + OFF_BH + TILEBN, &mBl, k0, n0, bz, mb);
        }
    };

    issue(0, 0);
    if (nslab > 1) issue(1, 64);

    float acc[4][NBW][4];
#pragma unroll
    for (int i = 0; i < 4; i++)
#pragma unroll
        for (int j = 0; j < NBW; j++)
#pragma unroll
            for (int p = 0; p < 4; p++) acc[i][j][p] = 0.f;

    const unsigned aoffL = (unsigned)(m_w + (lane & 15)) * 128 + ((lane >> 4) * 16);
    const unsigned boffL = (unsigned)(n_w + (lane & 7) + ((lane >> 4) << 3)) * 128
                         + ((lane & 8) ? 16 : 0);
    const unsigned sxor = (unsigned)(lane & 7) << 4;

    int phase[2] = {0, 0};
    for (int s = 0; s < nslab; s++) {
        const int buf = s & 1;
        mbar_wait(mbq + buf * 8, (unsigned)phase[buf]);
        phase[buf] ^= 1;
        const unsigned st = sa + buf * STGX;
#pragma unroll
        for (int kk = 0; kk < 4; kk++) {
            unsigned ah[4][4], al[4][4];
#pragma unroll
            for (int mb = 0; mb < 4; mb++) {
                const unsigned a = st + ((aoffL + mb * 2048 + kk * 32) ^ sxor);
                ldm_x4(ah[mb][0], ah[mb][1], ah[mb][2], ah[mb][3], a);
                if (NTERMS >= 2)
                    ldm_x4(al[mb][0], al[mb][1], al[mb][2], al[mb][3], a + TILEA);
            }
#pragma unroll
            for (int nbp = 0; nbp < NBP; nbp++) {
                unsigned bh[2][2], bl[2][2];
                const unsigned b = st + OFF_BH + ((boffL + nbp * 2048 + kk * 32) ^ sxor);
                ldm_x4(bh[0][0], bh[0][1], bh[1][0], bh[1][1], b);
                if (NTERMS == 3)
                    ldm_x4(bl[0][0], bl[0][1], bl[1][0], bl[1][1], b + TILEBN);
#pragma unroll
                for (int mb = 0; mb < 4; mb++)
#pragma unroll
                    for (int j = 0; j < 2; j++) {
                        float* c = acc[mb][2 * nbp + j];
                        mma16816(c, ah[mb], bh[j]);
                        if (NTERMS >= 2) mma16816(c, al[mb], bh[j]);
                        if (NTERMS == 3) mma16816(c, ah[mb], bl[j]);
                    }
            }
        }
        __syncthreads();
        if (s + 2 < nslab) issue(buf, (s + 2) * 64);
    }

    // ======================= epilogues =======================
    if (MODE == 1 || MODE == 2) {
#pragma unroll
        for (int mb = 0; mb < 4; mb++)
#pragma unroll
            for (int p = 0; p < 2; p++) {
                const long long row = m0 + m_w + mb * 16 + (lane >> 2) + p * 8;
#pragma unroll
                for (int nb = 0; nb < NBW; nb++) {
                    const int col = n0 + n_w + nb * 8 + (lane & 3) * 2;
                    float v0 = acc[mb][nb][2 * p];
                    float v1 = acc[mb][nb][2 * p + 1];
                    if (MODE == 1) {
                        float2 o = make_float2(v0 + bias[col], v1 + bias[col + 1]);
                        *(float2*)&Cf[row * ldC + col] = o;
                    } else {
                        __half h0 = __float2half(v0);
                        __half h1 = __float2half(v1);
                        *(unsigned*)&Ch[row * (long long)ldC + col] =
                            hpack(__half2float(h0), __half2float(h1));
                        *(unsigned*)&Cl[row * (long long)ldC + col] =
                            hpack(v0 - __half2float(h0), v1 - __half2float(h1));
                    }
                }
            }
    }

    if (MODE == 5) {
        // exp (fp32, no overflow) -> scale 2^-21 + clamp -> fp16-round ->
        // rowsum of rounded values (pre-mask, atomic) -> masked fp16 store
        const float SC = 4.76837158203125e-7f;   // 2^-21
        float rs[4][2];
#pragma unroll
        for (int mb = 0; mb < 4; mb++)
#pragma unroll
            for (int p = 0; p < 2; p++) rs[mb][p] = 0.f;
#pragma unroll
        for (int mb = 0; mb < 4; mb++)
#pragma unroll
            for (int nb = 0; nb < NBW; nb++)
#pragma unroll
                for (int p = 0; p < 2; p++) {
                    float e0 = fminf(__expf(acc[mb][nb][2 * p] * scale) * SC, 60000.f);
                    float e1 = fminf(__expf(acc[mb][nb][2 * p + 1] * scale) * SC, 60000.f);
                    // round to fp16 for self-consistent normalization
                    float r0 = __half2float(__float2half(e0));
                    float r1 = __half2float(__float2half(e1));
                    acc[mb][nb][2 * p] = r0;
                    acc[mb][nb][2 * p + 1] = r1;
                    rs[mb][p] += r0 + r1;
                }
#pragma unroll
        for (int mb = 0; mb < 4; mb++)
#pragma unroll
            for (int p = 0; p < 2; p++) {
                rs[mb][p] += __shfl_xor_sync(0xffffffffu, rs[mb][p], 1);
                rs[mb][p] += __shfl_xor_sync(0xffffffffu, rs[mb][p], 2);
            }
        if ((lane & 3) == 0) {
#pragma unroll
            for (int mb = 0; mb < 4; mb++)
#pragma unroll
                for (int p = 0; p < 2; p++) {
                    const int row = m0 + m_w + mb * 16 + (lane >> 2) + p * 8;
                    atomicAdd(&Cf[bz * NROWS + row], rs[mb][p]);
                }
        }
#pragma unroll
        for (int mb = 0; mb < 4; mb++)
#pragma unroll
            for (int p = 0; p < 2; p++) {
                const long long row = m0 + m_w + mb * 16 + (lane >> 2) + p * 8;
#pragma unroll
                for (int nb = 0; nb < NBW; nb++) {
                    const int col = n0 + n_w + nb * 8 + (lane & 3) * 2;
                    int2 mk = *(const int2*)&maskp[col];
                    float s0 = acc[mb][nb][2 * p] * (mk.x != 0 ? 1.f : 0.f);
                    float s1 = acc[mb][nb][2 * p + 1] * (mk.y != 0 ? 1.f : 0.f);
                    *(unsigned*)&Ch[(long long)bz * sC + row * (long long)ldC + col] =
                        hpack(s0, s1);
                }
            }
    }

    if (MODE == 6) {
        // per-row normalize by rowsum (bias), in-CTA transpose,
        // bug-faithful permuted split-fp16 write
        char* smal = smem + (int)(sa - smem_u32(smem));
        unsigned* S = (unsigned*)smal;
#pragma unroll
        for (int mb = 0; mb < 4; mb++)
#pragma unroll
            for (int p = 0; p < 2; p++) {
                const int row = m0 + m_w + mb * 16 + (lane >> 2) + p * 8;
                const float sc = 1.0f / bias[bz * NROWS + row];
                const int jl = row - m0;
#pragma unroll
                for (int nb = 0; nb < NBW; nb++) {
                    const int col = n0 + n_w + nb * 8 + (lane & 3) * 2;
                    float v0 = acc[mb][nb][2 * p] * sc;
                    float v1 = acc[mb][nb][2 * p + 1] * sc;
                    S[(col - n0) * 132 + jl] = hsplitpack(v0);
                    S[(col + 1 - n0) * 132 + jl] = hsplitpack(v1);
                }
            }
        __syncthreads();
        const int rr = m0 >> 9;
        const int j0 = m0 & 511;
        const long long ob = (long long)bz * ((long long)NROWS * CDIM) + j0;
#pragma unroll 4
        for (int rp = wid; rp < 256; rp += 8) {
            const int dl = rp >> 1;
            const int pl = rp & 1;
            uint4 q = *(uint4*)&S[dl * 132 + 4 * lane];
            unsigned a0, a1;
            if (pl == 0) {
                a0 = (q.x & 0xFFFFu) | (q.y << 16);
                a1 = (q.z & 0xFFFFu) | (q.w << 16);
            } else {
                a0 = (q.x >> 16) | (q.y & 0xFFFF0000u);
                a1 = (q.z >> 16) | (q.w & 0xFFFF0000u);
            }
            __half* dst = (pl ? Cl : Ch) + ob
                        + (long long)((((n0 + dl) << 3) + rr)) * 512;
            *(uint2*)(dst + 4 * lane) = make_uint2(a0, a1);
        }
    }
}

// ---------------------------------------------------------------------------
// Merged conversion: x, support -> (inh,inl) stacked ; Wv,Wp -> hi planes only
// ---------------------------------------------------------------------------
__global__ void __launch_bounds__(256) split_all(
    const float* __restrict__ x, const float* __restrict__ sup,
    const float* __restrict__ Wv, const float* __restrict__ Wp,
    __half* __restrict__ inh, __half* __restrict__ inl,
    __half* __restrict__ wvh, __half* __restrict__ wph)
{
    const int N1 = TOTQ * CDIM / 4;
    const int NW = CDIM * CDIM / 4;
    int i = blockIdx.x * 256 + threadIdx.x;
    if (i < 2 * N1) {
        const float* src = (i < N1) ? x : sup;
        int j = (i < N1) ? i : i - N1;
        float4 v = ((const float4*)src)[j];
        __half h0 = __float2half(v.x), h1 = __float2half(v.y);
        __half h2 = __float2half(v.z), h3 = __float2half(v.w);
        uint2 ph, pl;
        ph.x = hpack(__half2float(h0), __half2float(h1));
        ph.y = hpack(__half2float(h2), __half2float(h3));
        pl.x = hpack(v.x - __half2float(h0), v.y - __half2float(h1));
        pl.y = hpack(v.z - __half2float(h2), v.w - __half2float(h3));
        ((uint2*)inh)[i] = ph;
        ((uint2*)inl)[i] = pl;
    } else {
        int j = i - 2 * N1;
        if (j >= 2 * NW) return;
        const float* src = (j < NW) ? Wv : Wp;
        __half* dst = (j < NW) ? wvh : wph;
        int k = (j < NW) ? j : j - NW;
        float4 v = ((const float4*)src)[k];
        uint2 ph;
        ph.x = hpack(v.x, v.y);
        ph.y = hpack(v.z, v.w);
        ((uint2*)dst)[k] = ph;
    }
}

// ---------------------------------------------------------------------------
// kT (hi only): kth[b][d][m] = kh[b*4096+m][d]
// ---------------------------------------------------------------------------
__global__ void __launch_bounds__(256) transpose_hi(
    const __half* __restrict__ kh, __half* __restrict__ kth)
{
    __shared__ __half th[32][33];
    const int b = blockIdx.z;
    const int mm0 = blockIdx.x * 32;
    const int d0 = blockIdx.y * 32;
    const int tx = threadIdx.x, ty = threadIdx.y;
    const long long sbase = (long long)(b * 4096 + mm0) * CDIM + d0;
#pragma unroll
    for (int hh = 0; hh < 32; hh += 8)
        th[ty + hh][tx] = kh[sbase + (long long)(ty + hh) * CDIM + tx];
    __syncthreads();
    const long long dbase = (long long)b * CDIM * MROWS + (long long)d0 * MROWS + mm0;
#pragma unroll
    for (int hh = 0; hh < 32; hh += 8)
        kth[dbase + (long long)(ty + hh) * MROWS + tx] = th[tx][ty + hh];
}

// ---------------------------------------------------------------------------
// Host: tensormap encode via driver entry point
// ---------------------------------------------------------------------------
typedef CUresult (*PFN_tmapEnc)(
    CUtensorMap*, CUtensorMapDataType, cuuint32_t, void*,
    const cuuint64_t*, const cuuint64_t*, const cuuint32_t*, const cuuint32_t*,
    CUtensorMapInterleave, CUtensorMapSwizzle, CUtensorMapL2promotion,
    CUtensorMapFloatOOBfill);

static void enc_map(PFN_tmapEnc fn, CUtensorMap* m, const void* ptr,
                    unsigned long long K, unsigned long long rows,
                    unsigned long long batches, unsigned long long ldElems,
                    unsigned long long bStrideElems, unsigned boxRows)
{
    cuuint64_t dims[3] = {K, rows, batches};
    cuuint64_t strides[2] = {ldElems * 2ull, bStrideElems * 2ull};
    cuuint32_t box[3] = {64, boxRows, 1};
    cuuint32_t estr[3] = {1, 1, 1};
    fn(m, CU_TENSOR_MAP_DATA_TYPE_FLOAT16, 3, (void*)ptr,
       dims, strides, box, estr,
       CU_TENSOR_MAP_INTERLEAVE_NONE, CU_TENSOR_MAP_SWIZZLE_128B,
       CU_TENSOR_MAP_L2_PROMOTION_L2_128B, CU_TENSOR_MAP_FLOAT_OOB_FILL_NONE);
}

extern "C" void kernel_launch(void* const* d_in, const int* in_sizes, int n_in,
                              void* d_out, int out_size)
{
    const float* x       = (const float*)d_in[0];
    const float* support = (const float*)d_in[1];
    const int*   mask    = (const int*)  d_in[2];
    const float* Wv      = (const float*)d_in[3];
    const float* Wp      = (const float*)d_in[4];
    const float* bp      = (const float*)d_in[5];
    float* out = (float*)d_out;

    float* rowsum;
    __half *inh, *inl, *wvh, *wph;
    __half *qkh, *qkl, *kth, *ah, *o2h, *o2l;
    cudaGetSymbolAddress((void**)&rowsum, g_rowsum);
    cudaGetSymbolAddress((void**)&inh, g_inh); cudaGetSymbolAddress((void**)&inl, g_inl);
    cudaGetSymbolAddress((void**)&wvh, g_wvh);
    cudaGetSymbolAddress((void**)&wph, g_wph);
    cudaGetSymbolAddress((void**)&qkh, g_qkh); cudaGetSymbolAddress((void**)&qkl, g_qkl);
    cudaGetSymbolAddress((void**)&kth, g_kth);
    cudaGetSymbolAddress((void**)&ah, g_ah);
    cudaGetSymbolAddress((void**)&o2h, g_o2h); cudaGetSymbolAddress((void**)&o2l, g_o2l);

    __half* kh = qkh + (size_t)TOTQ * CDIM;

    void* sym = nullptr;
    cudaDriverEntryPointQueryResult qres;
    cudaGetDriverEntryPointByVersion("cuTensorMapEncodeTiled", &sym, 12000,
                                     cudaEnableDefault, &qres);
    PFN_tmapEnc enc = (PFN_tmapEnc)sym;

    const long long sQK = (long long)NROWS * CDIM;
    const long long sAT = (long long)NROWS * MROWS;

    CUtensorMap tInh, tInl, tWvh, tWph;
    enc_map(enc, &tInh, inh, CDIM, 2 * TOTQ, 1, CDIM, (long long)2 * TOTQ * CDIM, 128);
    enc_map(enc, &tInl, inl, CDIM, 2 * TOTQ, 1, CDIM, (long long)2 * TOTQ * CDIM, 128);
    enc_map(enc, &tWvh, wvh, CDIM, CDIM, 1, CDIM, (long long)CDIM * CDIM, 256);
    enc_map(enc, &tWph, wph, CDIM, CDIM, 1, CDIM, (long long)CDIM * CDIM, 256);
    CUtensorMap tQh, tQl, tKh;
    enc_map(enc, &tQh, qkh, CDIM, NROWS, BB, CDIM, sQK, 128);
    enc_map(enc, &tQl, qkl, CDIM, NROWS, BB, CDIM, sQK, 128);
    enc_map(enc, &tKh, kh,  CDIM, NROWS, BB, CDIM, sQK, 128);
    CUtensorMap tAh, tKTh;
    enc_map(enc, &tAh, ah, MROWS, NROWS, BB, MROWS, sAT, 128);
    enc_map(enc, &tKTh, kth, MROWS, CDIM, BB, MROWS, (long long)CDIM * MROWS, 128);
    CUtensorMap tO2h, tO2l;
    enc_map(enc, &tO2h, o2h, CDIM, TOTQ, 1, CDIM, (long long)TOTQ * CDIM, 128);
    enc_map(enc, &tO2l, o2l, CDIM, TOTQ, 1, CDIM, (long long)TOTQ * CDIM, 128);

    const int SMEM_P  = 1024 + 2 * (2 * TILEA + (256 * 64 * 2));      // 132096, occ1
    const int SMEM_QK = 1024 + 2 * (2 * TILEA + (128 * 64 * 2));      //  99328, occ2
    const int SMEM_AV = 1024 + 128 * 132 * 4;                         //  68608, occ2
    cudaFuncSetAttribute((const void*)tma_gemm<2,2,256,1>, cudaFuncAttributeMaxDynamicSharedMemorySize, SMEM_P);
    cudaFuncSetAttribute((const void*)tma_gemm<1,2,256,1>, cudaFuncAttributeMaxDynamicSharedMemorySize, SMEM_P);
    cudaFuncSetAttribute((const void*)tma_gemm<5,2,128,2>, cudaFuncAttributeMaxDynamicSharedMemorySize, SMEM_QK);
    cudaFuncSetAttribute((const void*)tma_gemm<6,1,128,2>, cudaFuncAttributeMaxDynamicSharedMemorySize, SMEM_AV);

    // 0) zero rowsum (graph-capturable)
    cudaMemsetAsync(rowsum, 0, TOTQ * sizeof(float));

    // 1) merged conversions
    {
        const int total = 2 * (TOTQ * CDIM / 4) + 2 * (CDIM * CDIM / 4);
        split_all<<<(total + 255) / 256, 256>>>(x, support, Wv, Wp,
                                                inh, inl, wvh, wph);
    }

    // 2) merged projection: [q;k] = [x;support] @ Wv-hi^T  (2-term, split out)
    tma_gemm<2,2,256,1><<<dim3(2, 256, 1), 256, SMEM_P>>>(
        tInh, tInl, tWvh, tWvh, CDIM, CDIM, 1.0f, 0,
        nullptr, nullptr, nullptr, qkh, qkl);

    // 3) kT[b][d][m] (hi only)
    transpose_hi<<<dim3(128, 16, BB), dim3(32, 8)>>>(kh, kth);

    // 4) fused QK^T + exp (clamped 2^-21 scale) + rowsum + mask -> fp16 E
    tma_gemm<5,2,128,2><<<dim3(32, 32, BB), 256, SMEM_QK>>>(
        tQh, tQl, tKh, tKh, MROWS, CDIM, 0.125f, sAT,
        nullptr, mask, rowsum, ah, nullptr);

    // 5) fused AV + per-row normalize + bug-faithful permute -> split-fp16 o2
    tma_gemm<6,1,128,2><<<dim3(4, 32, BB), 256, SMEM_AV>>>(
        tAh, tAh, tKTh, tKTh, CDIM, MROWS, 1.0f, sQK,
        rowsum, nullptr, nullptr, o2h, o2l);

    // 6) out = o2 @ Wp-hi^T + bp  (2-term)
    tma_gemm<1,2,256,1><<<dim3(2, 128, 1), 256, SMEM_P>>>(
        tO2h, tO2l, tWph, tWph, CDIM, CDIM, 1.0f, 0,
        bp, nullptr, out, nullptr, nullptr);
}

// round 15
// speedup vs baseline: 5.6025x; 1.0360x over previous
#include <cuda_runtime.h>
#include <cuda_fp16.h>
#include <cuda.h>

#define BB 4
#define NROWS 4096
#define MROWS 4096
#define CDIM 512
#define TOTQ (BB*NROWS)

// ---------------------------------------------------------------------------
// Device scratch
// ---------------------------------------------------------------------------
__device__ __align__(16) float g_rowsum[TOTQ];                 // 64 KB
__device__ __align__(16) __half g_inh[(size_t)2*TOTQ*CDIM];    // x | support
__device__ __align__(16) __half g_inl[(size_t)2*TOTQ*CDIM];
__device__ __align__(16) __half g_wvh[CDIM*CDIM];
__device__ __align__(16) __half g_wph[CDIM*CDIM];
__device__ __align__(16) __half g_qkh[(size_t)2*TOTQ*CDIM];    // q | k
__device__ __align__(16) __half g_qkl[(size_t)2*TOTQ*CDIM];
__device__ __align__(16) __half g_kth[(size_t)TOTQ*CDIM];
__device__ __align__(16) __half g_ah[(size_t)BB*NROWS*MROWS];  // scaled exp (hi), masked
__device__ __align__(16) __half g_o2h[(size_t)TOTQ*CDIM], g_o2l[(size_t)TOTQ*CDIM];

// ---------------------------------------------------------------------------
// device helpers
// ---------------------------------------------------------------------------
static __device__ __forceinline__ unsigned smem_u32(const void* p) {
    unsigned a;
    asm("{ .reg .u64 t; cvta.to.shared.u64 t, %1; cvt.u32.u64 %0, t; }" : "=r"(a) : "l"(p));
    return a;
}
static __device__ __forceinline__ void ldm_x4(unsigned& r0, unsigned& r1,
                                              unsigned& r2, unsigned& r3, unsigned a) {
    asm volatile("ldmatrix.sync.aligned.m8n8.x4.shared.b16 {%0,%1,%2,%3}, [%4];"
                 : "=r"(r0), "=r"(r1), "=r"(r2), "=r"(r3) : "r"(a));
}
static __device__ __forceinline__ void mma16816(float* c, const unsigned* a,
                                                const unsigned* b) {
    asm volatile(
        "mma.sync.aligned.m16n8k16.row.col.f32.f16.f16.f32 "
        "{%0,%1,%2,%3}, {%4,%5,%6,%7}, {%8,%9}, {%0,%1,%2,%3};"
        : "+f"(c[0]), "+f"(c[1]), "+f"(c[2]), "+f"(c[3])
        : "r"(a[0]), "r"(a[1]), "r"(a[2]), "r"(a[3]), "r"(b[0]), "r"(b[1]));
}
static __device__ __forceinline__ unsigned hpack(float a, float b) {
    __half2 t = __floats2half2_rn(a, b);
    return *reinterpret_cast<unsigned*>(&t);
}
static __device__ __forceinline__ unsigned hsplitpack(float v) {
    __half h = __float2half(v);
    float lo = v - __half2float(h);
    __half l = __float2half(lo);
    return (unsigned)(*reinterpret_cast<unsigned short*>(&h))
         | ((unsigned)(*reinterpret_cast<unsigned short*>(&l)) << 16);
}
static __device__ __forceinline__ void mbar_wait(unsigned mbar, unsigned phase) {
    asm volatile(
        "{\n\t.reg .pred P1;\n\t"
        "LAB_WAIT_%=:\n\t"
        "mbarrier.try_wait.parity.acquire.cta.shared::cta.b64 P1, [%0], %1, 0x989680;\n\t"
        "@P1 bra.uni LAB_DONE_%=;\n\t"
        "bra.uni LAB_WAIT_%=;\n\t"
        "LAB_DONE_%=:\n\t}"
        :: "r"(mbar), "r"(phase) : "memory");
}
static __device__ __forceinline__ void tma3(unsigned dst, const CUtensorMap* m,
                                            int x, int y, int z, unsigned mb) {
    asm volatile(
        "cp.async.bulk.tensor.3d.shared::cluster.global.tile.mbarrier::complete_tx::bytes "
        "[%0], [%1, {%2, %3, %4}], [%5];"
        :: "r"(dst), "l"(m), "r"(x), "r"(y), "r"(z), "r"(mb) : "memory");
}

// ---------------------------------------------------------------------------
// Split-fp16 HMMA GEMM, TMA loads. CTA 128 x TN, K-slab 64, 2-stage buffer.
// C = A @ B^T; A,B [rows,K] row-major.
// NTERMS=3: ah*bh+al*bh+ah*bl ; 2: ah*bh+al*bh ; 1: ah*bh
// MODE 1: Cf = acc + bias
// MODE 2: Ch = hi(acc); Cl = lo(acc) only for rows < sC (loLimit)
// MODE 5: E = exp(scale*acc)*2^-21 clamped; Ch = fp16(E)*mask;
//         rowsum(Cf) += fp16-rounded E (pre-mask, atomic)
// MODE 6: bug-faithful permuted split write of acc/rowsum(bias) into (Ch,Cl)
// ---------------------------------------------------------------------------
#define TILEA 16384                 // 128x64 fp16

template<int MODE, int NTERMS, int TN, int MINB>
__global__ void __launch_bounds__(256, MINB) tma_gemm(
    const __grid_constant__ CUtensorMap mAh, const __grid_constant__ CUtensorMap mAl,
    const __grid_constant__ CUtensorMap mBh, const __grid_constant__ CUtensorMap mBl,
    int ldC, int Kdim, float scale, long long sC,
    const float* __restrict__ bias, const int* __restrict__ maskp,
    float* __restrict__ Cf,
    __half* __restrict__ Ch, __half* __restrict__ Cl)
{
    constexpr unsigned TILEBN = TN * 64 * 2;
    constexpr unsigned NA = (NTERMS >= 2) ? 2u : 1u;
    constexpr unsigned NB = (NTERMS == 3) ? 2u : 1u;
    constexpr unsigned OFF_BH = NA * TILEA;
    constexpr unsigned STGX = NA * TILEA + NB * TILEBN;
    constexpr int NBP = TN / 64;
    constexpr int NBW = TN / 32;

    extern __shared__ char smem[];
    __shared__ __align__(16) unsigned long long mbar[2];
    const unsigned sa = (smem_u32(smem) + 1023) & ~1023u;
    const unsigned mbq = smem_u32(mbar);
    const int tid = threadIdx.x;
    const int wid = tid >> 5;
    const int lane = tid & 31;
    const int m0 = blockIdx.y * 128;
    const int n0 = blockIdx.x * TN;
    const int bz = blockIdx.z;

    const int m_w = (wid >> 2) * 64;
    const int n_w = (wid & 3) * (TN / 4);

    if (tid == 0) {
        asm volatile("mbarrier.init.shared.b64 [%0], 1;" :: "r"(mbq) : "memory");
        asm volatile("mbarrier.init.shared.b64 [%0], 1;" :: "r"(mbq + 8) : "memory");
    }
    __syncthreads();

    const int nslab = Kdim / 64;
    auto issue = [&](int buf, int k0) {
        if (tid == 0) {
            const unsigned mb = mbq + buf * 8;
            asm volatile("mbarrier.arrive.expect_tx.shared.b64 _, [%0], %1;"
                         :: "r"(mb), "r"(STGX) : "memory");
            const unsigned base = sa + buf * STGX;
            tma3(base, &mAh, k0, m0, bz, mb);
            if (NTERMS >= 2) tma3(base + TILEA, &mAl, k0, m0, bz, mb);
            tma3(base + OFF_BH, &mBh, k0, n0, bz, mb);
            if (NTERMS == 3) tma3(base + OFF_BH + TILEBN, &mBl, k0, n0, bz, mb);
        }
    };

    issue(0, 0);
    if (nslab > 1) issue(1, 64);

    float acc[4][NBW][4];
#pragma unroll
    for (int i = 0; i < 4; i++)
#pragma unroll
        for (int j = 0; j < NBW; j++)
#pragma unroll
            for (int p = 0; p < 4; p++) acc[i][j][p] = 0.f;

    const unsigned aoffL = (unsigned)(m_w + (lane & 15)) * 128 + ((lane >> 4) * 16);
    const unsigned boffL = (unsigned)(n_w + (lane & 7) + ((lane >> 4) << 3)) * 128
                         + ((lane & 8) ? 16 : 0);
    const unsigned sxor = (unsigned)(lane & 7) << 4;

    int phase[2] = {0, 0};
    for (int s = 0; s < nslab; s++) {
        const int buf = s & 1;
        mbar_wait(mbq + buf * 8, (unsigned)phase[buf]);
        phase[buf] ^= 1;
        const unsigned st = sa + buf * STGX;
#pragma unroll
        for (int kk = 0; kk < 4; kk++) {
            unsigned ah[4][4], al[4][4];
#pragma unroll
            for (int mb = 0; mb < 4; mb++) {
                const unsigned a = st + ((aoffL + mb * 2048 + kk * 32) ^ sxor);
                ldm_x4(ah[mb][0], ah[mb][1], ah[mb][2], ah[mb][3], a);
                if (NTERMS >= 2)
                    ldm_x4(al[mb][0], al[mb][1], al[mb][2], al[mb][3], a + TILEA);
            }
#pragma unroll
            for (int nbp = 0; nbp < NBP; nbp++) {
                unsigned bh[2][2], bl[2][2];
                const unsigned b = st + OFF_BH + ((boffL + nbp * 2048 + kk * 32) ^ sxor);
                ldm_x4(bh[0][0], bh[0][1], bh[1][0], bh[1][1], b);
                if (NTERMS == 3)
                    ldm_x4(bl[0][0], bl[0][1], bl[1][0], bl[1][1], b + TILEBN);
#pragma unroll
                for (int mb = 0; mb < 4; mb++)
#pragma unroll
                    for (int j = 0; j < 2; j++) {
                        float* c = acc[mb][2 * nbp + j];
                        mma16816(c, ah[mb], bh[j]);
                        if (NTERMS >= 2) mma16816(c, al[mb], bh[j]);
                        if (NTERMS == 3) mma16816(c, ah[mb], bl[j]);
                    }
            }
        }
        __syncthreads();
        if (s + 2 < nslab) issue(buf, (s + 2) * 64);
    }

    // ======================= epilogues =======================
    if (MODE == 1 || MODE == 2) {
#pragma unroll
        for (int mb = 0; mb < 4; mb++)
#pragma unroll
            for (int p = 0; p < 2; p++) {
                const long long row = m0 + m_w + mb * 16 + (lane >> 2) + p * 8;
#pragma unroll
                for (int nb = 0; nb < NBW; nb++) {
                    const int col = n0 + n_w + nb * 8 + (lane & 3) * 2;
                    float v0 = acc[mb][nb][2 * p];
                    float v1 = acc[mb][nb][2 * p + 1];
                    if (MODE == 1) {
                        float2 o = make_float2(v0 + bias[col], v1 + bias[col + 1]);
                        *(float2*)&Cf[row * ldC + col] = o;
                    } else {
                        __half h0 = __float2half(v0);
                        __half h1 = __float2half(v1);
                        *(unsigned*)&Ch[row * (long long)ldC + col] =
                            hpack(__half2float(h0), __half2float(h1));
                        if (row < sC)
                            *(unsigned*)&Cl[row * (long long)ldC + col] =
                                hpack(v0 - __half2float(h0), v1 - __half2float(h1));
                    }
                }
            }
    }

    if (MODE == 5) {
        const float SC = 4.76837158203125e-7f;   // 2^-21
        float rs[4][2];
#pragma unroll
        for (int mb = 0; mb < 4; mb++)
#pragma unroll
            for (int p = 0; p < 2; p++) rs[mb][p] = 0.f;
#pragma unroll
        for (int mb = 0; mb < 4; mb++)
#pragma unroll
            for (int nb = 0; nb < NBW; nb++)
#pragma unroll
                for (int p = 0; p < 2; p++) {
                    float e0 = fminf(__expf(acc[mb][nb][2 * p] * scale) * SC, 60000.f);
                    float e1 = fminf(__expf(acc[mb][nb][2 * p + 1] * scale) * SC, 60000.f);
                    float r0 = __half2float(__float2half(e0));
                    float r1 = __half2float(__float2half(e1));
                    acc[mb][nb][2 * p] = r0;
                    acc[mb][nb][2 * p + 1] = r1;
                    rs[mb][p] += r0 + r1;
                }
#pragma unroll
        for (int mb = 0; mb < 4; mb++)
#pragma unroll
            for (int p = 0; p < 2; p++) {
                rs[mb][p] += __shfl_xor_sync(0xffffffffu, rs[mb][p], 1);
                rs[mb][p] += __shfl_xor_sync(0xffffffffu, rs[mb][p], 2);
            }
        if ((lane & 3) == 0) {
#pragma unroll
            for (int mb = 0; mb < 4; mb++)
#pragma unroll
                for (int p = 0; p < 2; p++) {
                    const int row = m0 + m_w + mb * 16 + (lane >> 2) + p * 8;
                    atomicAdd(&Cf[bz * NROWS + row], rs[mb][p]);
                }
        }
#pragma unroll
        for (int mb = 0; mb < 4; mb++)
#pragma unroll
            for (int p = 0; p < 2; p++) {
                const long long row = m0 + m_w + mb * 16 + (lane >> 2) + p * 8;
#pragma unroll
                for (int nb = 0; nb < NBW; nb++) {
                    const int col = n0 + n_w + nb * 8 + (lane & 3) * 2;
                    int2 mk = *(const int2*)&maskp[col];
                    float s0 = acc[mb][nb][2 * p] * (mk.x != 0 ? 1.f : 0.f);
                    float s1 = acc[mb][nb][2 * p + 1] * (mk.y != 0 ? 1.f : 0.f);
                    *(unsigned*)&Ch[(long long)bz * sC + row * (long long)ldC + col] =
                        hpack(s0, s1);
                }
            }
    }

    if (MODE == 6) {
        char* smal = smem + (int)(sa - smem_u32(smem));
        unsigned* S = (unsigned*)smal;
#pragma unroll
        for (int mb = 0; mb < 4; mb++)
#pragma unroll
            for (int p = 0; p < 2; p++) {
                const int row = m0 + m_w + mb * 16 + (lane >> 2) + p * 8;
                const float sc = 1.0f / bias[bz * NROWS + row];
                const int jl = row - m0;
#pragma unroll
                for (int nb = 0; nb < NBW; nb++) {
                    const int col = n0 + n_w + nb * 8 + (lane & 3) * 2;
                    float v0 = acc[mb][nb][2 * p] * sc;
                    float v1 = acc[mb][nb][2 * p + 1] * sc;
                    S[(col - n0) * 132 + jl] = hsplitpack(v0);
                    S[(col + 1 - n0) * 132 + jl] = hsplitpack(v1);
                }
            }
        __syncthreads();
        const int rr = m0 >> 9;
        const int j0 = m0 & 511;
        const long long ob = (long long)bz * ((long long)NROWS * CDIM) + j0;
#pragma unroll 4
        for (int rp = wid; rp < 256; rp += 8) {
            const int dl = rp >> 1;
            const int pl = rp & 1;
            uint4 q = *(uint4*)&S[dl * 132 + 4 * lane];
            unsigned a0, a1;
            if (pl == 0) {
                a0 = (q.x & 0xFFFFu) | (q.y << 16);
                a1 = (q.z & 0xFFFFu) | (q.w << 16);
            } else {
                a0 = (q.x >> 16) | (q.y & 0xFFFF0000u);
                a1 = (q.z >> 16) | (q.w & 0xFFFF0000u);
            }
            __half* dst = (pl ? Cl : Ch) + ob
                        + (long long)((((n0 + dl) << 3) + rr)) * 512;
            *(uint2*)(dst + 4 * lane) = make_uint2(a0, a1);
        }
    }
}

// ---------------------------------------------------------------------------
// Merged conversion: x, support -> (inh,inl) stacked ; Wv,Wp -> hi planes only
// ---------------------------------------------------------------------------
__global__ void __launch_bounds__(256) split_all(
    const float* __restrict__ x, const float* __restrict__ sup,
    const float* __restrict__ Wv, const float* __restrict__ Wp,
    __half* __restrict__ inh, __half* __restrict__ inl,
    __half* __restrict__ wvh, __half* __restrict__ wph)
{
    const int N1 = TOTQ * CDIM / 4;
    const int NW = CDIM * CDIM / 4;
    int i = blockIdx.x * 256 + threadIdx.x;
    if (i < 2 * N1) {
        const float* src = (i < N1) ? x : sup;
        int j = (i < N1) ? i : i - N1;
        float4 v = ((const float4*)src)[j];
        __half h0 = __float2half(v.x), h1 = __float2half(v.y);
        __half h2 = __float2half(v.z), h3 = __float2half(v.w);
        uint2 ph, pl;
        ph.x = hpack(__half2float(h0), __half2float(h1));
        ph.y = hpack(__half2float(h2), __half2float(h3));
        pl.x = hpack(v.x - __half2float(h0), v.y - __half2float(h1));
        pl.y = hpack(v.z - __half2float(h2), v.w - __half2float(h3));
        ((uint2*)inh)[i] = ph;
        ((uint2*)inl)[i] = pl;
    } else {
        int j = i - 2 * N1;
        if (j >= 2 * NW) return;
        const float* src = (j < NW) ? Wv : Wp;
        __half* dst = (j < NW) ? wvh : wph;
        int k = (j < NW) ? j : j - NW;
        float4 v = ((const float4*)src)[k];
        uint2 ph;
        ph.x = hpack(v.x, v.y);
        ph.y = hpack(v.z, v.w);
        ((uint2*)dst)[k] = ph;
    }
}

// ---------------------------------------------------------------------------
// kT (hi only): kth[b][d][m] = kh[b*4096+m][d]
// ---------------------------------------------------------------------------
__global__ void __launch_bounds__(256) transpose_hi(
    const __half* __restrict__ kh, __half* __restrict__ kth)
{
    __shared__ __half th[32][33];
    const int b = blockIdx.z;
    const int mm0 = blockIdx.x * 32;
    const int d0 = blockIdx.y * 32;
    const int tx = threadIdx.x, ty = threadIdx.y;
    const long long sbase = (long long)(b * 4096 + mm0) * CDIM + d0;
#pragma unroll
    for (int hh = 0; hh < 32; hh += 8)
        th[ty + hh][tx] = kh[sbase + (long long)(ty + hh) * CDIM + tx];
    __syncthreads();
    const long long dbase = (long long)b * CDIM * MROWS + (long long)d0 * MROWS + mm0;
#pragma unroll
    for (int hh = 0; hh < 32; hh += 8)
        kth[dbase + (long long)(ty + hh) * MROWS + tx] = th[tx][ty + hh];
}

// ---------------------------------------------------------------------------
// Host: tensormap encode via driver entry point
// ---------------------------------------------------------------------------
typedef CUresult (*PFN_tmapEnc)(
    CUtensorMap*, CUtensorMapDataType, cuuint32_t, void*,
    const cuuint64_t*, const cuuint64_t*, const cuuint32_t*, const cuuint32_t*,
    CUtensorMapInterleave, CUtensorMapSwizzle, CUtensorMapL2promotion,
    CUtensorMapFloatOOBfill);

static void enc_map(PFN_tmapEnc fn, CUtensorMap* m, const void* ptr,
                    unsigned long long K, unsigned long long rows,
                    unsigned long long batches, unsigned long long ldElems,
                    unsigned long long bStrideElems, unsigned boxRows)
{
    cuuint64_t dims[3] = {K, rows, batches};
    cuuint64_t strides[2] = {ldElems * 2ull, bStrideElems * 2ull};
    cuuint32_t box[3] = {64, boxRows, 1};
    cuuint32_t estr[3] = {1, 1, 1};
    fn(m, CU_TENSOR_MAP_DATA_TYPE_FLOAT16, 3, (void*)ptr,
       dims, strides, box, estr,
       CU_TENSOR_MAP_INTERLEAVE_NONE, CU_TENSOR_MAP_SWIZZLE_128B,
       CU_TENSOR_MAP_L2_PROMOTION_L2_128B, CU_TENSOR_MAP_FLOAT_OOB_FILL_NONE);
}

extern "C" void kernel_launch(void* const* d_in, const int* in_sizes, int n_in,
                              void* d_out, int out_size)
{
    const float* x       = (const float*)d_in[0];
    const float* support = (const float*)d_in[1];
    const int*   mask    = (const int*)  d_in[2];
    const float* Wv      = (const float*)d_in[3];
    const float* Wp      = (const float*)d_in[4];
    const float* bp      = (const float*)d_in[5];
    float* out = (float*)d_out;

    float* rowsum;
    __half *inh, *inl, *wvh, *wph;
    __half *qkh, *qkl, *kth, *ah, *o2h, *o2l;
    cudaGetSymbolAddress((void**)&rowsum, g_rowsum);
    cudaGetSymbolAddress((void**)&inh, g_inh); cudaGetSymbolAddress((void**)&inl, g_inl);
    cudaGetSymbolAddress((void**)&wvh, g_wvh);
    cudaGetSymbolAddress((void**)&wph, g_wph);
    cudaGetSymbolAddress((void**)&qkh, g_qkh); cudaGetSymbolAddress((void**)&qkl, g_qkl);
    cudaGetSymbolAddress((void**)&kth, g_kth);
    cudaGetSymbolAddress((void**)&ah, g_ah);
    cudaGetSymbolAddress((void**)&o2h, g_o2h); cudaGetSymbolAddress((void**)&o2l, g_o2l);

    __half* kh = qkh + (size_t)TOTQ * CDIM;

    void* sym = nullptr;
    cudaDriverEntryPointQueryResult qres;
    cudaGetDriverEntryPointByVersion("cuTensorMapEncodeTiled", &sym, 12000,
                                     cudaEnableDefault, &qres);
    PFN_tmapEnc enc = (PFN_tmapEnc)sym;

    const long long sQK = (long long)NROWS * CDIM;
    const long long sAT = (long long)NROWS * MROWS;

    CUtensorMap tInh, tInl, tWvh, tWph;
    enc_map(enc, &tInh, inh, CDIM, 2 * TOTQ, 1, CDIM, (long long)2 * TOTQ * CDIM, 128);
    enc_map(enc, &tInl, inl, CDIM, 2 * TOTQ, 1, CDIM, (long long)2 * TOTQ * CDIM, 128);
    enc_map(enc, &tWvh, wvh, CDIM, CDIM, 1, CDIM, (long long)CDIM * CDIM, 128);
    enc_map(enc, &tWph, wph, CDIM, CDIM, 1, CDIM, (long long)CDIM * CDIM, 128);
    CUtensorMap tQh, tQl, tKh;
    enc_map(enc, &tQh, qkh, CDIM, NROWS, BB, CDIM, sQK, 128);
    enc_map(enc, &tQl, qkl, CDIM, NROWS, BB, CDIM, sQK, 128);
    enc_map(enc, &tKh, kh,  CDIM, NROWS, BB, CDIM, sQK, 128);
    CUtensorMap tAh, tKTh;
    enc_map(enc, &tAh, ah, MROWS, NROWS, BB, MROWS, sAT, 128);
    enc_map(enc, &tKTh, kth, MROWS, CDIM, BB, MROWS, (long long)CDIM * MROWS, 128);
    CUtensorMap tO2h, tO2l;
    enc_map(enc, &tO2h, o2h, CDIM, TOTQ, 1, CDIM, (long long)TOTQ * CDIM, 128);
    enc_map(enc, &tO2l, o2l, CDIM, TOTQ, 1, CDIM, (long long)TOTQ * CDIM, 128);

    // all GEMMs now TN=128 / occ-2
    const int SMEM_2T = 1024 + 2 * (2 * TILEA + (128 * 64 * 2));      //  99328
    const int SMEM_AV = 1024 + 128 * 132 * 4;                         //  68608
    cudaFuncSetAttribute((const void*)tma_gemm<2,2,128,2>, cudaFuncAttributeMaxDynamicSharedMemorySize, SMEM_2T);
    cudaFuncSetAttribute((const void*)tma_gemm<1,2,128,2>, cudaFuncAttributeMaxDynamicSharedMemorySize, SMEM_2T);
    cudaFuncSetAttribute((const void*)tma_gemm<5,2,128,2>, cudaFuncAttributeMaxDynamicSharedMemorySize, SMEM_2T);
    cudaFuncSetAttribute((const void*)tma_gemm<6,1,128,2>, cudaFuncAttributeMaxDynamicSharedMemorySize, SMEM_AV);

    // 0) zero rowsum (graph-capturable)
    cudaMemsetAsync(rowsum, 0, TOTQ * sizeof(float));

    // 1) merged conversions
    {
        const int total = 2 * (TOTQ * CDIM / 4) + 2 * (CDIM * CDIM / 4);
        split_all<<<(total + 255) / 256, 256>>>(x, support, Wv, Wp,
                                                inh, inl, wvh, wph);
    }

    // 2) merged projection: [q;k] = [x;support] @ Wv-hi^T
    //    (2-term, occ-2, split out; lo-plane only for q rows < TOTQ)
    tma_gemm<2,2,128,2><<<dim3(4, 256, 1), 256, SMEM_2T>>>(
        tInh, tInl, tWvh, tWvh, CDIM, CDIM, 1.0f, (long long)TOTQ,
        nullptr, nullptr, nullptr, qkh, qkl);

    // 3) kT[b][d][m] (hi only)
    transpose_hi<<<dim3(128, 16, BB), dim3(32, 8)>>>(kh, kth);

    // 4) fused QK^T + exp (clamped 2^-21) + rowsum + mask -> fp16 E
    tma_gemm<5,2,128,2><<<dim3(32, 32, BB), 256, SMEM_2T>>>(
        tQh, tQl, tKh, tKh, MROWS, CDIM, 0.125f, sAT,
        nullptr, mask, rowsum, ah, nullptr);

    // 5) fused AV + per-row normalize + bug-faithful permute -> split-fp16 o2
    tma_gemm<6,1,128,2><<<dim3(4, 32, BB), 256, SMEM_AV>>>(
        tAh, tAh, tKTh, tKTh, CDIM, MROWS, 1.0f, sQK,
        rowsum, nullptr, nullptr, o2h, o2l);

    // 6) out = o2 @ Wp-hi^T + bp  (2-term, occ-2)
    tma_gemm<1,2,128,2><<<dim3(4, 128, 1), 256, SMEM_2T>>>(
        tO2h, tO2l, tWph, tWph, CDIM, CDIM, 1.0f, 0,
        bp, nullptr, out, nullptr, nullptr);
}

// round 16
// speedup vs baseline: 5.6414x; 1.0069x over previous
#include <cuda_runtime.h>
#include <cuda_fp16.h>
#include <cuda.h>

#define BB 4
#define NROWS 4096
#define MROWS 4096
#define CDIM 512
#define TOTQ (BB*NROWS)

// ---------------------------------------------------------------------------
// Device scratch
// ---------------------------------------------------------------------------
__device__ __align__(16) float g_rowsum[TOTQ];                 // 64 KB
__device__ __align__(16) __half g_inh[(size_t)2*TOTQ*CDIM];    // x | support
__device__ __align__(16) __half g_inl[(size_t)2*TOTQ*CDIM];
__device__ __align__(16) __half g_wvh[CDIM*CDIM];
__device__ __align__(16) __half g_wph[CDIM*CDIM];
__device__ __align__(16) __half g_qkh[(size_t)2*TOTQ*CDIM];    // q | k
__device__ __align__(16) __half g_qkl[(size_t)2*TOTQ*CDIM];
__device__ __align__(16) __half g_kth[(size_t)TOTQ*CDIM];
__device__ __align__(16) __half g_ah[(size_t)BB*NROWS*MROWS];  // scaled exp (hi), masked
__device__ __align__(16) __half g_o2h[(size_t)TOTQ*CDIM], g_o2l[(size_t)TOTQ*CDIM];

// ---------------------------------------------------------------------------
// device helpers
// ---------------------------------------------------------------------------
static __device__ __forceinline__ unsigned smem_u32(const void* p) {
    unsigned a;
    asm("{ .reg .u64 t; cvta.to.shared.u64 t, %1; cvt.u32.u64 %0, t; }" : "=r"(a) : "l"(p));
    return a;
}
static __device__ __forceinline__ void ldm_x4(unsigned& r0, unsigned& r1,
                                              unsigned& r2, unsigned& r3, unsigned a) {
    asm volatile("ldmatrix.sync.aligned.m8n8.x4.shared.b16 {%0,%1,%2,%3}, [%4];"
                 : "=r"(r0), "=r"(r1), "=r"(r2), "=r"(r3) : "r"(a));
}
static __device__ __forceinline__ void mma16816(float* c, const unsigned* a,
                                                const unsigned* b) {
    asm volatile(
        "mma.sync.aligned.m16n8k16.row.col.f32.f16.f16.f32 "
        "{%0,%1,%2,%3}, {%4,%5,%6,%7}, {%8,%9}, {%0,%1,%2,%3};"
        : "+f"(c[0]), "+f"(c[1]), "+f"(c[2]), "+f"(c[3])
        : "r"(a[0]), "r"(a[1]), "r"(a[2]), "r"(a[3]), "r"(b[0]), "r"(b[1]));
}
static __device__ __forceinline__ unsigned hpack(float a, float b) {
    __half2 t = __floats2half2_rn(a, b);
    return *reinterpret_cast<unsigned*>(&t);
}
static __device__ __forceinline__ unsigned hsplitpack(float v) {
    __half h = __float2half(v);
    float lo = v - __half2float(h);
    __half l = __float2half(lo);
    return (unsigned)(*reinterpret_cast<unsigned short*>(&h))
         | ((unsigned)(*reinterpret_cast<unsigned short*>(&l)) << 16);
}
static __device__ __forceinline__ void mbar_wait(unsigned mbar, unsigned phase) {
    asm volatile(
        "{\n\t.reg .pred P1;\n\t"
        "LAB_WAIT_%=:\n\t"
        "mbarrier.try_wait.parity.acquire.cta.shared::cta.b64 P1, [%0], %1, 0x989680;\n\t"
        "@P1 bra.uni LAB_DONE_%=;\n\t"
        "bra.uni LAB_WAIT_%=;\n\t"
        "LAB_DONE_%=:\n\t}"
        :: "r"(mbar), "r"(phase) : "memory");
}
static __device__ __forceinline__ void tma3(unsigned dst, const CUtensorMap* m,
                                            int x, int y, int z, unsigned mb) {
    asm volatile(
        "cp.async.bulk.tensor.3d.shared::cluster.global.tile.mbarrier::complete_tx::bytes "
        "[%0], [%1, {%2, %3, %4}], [%5];"
        :: "r"(dst), "l"(m), "r"(x), "r"(y), "r"(z), "r"(mb) : "memory");
}

// ---------------------------------------------------------------------------
// Split-fp16 HMMA GEMM, TMA loads. CTA 128 x TN, K-slab 64, 2-stage buffer.
// C = A @ B^T; A,B [rows,K] row-major.
// NTERMS=3: ah*bh+al*bh+ah*bl ; 2: ah*bh+al*bh ; 1: ah*bh
// MODE 1: Cf = acc + bias
// MODE 2: Ch = hi(acc); Cl = lo(acc) only for rows < sC (loLimit)
// MODE 5: E = exp2(scale*acc)*2^-21 clamped (scale has log2e folded in);
//         Ch = fp16(E)*mask;  rowsum(Cf) += E (pre-mask, atomic)
// MODE 6: bug-faithful permuted split write of acc/rowsum(bias) into (Ch,Cl)
// ---------------------------------------------------------------------------
#define TILEA 16384                 // 128x64 fp16

template<int MODE, int NTERMS, int TN, int MINB>
__global__ void __launch_bounds__(256, MINB) tma_gemm(
    const __grid_constant__ CUtensorMap mAh, const __grid_constant__ CUtensorMap mAl,
    const __grid_constant__ CUtensorMap mBh, const __grid_constant__ CUtensorMap mBl,
    int ldC, int Kdim, float scale, long long sC,
    const float* __restrict__ bias, const int* __restrict__ maskp,
    float* __restrict__ Cf,
    __half* __restrict__ Ch, __half* __restrict__ Cl)
{
    constexpr unsigned TILEBN = TN * 64 * 2;
    constexpr unsigned NA = (NTERMS >= 2) ? 2u : 1u;
    constexpr unsigned NB = (NTERMS == 3) ? 2u : 1u;
    constexpr unsigned OFF_BH = NA * TILEA;
    constexpr unsigned STGX = NA * TILEA + NB * TILEBN;
    constexpr int NBP = TN / 64;
    constexpr int NBW = TN / 32;

    extern __shared__ char smem[];
    __shared__ __align__(16) unsigned long long mbar[2];
    const unsigned sa = (smem_u32(smem) + 1023) & ~1023u;
    const unsigned mbq = smem_u32(mbar);
    const int tid = threadIdx.x;
    const int wid = tid >> 5;
    const int lane = tid & 31;
    const int m0 = blockIdx.y * 128;
    const int n0 = blockIdx.x * TN;
    const int bz = blockIdx.z;

    const int m_w = (wid >> 2) * 64;
    const int n_w = (wid & 3) * (TN / 4);

    if (tid == 0) {
        asm volatile("mbarrier.init.shared.b64 [%0], 1;" :: "r"(mbq) : "memory");
        asm volatile("mbarrier.init.shared.b64 [%0], 1;" :: "r"(mbq + 8) : "memory");
    }
    __syncthreads();

    const int nslab = Kdim / 64;
    auto issue = [&](int buf, int k0) {
        if (tid == 0) {
            const unsigned mb = mbq + buf * 8;
            asm volatile("mbarrier.arrive.expect_tx.shared.b64 _, [%0], %1;"
                         :: "r"(mb), "r"(STGX) : "memory");
            const unsigned base = sa + buf * STGX;
            tma3(base, &mAh, k0, m0, bz, mb);
            if (NTERMS >= 2) tma3(base + TILEA, &mAl, k0, m0, bz, mb);
            tma3(base + OFF_BH, &mBh, k0, n0, bz, mb);
            if (NTERMS == 3) tma3(base + OFF_BH + TILEBN, &mBl, k0, n0, bz, mb);
        }
    };

    issue(0, 0);
    if (nslab > 1) issue(1, 64);

    float acc[4][NBW][4];
#pragma unroll
    for (int i = 0; i < 4; i++)
#pragma unroll
        for (int j = 0; j < NBW; j++)
#pragma unroll
            for (int p = 0; p < 4; p++) acc[i][j][p] = 0.f;

    const unsigned aoffL = (unsigned)(m_w + (lane & 15)) * 128 + ((lane >> 4) * 16);
    const unsigned boffL = (unsigned)(n_w + (lane & 7) + ((lane >> 4) << 3)) * 128
                         + ((lane & 8) ? 16 : 0);
    const unsigned sxor = (unsigned)(lane & 7) << 4;

    int phase[2] = {0, 0};
    for (int s = 0; s < nslab; s++) {
        const int buf = s & 1;
        mbar_wait(mbq + buf * 8, (unsigned)phase[buf]);
        phase[buf] ^= 1;
        const unsigned st = sa + buf * STGX;
#pragma unroll
        for (int kk = 0; kk < 4; kk++) {
            unsigned ah[4][4], al[4][4];
#pragma unroll
            for (int mb = 0; mb < 4; mb++) {
                const unsigned a = st + ((aoffL + mb * 2048 + kk * 32) ^ sxor);
                ldm_x4(ah[mb][0], ah[mb][1], ah[mb][2], ah[mb][3], a);
                if (NTERMS >= 2)
                    ldm_x4(al[mb][0], al[mb][1], al[mb][2], al[mb][3], a + TILEA);
            }
#pragma unroll
            for (int nbp = 0; nbp < NBP; nbp++) {
                unsigned bh[2][2], bl[2][2];
                const unsigned b = st + OFF_BH + ((boffL + nbp * 2048 + kk * 32) ^ sxor);
                ldm_x4(bh[0][0], bh[0][1], bh[1][0], bh[1][1], b);
                if (NTERMS == 3)
                    ldm_x4(bl[0][0], bl[0][1], bl[1][0], bl[1][1], b + TILEBN);
#pragma unroll
                for (int mb = 0; mb < 4; mb++)
#pragma unroll
                    for (int j = 0; j < 2; j++) {
                        float* c = acc[mb][2 * nbp + j];
                        mma16816(c, ah[mb], bh[j]);
                        if (NTERMS >= 2) mma16816(c, al[mb], bh[j]);
                        if (NTERMS == 3) mma16816(c, ah[mb], bl[j]);
                    }
            }
        }
        __syncthreads();
        if (s + 2 < nslab) issue(buf, (s + 2) * 64);
    }

    // ======================= epilogues =======================
    if (MODE == 1 || MODE == 2) {
#pragma unroll
        for (int mb = 0; mb < 4; mb++)
#pragma unroll
            for (int p = 0; p < 2; p++) {
                const long long row = m0 + m_w + mb * 16 + (lane >> 2) + p * 8;
#pragma unroll
                for (int nb = 0; nb < NBW; nb++) {
                    const int col = n0 + n_w + nb * 8 + (lane & 3) * 2;
                    float v0 = acc[mb][nb][2 * p];
                    float v1 = acc[mb][nb][2 * p + 1];
                    if (MODE == 1) {
                        float2 o = make_float2(v0 + bias[col], v1 + bias[col + 1]);
                        *(float2*)&Cf[row * ldC + col] = o;
                    } else {
                        __half h0 = __float2half(v0);
                        __half h1 = __float2half(v1);
                        *(unsigned*)&Ch[row * (long long)ldC + col] =
                            hpack(__half2float(h0), __half2float(h1));
                        if (row < sC)
                            *(unsigned*)&Cl[row * (long long)ldC + col] =
                                hpack(v0 - __half2float(h0), v1 - __half2float(h1));
                    }
                }
            }
    }

    if (MODE == 5) {
        const float SC = 4.76837158203125e-7f;   // 2^-21
        // hoist mask (col depends only on nb)
        float mk0[NBW], mk1[NBW];
#pragma unroll
        for (int nb = 0; nb < NBW; nb++) {
            const int col = n0 + n_w + nb * 8 + (lane & 3) * 2;
            int2 mk = *(const int2*)&maskp[col];
            mk0[nb] = (mk.x != 0) ? 1.f : 0.f;
            mk1[nb] = (mk.y != 0) ? 1.f : 0.f;
        }
        float rs[4][2];
#pragma unroll
        for (int mb = 0; mb < 4; mb++)
#pragma unroll
            for (int p = 0; p < 2; p++) rs[mb][p] = 0.f;
#pragma unroll
        for (int mb = 0; mb < 4; mb++)
#pragma unroll
            for (int nb = 0; nb < NBW; nb++)
#pragma unroll
                for (int p = 0; p < 2; p++) {
                    // scale already includes log2(e)*0.125; exp2f -> single MUFU path
                    float e0 = fminf(exp2f(acc[mb][nb][2 * p] * scale) * SC, 60000.f);
                    float e1 = fminf(exp2f(acc[mb][nb][2 * p + 1] * scale) * SC, 60000.f);
                    acc[mb][nb][2 * p] = e0;
                    acc[mb][nb][2 * p + 1] = e1;
                    rs[mb][p] += e0 + e1;
                }
#pragma unroll
        for (int mb = 0; mb < 4; mb++)
#pragma unroll
            for (int p = 0; p < 2; p++) {
                rs[mb][p] += __shfl_xor_sync(0xffffffffu, rs[mb][p], 1);
                rs[mb][p] += __shfl_xor_sync(0xffffffffu, rs[mb][p], 2);
            }
        if ((lane & 3) == 0) {
#pragma unroll
            for (int mb = 0; mb < 4; mb++)
#pragma unroll
                for (int p = 0; p < 2; p++) {
                    const int row = m0 + m_w + mb * 16 + (lane >> 2) + p * 8;
                    atomicAdd(&Cf[bz * NROWS + row], rs[mb][p]);
                }
        }
#pragma unroll
        for (int mb = 0; mb < 4; mb++)
#pragma unroll
            for (int p = 0; p < 2; p++) {
                const long long row = m0 + m_w + mb * 16 + (lane >> 2) + p * 8;
#pragma unroll
                for (int nb = 0; nb < NBW; nb++) {
                    const int col = n0 + n_w + nb * 8 + (lane & 3) * 2;
                    *(unsigned*)&Ch[(long long)bz * sC + row * (long long)ldC + col] =
                        hpack(acc[mb][nb][2 * p] * mk0[nb],
                              acc[mb][nb][2 * p + 1] * mk1[nb]);
                }
            }
    }

    if (MODE == 6) {
        char* smal = smem + (int)(sa - smem_u32(smem));
        unsigned* S = (unsigned*)smal;
#pragma unroll
        for (int mb = 0; mb < 4; mb++)
#pragma unroll
            for (int p = 0; p < 2; p++) {
                const int row = m0 + m_w + mb * 16 + (lane >> 2) + p * 8;
                const float sc = 1.0f / bias[bz * NROWS + row];
                const int jl = row - m0;
#pragma unroll
                for (int nb = 0; nb < NBW; nb++) {
                    const int col = n0 + n_w + nb * 8 + (lane & 3) * 2;
                    float v0 = acc[mb][nb][2 * p] * sc;
                    float v1 = acc[mb][nb][2 * p + 1] * sc;
                    S[(col - n0) * 132 + jl] = hsplitpack(v0);
                    S[(col + 1 - n0) * 132 + jl] = hsplitpack(v1);
                }
            }
        __syncthreads();
        const int rr = m0 >> 9;
        const int j0 = m0 & 511;
        const long long ob = (long long)bz * ((long long)NROWS * CDIM) + j0;
#pragma unroll 4
        for (int rp = wid; rp < 256; rp += 8) {
            const int dl = rp >> 1;
            const int pl = rp & 1;
            uint4 q = *(uint4*)&S[dl * 132 + 4 * lane];
            unsigned a0, a1;
            if (pl == 0) {
                a0 = (q.x & 0xFFFFu) | (q.y << 16);
                a1 = (q.z & 0xFFFFu) | (q.w << 16);
            } else {
                a0 = (q.x >> 16) | (q.y & 0xFFFF0000u);
                a1 = (q.z >> 16) | (q.w & 0xFFFF0000u);
            }
            __half* dst = (pl ? Cl : Ch) + ob
                        + (long long)((((n0 + dl) << 3) + rr)) * 512;
            *(uint2*)(dst + 4 * lane) = make_uint2(a0, a1);
        }
    }
}

// ---------------------------------------------------------------------------
// Merged conversion: x, support -> (inh,inl) stacked ; Wv,Wp -> hi planes only
// ---------------------------------------------------------------------------
__global__ void __launch_bounds__(256) split_all(
    const float* __restrict__ x, const float* __restrict__ sup,
    const float* __restrict__ Wv, const float* __restrict__ Wp,
    __half* __restrict__ inh, __half* __restrict__ inl,
    __half* __restrict__ wvh, __half* __restrict__ wph)
{
    const int N1 = TOTQ * CDIM / 4;
    const int NW = CDIM * CDIM / 4;
    int i = blockIdx.x * 256 + threadIdx.x;
    if (i < 2 * N1) {
        const float* src = (i < N1) ? x : sup;
        int j = (i < N1) ? i : i - N1;
        float4 v = ((const float4*)src)[j];
        __half h0 = __float2half(v.x), h1 = __float2half(v.y);
        __half h2 = __float2half(v.z), h3 = __float2half(v.w);
        uint2 ph, pl;
        ph.x = hpack(__half2float(h0), __half2float(h1));
        ph.y = hpack(__half2float(h2), __half2float(h3));
        pl.x = hpack(v.x - __half2float(h0), v.y - __half2float(h1));
        pl.y = hpack(v.z - __half2float(h2), v.w - __half2float(h3));
        ((uint2*)inh)[i] = ph;
        ((uint2*)inl)[i] = pl;
    } else {
        int j = i - 2 * N1;
        if (j >= 2 * NW) return;
        const float* src = (j < NW) ? Wv : Wp;
        __half* dst = (j < NW) ? wvh : wph;
        int k = (j < NW) ? j : j - NW;
        float4 v = ((const float4*)src)[k];
        uint2 ph;
        ph.x = hpack(v.x, v.y);
        ph.y = hpack(v.z, v.w);
        ((uint2*)dst)[k] = ph;
    }
}

// ---------------------------------------------------------------------------
// kT (hi only): kth[b][d][m] = kh[b*4096+m][d]
// ---------------------------------------------------------------------------
__global__ void __launch_bounds__(256) transpose_hi(
    const __half* __restrict__ kh, __half* __restrict__ kth)
{
    __shared__ __half th[32][33];
    const int b = blockIdx.z;
    const int mm0 = blockIdx.x * 32;
    const int d0 = blockIdx.y * 32;
    const int tx = threadIdx.x, ty = threadIdx.y;
    const long long sbase = (long long)(b * 4096 + mm0) * CDIM + d0;
#pragma unroll
    for (int hh = 0; hh < 32; hh += 8)
        th[ty + hh][tx] = kh[sbase + (long long)(ty + hh) * CDIM + tx];
    __syncthreads();
    const long long dbase = (long long)b * CDIM * MROWS + (long long)d0 * MROWS + mm0;
#pragma unroll
    for (int hh = 0; hh < 32; hh += 8)
        kth[dbase + (long long)(ty + hh) * MROWS + tx] = th[tx][ty + hh];
}

// ---------------------------------------------------------------------------
// Host: tensormap encode via driver entry point
// ---------------------------------------------------------------------------
typedef CUresult (*PFN_tmapEnc)(
    CUtensorMap*, CUtensorMapDataType, cuuint32_t, void*,
    const cuuint64_t*, const cuuint64_t*, const cuuint32_t*, const cuuint32_t*,
    CUtensorMapInterleave, CUtensorMapSwizzle, CUtensorMapL2promotion,
    CUtensorMapFloatOOBfill);

static void enc_map(PFN_tmapEnc fn, CUtensorMap* m, const void* ptr,
                    unsigned long long K, unsigned long long rows,
                    unsigned long long batches, unsigned long long ldElems,
                    unsigned long long bStrideElems, unsigned boxRows)
{
    cuuint64_t dims[3] = {K, rows, batches};
    cuuint64_t strides[2] = {ldElems * 2ull, bStrideElems * 2ull};
    cuuint32_t box[3] = {64, boxRows, 1};
    cuuint32_t estr[3] = {1, 1, 1};
    fn(m, CU_TENSOR_MAP_DATA_TYPE_FLOAT16, 3, (void*)ptr,
       dims, strides, box, estr,
       CU_TENSOR_MAP_INTERLEAVE_NONE, CU_TENSOR_MAP_SWIZZLE_128B,
       CU_TENSOR_MAP_L2_PROMOTION_L2_128B, CU_TENSOR_MAP_FLOAT_OOB_FILL_NONE);
}

extern "C" void kernel_launch(void* const* d_in, const int* in_sizes, int n_in,
                              void* d_out, int out_size)
{
    const float* x       = (const float*)d_in[0];
    const float* support = (const float*)d_in[1];
    const int*   mask    = (const int*)  d_in[2];
    const float* Wv      = (const float*)d_in[3];
    const float* Wp      = (const float*)d_in[4];
    const float* bp      = (const float*)d_in[5];
    float* out = (float*)d_out;

    float* rowsum;
    __half *inh, *inl, *wvh, *wph;
    __half *qkh, *qkl, *kth, *ah, *o2h, *o2l;
    cudaGetSymbolAddress((void**)&rowsum, g_rowsum);
    cudaGetSymbolAddress((void**)&inh, g_inh); cudaGetSymbolAddress((void**)&inl, g_inl);
    cudaGetSymbolAddress((void**)&wvh, g_wvh);
    cudaGetSymbolAddress((void**)&wph, g_wph);
    cudaGetSymbolAddress((void**)&qkh, g_qkh); cudaGetSymbolAddress((void**)&qkl, g_qkl);
    cudaGetSymbolAddress((void**)&kth, g_kth);
    cudaGetSymbolAddress((void**)&ah, g_ah);
    cudaGetSymbolAddress((void**)&o2h, g_o2h); cudaGetSymbolAddress((void**)&o2l, g_o2l);

    __half* kh = qkh + (size_t)TOTQ * CDIM;

    void* sym = nullptr;
    cudaDriverEntryPointQueryResult qres;
    cudaGetDriverEntryPointByVersion("cuTensorMapEncodeTiled", &sym, 12000,
                                     cudaEnableDefault, &qres);
    PFN_tmapEnc enc = (PFN_tmapEnc)sym;

    const long long sQK = (long long)NROWS * CDIM;
    const long long sAT = (long long)NROWS * MROWS;

    CUtensorMap tInh, tInl, tWvh, tWph;
    enc_map(enc, &tInh, inh, CDIM, 2 * TOTQ, 1, CDIM, (long long)2 * TOTQ * CDIM, 128);
    enc_map(enc, &tInl, inl, CDIM, 2 * TOTQ, 1, CDIM, (long long)2 * TOTQ * CDIM, 128);
    enc_map(enc, &tWvh, wvh, CDIM, CDIM, 1, CDIM, (long long)CDIM * CDIM, 128);
    enc_map(enc, &tWph, wph, CDIM, CDIM, 1, CDIM, (long long)CDIM * CDIM, 128);
    CUtensorMap tQh, tQl, tKh;
    enc_map(enc, &tQh, qkh, CDIM, NROWS, BB, CDIM, sQK, 128);
    enc_map(enc, &tQl, qkl, CDIM, NROWS, BB, CDIM, sQK, 128);
    enc_map(enc, &tKh, kh,  CDIM, NROWS, BB, CDIM, sQK, 128);
    CUtensorMap tAh, tKTh;
    enc_map(enc, &tAh, ah, MROWS, NROWS, BB, MROWS, sAT, 128);
    enc_map(enc, &tKTh, kth, MROWS, CDIM, BB, MROWS, (long long)CDIM * MROWS, 128);
    CUtensorMap tO2h, tO2l;
    enc_map(enc, &tO2h, o2h, CDIM, TOTQ, 1, CDIM, (long long)TOTQ * CDIM, 128);
    enc_map(enc, &tO2l, o2l, CDIM, TOTQ, 1, CDIM, (long long)TOTQ * CDIM, 128);

    const int SMEM_2T = 1024 + 2 * (2 * TILEA + (128 * 64 * 2));      //  99328
    const int SMEM_AV = 1024 + 128 * 132 * 4;                         //  68608
    cudaFuncSetAttribute((const void*)tma_gemm<2,2,128,2>, cudaFuncAttributeMaxDynamicSharedMemorySize, SMEM_2T);
    cudaFuncSetAttribute((const void*)tma_gemm<1,2,128,2>, cudaFuncAttributeMaxDynamicSharedMemorySize, SMEM_2T);
    cudaFuncSetAttribute((const void*)tma_gemm<5,2,128,2>, cudaFuncAttributeMaxDynamicSharedMemorySize, SMEM_2T);
    cudaFuncSetAttribute((const void*)tma_gemm<6,1,128,2>, cudaFuncAttributeMaxDynamicSharedMemorySize, SMEM_AV);

    // 0) zero rowsum (graph-capturable)
    cudaMemsetAsync(rowsum, 0, TOTQ * sizeof(float));

    // 1) merged conversions
    {
        const int total = 2 * (TOTQ * CDIM / 4) + 2 * (CDIM * CDIM / 4);
        split_all<<<(total + 255) / 256, 256>>>(x, support, Wv, Wp,
                                                inh, inl, wvh, wph);
    }

    // 2) merged projection: [q;k] = [x;support] @ Wv-hi^T
    //    (2-term, occ-2, split out; lo-plane only for q rows < TOTQ)
    tma_gemm<2,2,128,2><<<dim3(4, 256, 1), 256, SMEM_2T>>>(
        tInh, tInl, tWvh, tWvh, CDIM, CDIM, 1.0f, (long long)TOTQ,
        nullptr, nullptr, nullptr, qkh, qkl);

    // 3) kT[b][d][m] (hi only)
    transpose_hi<<<dim3(128, 16, BB), dim3(32, 8)>>>(kh, kth);

    // 4) fused QK^T + exp2 (log2e*0.125 folded) + rowsum + mask -> fp16 E
    const float QSCALE = 0.125f * 1.4426950408889634f;
    tma_gemm<5,2,128,2><<<dim3(32, 32, BB), 256, SMEM_2T>>>(
        tQh, tQl, tKh, tKh, MROWS, CDIM, QSCALE, sAT,
        nullptr, mask, rowsum, ah, nullptr);

    // 5) fused AV + per-row normalize + bug-faithful permute -> split-fp16 o2
    tma_gemm<6,1,128,2><<<dim3(4, 32, BB), 256, SMEM_AV>>>(
        tAh, tAh, tKTh, tKTh, CDIM, MROWS, 1.0f, sQK,
        rowsum, nullptr, nullptr, o2h, o2l);

    // 6) out = o2 @ Wp-hi^T + bp  (2-term, occ-2)
    tma_gemm<1,2,128,2><<<dim3(4, 128, 1), 256, SMEM_2T>>>(
        tO2h, tO2l, tWph, tWph, CDIM, CDIM, 1.0f, 0,
        bp, nullptr, out, nullptr, nullptr);
}